// round 2
// baseline (speedup 1.0000x reference)
#include <cuda_runtime.h>

// TriangleAttention: B=1, N=256, D=128, H=4, kd=32
// Pipeline:
//   1. ln_nb_kernel   : LayerNorm(pair_act) -> g_x ; nb[h,i,j]=x(i,j)·w2d[h] -> g_nbT[h][j][i]
//   2. qkvg_gemm      : g_qkvg[m][0:128]=q*scale, [128:256]=k, [256:384]=v, [384:512]=sigmoid(g+bg)
//   3. attn_kernel    : per (r,h): softmax(q·k + bias + nb) @ v, gated -> g_og
//   4. out_gemm       : out = (g_og @ wo^T + bo) * mask

#define MTOT 65536

__device__ float g_x[MTOT * 128];            // 32 MB
__device__ float g_qkvg[MTOT * 512];         // 128 MB
__device__ float g_nbT[4 * MTOT];            // 1 MB   [h][j*256+i]
__device__ float g_og[MTOT * 128];           // 32 MB

// exp via 6-FMA polynomial 2^f (cephes exp2f minimax), avoids MUFU bottleneck.
__device__ __forceinline__ float fast_exp(float x) {
    x = fminf(fmaxf(x, -80.f), 80.f);
    float t = x * 1.4426950408889634f;
    float fi = floorf(t);
    float f = t - fi;
    float r = 1.5353368e-4f;
    r = fmaf(r, f, 1.3398887e-3f);
    r = fmaf(r, f, 9.6184374e-3f);
    r = fmaf(r, f, 5.5503325e-2f);
    r = fmaf(r, f, 2.4022648e-1f);
    r = fmaf(r, f, 6.9314720e-1f);
    r = fmaf(r, f, 1.0f);
    return r * __int_as_float(((int)fi + 127) << 23);
}

// ---------------------------------------------------------------------------
// Kernel 1: LayerNorm + nb bias. One block (128 threads) per pair row m.
// ---------------------------------------------------------------------------
__global__ __launch_bounds__(128) void ln_nb_kernel(
    const float* __restrict__ pa, const float* __restrict__ sc,
    const float* __restrict__ bi, const float* __restrict__ w2d) {
    __shared__ float ws1[4], ws2[4], wnb[16];
    int m = blockIdx.x, d = threadIdx.x;
    int lane = d & 31, wid = d >> 5;

    float v = pa[(size_t)m * 128 + d];
    float s1 = v, s2 = v * v;
#pragma unroll
    for (int o = 16; o > 0; o >>= 1) {
        s1 += __shfl_xor_sync(0xffffffffu, s1, o);
        s2 += __shfl_xor_sync(0xffffffffu, s2, o);
    }
    if (lane == 0) { ws1[wid] = s1; ws2[wid] = s2; }
    __syncthreads();
    float mean = (ws1[0] + ws1[1] + ws1[2] + ws1[3]) * 0.0078125f;
    float ex2  = (ws2[0] + ws2[1] + ws2[2] + ws2[3]) * 0.0078125f;
    float var = ex2 - mean * mean;
    float x = (v - mean) * rsqrtf(var + 1e-5f) * sc[d] + bi[d];
    g_x[(size_t)m * 128 + d] = x;

    float p0 = x * w2d[d];
    float p1 = x * w2d[128 + d];
    float p2 = x * w2d[256 + d];
    float p3 = x * w2d[384 + d];
#pragma unroll
    for (int o = 16; o > 0; o >>= 1) {
        p0 += __shfl_xor_sync(0xffffffffu, p0, o);
        p1 += __shfl_xor_sync(0xffffffffu, p1, o);
        p2 += __shfl_xor_sync(0xffffffffu, p2, o);
        p3 += __shfl_xor_sync(0xffffffffu, p3, o);
    }
    if (lane == 0) {
        wnb[0 + wid] = p0; wnb[4 + wid] = p1;
        wnb[8 + wid] = p2; wnb[12 + wid] = p3;
    }
    __syncthreads();
    if (d < 4) {
        float nb = wnb[d * 4] + wnb[d * 4 + 1] + wnb[d * 4 + 2] + wnb[d * 4 + 3];
        int i = m >> 8, j = m & 255;
        g_nbT[d * 65536 + j * 256 + i] = nb;  // transposed: coalesced per-j reads
    }
}

// ---------------------------------------------------------------------------
// Kernel 2: C[65536,512] = x @ [wq|wk|wv|wg]^T with fused q-scale / sigmoid(g).
// 64x64 tile, 256 threads, 4x4 micro-tile. Tiles stored [k][mn] with pad 68.
// ---------------------------------------------------------------------------
__global__ __launch_bounds__(256) void qkvg_gemm_kernel(
    const float* __restrict__ wq, const float* __restrict__ wk,
    const float* __restrict__ wv, const float* __restrict__ wg,
    const float* __restrict__ bg) {
    __shared__ float As[64][68];
    __shared__ float Bs[64][68];
    int tid = threadIdx.x;
    int tx = tid & 15, ty = tid >> 4;
    int m0 = blockIdx.y * 64;
    int bx = blockIdx.x;  // 0..7 -> weight matrix bx>>1, local half bx&1
    const float* W = (bx < 2) ? wq : (bx < 4) ? wk : (bx < 6) ? wv : wg;
    int n0loc = (bx & 1) * 64;

    float acc[4][4];
#pragma unroll
    for (int i = 0; i < 4; i++)
#pragma unroll
        for (int j = 0; j < 4; j++) acc[i][j] = 0.f;

    for (int k0 = 0; k0 < 128; k0 += 64) {
        __syncthreads();
#pragma unroll
        for (int it = 0; it < 16; it++) {
            int idx = tid + it * 256;
            int r = idx >> 6, c = idx & 63;
            As[c][r] = g_x[(size_t)(m0 + r) * 128 + k0 + c];
            Bs[c][r] = W[(n0loc + r) * 128 + k0 + c];
        }
        __syncthreads();
#pragma unroll 8
        for (int k = 0; k < 64; k++) {
            float4 a = *(const float4*)&As[k][ty * 4];
            float4 b = *(const float4*)&Bs[k][tx * 4];
            acc[0][0] = fmaf(a.x, b.x, acc[0][0]);
            acc[0][1] = fmaf(a.x, b.y, acc[0][1]);
            acc[0][2] = fmaf(a.x, b.z, acc[0][2]);
            acc[0][3] = fmaf(a.x, b.w, acc[0][3]);
            acc[1][0] = fmaf(a.y, b.x, acc[1][0]);
            acc[1][1] = fmaf(a.y, b.y, acc[1][1]);
            acc[1][2] = fmaf(a.y, b.z, acc[1][2]);
            acc[1][3] = fmaf(a.y, b.w, acc[1][3]);
            acc[2][0] = fmaf(a.z, b.x, acc[2][0]);
            acc[2][1] = fmaf(a.z, b.y, acc[2][1]);
            acc[2][2] = fmaf(a.z, b.z, acc[2][2]);
            acc[2][3] = fmaf(a.z, b.w, acc[2][3]);
            acc[3][0] = fmaf(a.w, b.x, acc[3][0]);
            acc[3][1] = fmaf(a.w, b.y, acc[3][1]);
            acc[3][2] = fmaf(a.w, b.z, acc[3][2]);
            acc[3][3] = fmaf(a.w, b.w, acc[3][3]);
        }
    }

    const float qscale = 0.17677669529663687f;  // 32^-0.5
    int nbase = bx * 64 + tx * 4;
#pragma unroll
    for (int i = 0; i < 4; i++) {
        int m = m0 + ty * 4 + i;
        float vv[4];
#pragma unroll
        for (int j = 0; j < 4; j++) {
            float val = acc[i][j];
            int n = nbase + j;
            if (n < 128) {
                val *= qscale;
            } else if (n >= 384) {
                val = val + bg[n - 384];
                val = 1.f / (1.f + fast_exp(-val));
            }
            vv[j] = val;
        }
        *(float4*)&g_qkvg[(size_t)m * 512 + nbase] =
            make_float4(vv[0], vv[1], vv[2], vv[3]);
    }
}

// ---------------------------------------------------------------------------
// Kernel 3: attention per (r, h). 256 threads, thread i = query i.
// k/v staged in smem in two 128-key tiles (33 KB). Single-pass softmax
// (shift-invariant; logits clamped in fast_exp). Gating fused in epilogue.
// ---------------------------------------------------------------------------
__global__ __launch_bounds__(256) void attn_kernel(const float* __restrict__ mask) {
    __shared__ float ksm[128 * 32];
    __shared__ float vsm[128 * 32];
    __shared__ float bsm[256];
    int h = blockIdx.x, r = blockIdx.y;
    int tid = threadIdx.x;
    size_t rowbase = (size_t)(r * 256) * 512;

    bsm[tid] = 32768.f * (mask[r * 256 + tid] - 1.f);

    int i = tid;
    float q[32];
    {
        const float4* qp = (const float4*)&g_qkvg[rowbase + (size_t)i * 512 + h * 32];
#pragma unroll
        for (int c4 = 0; c4 < 8; c4++) {
            float4 t = qp[c4];
            q[c4 * 4 + 0] = t.x; q[c4 * 4 + 1] = t.y;
            q[c4 * 4 + 2] = t.z; q[c4 * 4 + 3] = t.w;
        }
    }
    float acc[32];
#pragma unroll
    for (int c = 0; c < 32; c++) acc[c] = 0.f;
    float l = 0.f;
    const float* nbp = g_nbT + h * 65536 + i;

    for (int jt = 0; jt < 2; jt++) {
        __syncthreads();
#pragma unroll
        for (int it = 0; it < 16; it++) {
            int idx = tid + it * 256;       // 0..4095
            int j = idx >> 5, c = idx & 31;
            // FIX (R1): per-head offset h*32 was missing -> heads 1..3 read head-0 k/v
            size_t gidx = rowbase + (size_t)(jt * 128 + j) * 512 + h * 32 + c;
            ksm[idx] = g_qkvg[gidx + 128];
            vsm[idx] = g_qkvg[gidx + 256];
        }
        __syncthreads();
#pragma unroll 2
        for (int lj = 0; lj < 128; lj++) {
            int j = jt * 128 + lj;
            float s = bsm[j] + nbp[(size_t)j * 256];
            const float4* kp = (const float4*)&ksm[lj * 32];
#pragma unroll
            for (int c4 = 0; c4 < 8; c4++) {
                float4 kk = kp[c4];
                s = fmaf(q[c4 * 4 + 0], kk.x, s);
                s = fmaf(q[c4 * 4 + 1], kk.y, s);
                s = fmaf(q[c4 * 4 + 2], kk.z, s);
                s = fmaf(q[c4 * 4 + 3], kk.w, s);
            }
            float p = fast_exp(s);
            l += p;
            const float4* vp = (const float4*)&vsm[lj * 32];
#pragma unroll
            for (int c4 = 0; c4 < 8; c4++) {
                float4 vv = vp[c4];
                acc[c4 * 4 + 0] = fmaf(p, vv.x, acc[c4 * 4 + 0]);
                acc[c4 * 4 + 1] = fmaf(p, vv.y, acc[c4 * 4 + 1]);
                acc[c4 * 4 + 2] = fmaf(p, vv.z, acc[c4 * 4 + 2]);
                acc[c4 * 4 + 3] = fmaf(p, vv.w, acc[c4 * 4 + 3]);
            }
        }
    }

    float rl = 1.f / l;
    const float4* gp = (const float4*)&g_qkvg[rowbase + (size_t)i * 512 + 384 + h * 32];
    float4* op = (float4*)&g_og[(size_t)(r * 256 + i) * 128 + h * 32];
#pragma unroll
    for (int c4 = 0; c4 < 8; c4++) {
        float4 gv = gp[c4];
        op[c4] = make_float4(acc[c4 * 4 + 0] * rl * gv.x,
                             acc[c4 * 4 + 1] * rl * gv.y,
                             acc[c4 * 4 + 2] * rl * gv.z,
                             acc[c4 * 4 + 3] * rl * gv.w);
    }
}

// ---------------------------------------------------------------------------
// Kernel 4: out = (og @ wo^T + bo) * mask. Same tiling as kernel 2.
// ---------------------------------------------------------------------------
__global__ __launch_bounds__(256) void out_gemm_kernel(
    const float* __restrict__ wo, const float* __restrict__ bo,
    const float* __restrict__ mask, float* __restrict__ out) {
    __shared__ float As[64][68];
    __shared__ float Bs[64][68];
    int tid = threadIdx.x;
    int tx = tid & 15, ty = tid >> 4;
    int m0 = blockIdx.y * 64;
    int n0 = blockIdx.x * 64;

    float acc[4][4];
#pragma unroll
    for (int i = 0; i < 4; i++)
#pragma unroll
        for (int j = 0; j < 4; j++) acc[i][j] = 0.f;

    for (int k0 = 0; k0 < 128; k0 += 64) {
        __syncthreads();
#pragma unroll
        for (int it = 0; it < 16; it++) {
            int idx = tid + it * 256;
            int r = idx >> 6, c = idx & 63;
            As[c][r] = g_og[(size_t)(m0 + r) * 128 + k0 + c];
            Bs[c][r] = wo[(n0 + r) * 128 + k0 + c];
        }
        __syncthreads();
#pragma unroll 8
        for (int k = 0; k < 64; k++) {
            float4 a = *(const float4*)&As[k][ty * 4];
            float4 b = *(const float4*)&Bs[k][tx * 4];
            acc[0][0] = fmaf(a.x, b.x, acc[0][0]);
            acc[0][1] = fmaf(a.x, b.y, acc[0][1]);
            acc[0][2] = fmaf(a.x, b.z, acc[0][2]);
            acc[0][3] = fmaf(a.x, b.w, acc[0][3]);
            acc[1][0] = fmaf(a.y, b.x, acc[1][0]);
            acc[1][1] = fmaf(a.y, b.y, acc[1][1]);
            acc[1][2] = fmaf(a.y, b.z, acc[1][2]);
            acc[1][3] = fmaf(a.y, b.w, acc[1][3]);
            acc[2][0] = fmaf(a.z, b.x, acc[2][0]);
            acc[2][1] = fmaf(a.z, b.y, acc[2][1]);
            acc[2][2] = fmaf(a.z, b.z, acc[2][2]);
            acc[2][3] = fmaf(a.z, b.w, acc[2][3]);
            acc[3][0] = fmaf(a.w, b.x, acc[3][0]);
            acc[3][1] = fmaf(a.w, b.y, acc[3][1]);
            acc[3][2] = fmaf(a.w, b.z, acc[3][2]);
            acc[3][3] = fmaf(a.w, b.w, acc[3][3]);
        }
    }

    int nbase = n0 + tx * 4;
#pragma unroll
    for (int i = 0; i < 4; i++) {
        int m = m0 + ty * 4 + i;
        float mk = mask[m];
        float4 o;
        o.x = (acc[i][0] + bo[nbase + 0]) * mk;
        o.y = (acc[i][1] + bo[nbase + 1]) * mk;
        o.z = (acc[i][2] + bo[nbase + 2]) * mk;
        o.w = (acc[i][3] + bo[nbase + 3]) * mk;
        *(float4*)&out[(size_t)m * 128 + nbase] = o;
    }
}

// ---------------------------------------------------------------------------

extern "C" void kernel_launch(void* const* d_in, const int* in_sizes, int n_in,
                              void* d_out, int out_size) {
    const float* pa  = (const float*)d_in[0];   // pair_act  [1,256,256,128]
    const float* pm  = (const float*)d_in[1];   // pair_mask [1,256,256]
    const float* lns = (const float*)d_in[2];   // ln_scale  [128]
    const float* lnb = (const float*)d_in[3];   // ln_bias   [128]
    const float* w2d = (const float*)d_in[4];   // w2d       [4,128]
    const float* wq  = (const float*)d_in[5];   // wq        [128,128]
    const float* wk  = (const float*)d_in[6];
    const float* wv  = (const float*)d_in[7];
    const float* wg  = (const float*)d_in[8];
    const float* bg  = (const float*)d_in[9];   // bg        [128]
    const float* wo  = (const float*)d_in[10];
    const float* bo  = (const float*)d_in[11];
    float* out = (float*)d_out;

    ln_nb_kernel<<<65536, 128>>>(pa, lns, lnb, w2d);
    qkvg_gemm_kernel<<<dim3(8, 1024), 256>>>(wq, wk, wv, wg, bg);
    attn_kernel<<<dim3(4, 256), 256>>>(pm);
    out_gemm_kernel<<<dim3(2, 1024), 256>>>(wo, bo, pm, out);
}

// round 3
// speedup vs baseline: 1.5439x; 1.5439x over previous
#include <cuda_runtime.h>
#include <cuda_bf16.h>

// TriangleAttention: B=1, N=256, D=128, H=4, kd=32
// Pipeline:
//   0. prep_w      : split wq|wk|wv|wg|wo into bf16 hi/lo planes
//   1. ln_nb       : LayerNorm -> packed split-bf16 x ; nb[h,i,j] -> g_nbT[h][j][i]
//   2. mma_gemm(0) : g_qkvg = x @ [wq|wk|wv|wg]^T (split-bf16 tensor-core, fp32 out)
//   3. attn        : per (r,h) softmax(qk+bias+nb)@v, gated -> packed split-bf16 og
//   4. mma_gemm(1) : out = (og @ wo^T + bo) * mask

#define MTOT 65536

__device__ unsigned int g_x2[MTOT * 128];      // packed: lo16=bf16 hi part, hi16=bf16 lo part
__device__ unsigned int g_og2[MTOT * 128];     // same packing
__device__ float g_qkvg[MTOT * 512];           // q*scale | k | v | sigmoid(g)
__device__ float g_nbT[4 * MTOT];              // [h][j*256+i]
__device__ __nv_bfloat16 g_wh[5 * 16384];      // wq wk wv wg wo (hi)
__device__ __nv_bfloat16 g_wl[5 * 16384];      // (lo)

// exp via FMA polynomial (avoids MUFU throughput wall)
__device__ __forceinline__ float fast_exp(float x) {
    x = fminf(fmaxf(x, -80.f), 80.f);
    float t = x * 1.4426950408889634f;
    float fi = floorf(t);
    float f = t - fi;
    float r = 1.5353368e-4f;
    r = fmaf(r, f, 1.3398887e-3f);
    r = fmaf(r, f, 9.6184374e-3f);
    r = fmaf(r, f, 5.5503325e-2f);
    r = fmaf(r, f, 2.4022648e-1f);
    r = fmaf(r, f, 6.9314720e-1f);
    r = fmaf(r, f, 1.0f);
    return r * __int_as_float(((int)fi + 127) << 23);
}

__device__ __forceinline__ unsigned int pack_split(float v) {
    __nv_bfloat16 h = __float2bfloat16(v);
    float res = v - __bfloat162float(h);
    __nv_bfloat16 l = __float2bfloat16(res);
    return ((unsigned int)__bfloat16_as_ushort(l) << 16) |
           (unsigned int)__bfloat16_as_ushort(h);
}

__device__ __forceinline__ void ldsm4(unsigned int* r, const void* p) {
    unsigned int a = (unsigned int)__cvta_generic_to_shared(p);
    asm volatile("ldmatrix.sync.aligned.m8n8.x4.shared.b16 {%0,%1,%2,%3}, [%4];"
                 : "=r"(r[0]), "=r"(r[1]), "=r"(r[2]), "=r"(r[3]) : "r"(a));
}

__device__ __forceinline__ void mma16816(float* c, const unsigned int* a,
                                         const unsigned int* b) {
    asm volatile(
        "mma.sync.aligned.m16n8k16.row.col.f32.bf16.bf16.f32 "
        "{%0,%1,%2,%3}, {%4,%5,%6,%7}, {%8,%9}, {%0,%1,%2,%3};"
        : "+f"(c[0]), "+f"(c[1]), "+f"(c[2]), "+f"(c[3])
        : "r"(a[0]), "r"(a[1]), "r"(a[2]), "r"(a[3]), "r"(b[0]), "r"(b[1]));
}

// ---------------------------------------------------------------------------
// Kernel 0: split all 5 weight matrices into bf16 hi/lo planes.
// ---------------------------------------------------------------------------
__global__ __launch_bounds__(512) void prep_w_kernel(
    const float* __restrict__ wq, const float* __restrict__ wk,
    const float* __restrict__ wv, const float* __restrict__ wg,
    const float* __restrict__ wo) {
    int idx = blockIdx.x * 512 + threadIdx.x;   // 0..81919
    int which = idx >> 14, off = idx & 16383;
    float w;
    if (which == 0) w = wq[off];
    else if (which == 1) w = wk[off];
    else if (which == 2) w = wv[off];
    else if (which == 3) w = wg[off];
    else w = wo[off];
    __nv_bfloat16 h = __float2bfloat16(w);
    g_wh[idx] = h;
    g_wl[idx] = __float2bfloat16(w - __bfloat162float(h));
}

// ---------------------------------------------------------------------------
// Kernel 1: LayerNorm + nb bias. One block (128 threads) per pair row m.
// ---------------------------------------------------------------------------
__global__ __launch_bounds__(128) void ln_nb_kernel(
    const float* __restrict__ pa, const float* __restrict__ sc,
    const float* __restrict__ bi, const float* __restrict__ w2d) {
    __shared__ float ws1[4], ws2[4], wnb[16];
    int m = blockIdx.x, d = threadIdx.x;
    int lane = d & 31, wid = d >> 5;

    float v = pa[(size_t)m * 128 + d];
    float s1 = v, s2 = v * v;
#pragma unroll
    for (int o = 16; o > 0; o >>= 1) {
        s1 += __shfl_xor_sync(0xffffffffu, s1, o);
        s2 += __shfl_xor_sync(0xffffffffu, s2, o);
    }
    if (lane == 0) { ws1[wid] = s1; ws2[wid] = s2; }
    __syncthreads();
    float mean = (ws1[0] + ws1[1] + ws1[2] + ws1[3]) * 0.0078125f;
    float ex2  = (ws2[0] + ws2[1] + ws2[2] + ws2[3]) * 0.0078125f;
    float var = ex2 - mean * mean;
    float x = (v - mean) * rsqrtf(var + 1e-5f) * sc[d] + bi[d];
    g_x2[(size_t)m * 128 + d] = pack_split(x);

    float p0 = x * w2d[d];
    float p1 = x * w2d[128 + d];
    float p2 = x * w2d[256 + d];
    float p3 = x * w2d[384 + d];
#pragma unroll
    for (int o = 16; o > 0; o >>= 1) {
        p0 += __shfl_xor_sync(0xffffffffu, p0, o);
        p1 += __shfl_xor_sync(0xffffffffu, p1, o);
        p2 += __shfl_xor_sync(0xffffffffu, p2, o);
        p3 += __shfl_xor_sync(0xffffffffu, p3, o);
    }
    if (lane == 0) {
        wnb[0 + wid] = p0; wnb[4 + wid] = p1;
        wnb[8 + wid] = p2; wnb[12 + wid] = p3;
    }
    __syncthreads();
    if (d < 4) {
        float nb = wnb[d * 4] + wnb[d * 4 + 1] + wnb[d * 4 + 2] + wnb[d * 4 + 3];
        int i = m >> 8, j = m & 255;
        g_nbT[d * 65536 + j * 256 + i] = nb;
    }
}

// ---------------------------------------------------------------------------
// Kernels 2/4: split-bf16 tensor-core GEMM, C = A @ W^T (+ epilogue).
// Block: 128(M) x 64(N), k-tile 32, 8 warps in 2(m) x 4(n); warp tile 64x16.
// A from packed g_x2/g_og2; W from g_wh/g_wl. C fp32: Ah*Wh + Ah*Wl + Al*Wh.
// Smem rows padded to 80B -> conflict-free ldmatrix. 30KB static smem.
// mode 0: qkvg epilogue (q-scale / sigmoid(g+bg)) -> g_qkvg
// mode 1: out epilogue ((c+bo)*mask) -> out
// ---------------------------------------------------------------------------
__global__ __launch_bounds__(256) void mma_gemm_kernel(
    int mode, const float* __restrict__ bias,
    const float* __restrict__ mask, float* __restrict__ out) {
    __shared__ __align__(16) char smb[30720];
    const int AH = 0, AL = 10240, BH = 20480, BL = 25600;
    int tid = threadIdx.x, lane = tid & 31, wid = tid >> 5;
    int wm = wid & 1, wn = wid >> 1;
    int bx = blockIdx.x, m0 = blockIdx.y * 128;
    const unsigned int* Apk = (mode == 0) ? g_x2 : g_og2;
    int widx = (mode == 0) ? (bx >> 1) : 4;
    int nloc = (mode == 0) ? ((bx & 1) * 64) : bx * 64;
    int woff = widx * 16384;

    float c[4][2][4];
#pragma unroll
    for (int a = 0; a < 4; a++)
#pragma unroll
        for (int b = 0; b < 2; b++)
#pragma unroll
            for (int d = 0; d < 4; d++) c[a][b][d] = 0.f;

    // ldmatrix per-lane source rows (see mma.m16n8k16 fragment layout)
    int rowA = ((lane >> 3) & 1) * 8 + (lane & 7);
    int kofA = (lane >> 4) * 8;
    int rowB = (lane & 7) + ((lane >> 4) & 1) * 8;
    int kofB = ((lane >> 3) & 1) * 8;

    for (int kt = 0; kt < 128; kt += 32) {
        __syncthreads();
        // stage A tile 128x32 (hi+lo split from packed)
#pragma unroll
        for (int p = 0; p < 4; p++) {
            int idx = tid + p * 256;
            int r = idx >> 3, g = idx & 7;
            uint4 u = *(const uint4*)&Apk[(size_t)(m0 + r) * 128 + kt + g * 4];
            uint2 hv, lv;
            hv.x = (u.x & 0xffffu) | (u.y << 16);
            hv.y = (u.z & 0xffffu) | (u.w << 16);
            lv.x = (u.x >> 16) | (u.y & 0xffff0000u);
            lv.y = (u.z >> 16) | (u.w & 0xffff0000u);
            *(uint2*)(smb + AH + r * 80 + g * 8) = hv;
            *(uint2*)(smb + AL + r * 80 + g * 8) = lv;
        }
        // stage B tile 64x32 (weights, already split)
        {
            int r = tid >> 2, g = tid & 3;
            *(uint4*)(smb + BH + r * 80 + g * 16) =
                *(const uint4*)&g_wh[woff + (nloc + r) * 128 + kt + g * 8];
            *(uint4*)(smb + BL + r * 80 + g * 16) =
                *(const uint4*)&g_wl[woff + (nloc + r) * 128 + kt + g * 8];
        }
        __syncthreads();
#pragma unroll
        for (int ks = 0; ks < 2; ks++) {
            unsigned int ah[4][4], al[4][4], bh[4], bl[4];
#pragma unroll
            for (int mt = 0; mt < 4; mt++) {
                const char* pa = smb + AH + (wm * 64 + mt * 16 + rowA) * 80 +
                                 (ks * 16 + kofA) * 2;
                ldsm4(ah[mt], pa);
                ldsm4(al[mt], pa + (AL - AH));
            }
            const char* pb = smb + BH + (wn * 16 + rowB) * 80 +
                             (ks * 16 + kofB) * 2;
            ldsm4(bh, pb);
            ldsm4(bl, pb + (BL - BH));
#pragma unroll
            for (int mt = 0; mt < 4; mt++)
#pragma unroll
                for (int nt = 0; nt < 2; nt++) {
                    mma16816(c[mt][nt], ah[mt], &bh[nt * 2]);
                    mma16816(c[mt][nt], ah[mt], &bl[nt * 2]);
                    mma16816(c[mt][nt], al[mt], &bh[nt * 2]);
                }
        }
    }

    const float qscale = 0.17677669529663687f;  // 32^-0.5
#pragma unroll
    for (int mt = 0; mt < 4; mt++) {
        int r0 = m0 + wm * 64 + mt * 16 + (lane >> 2);
#pragma unroll
        for (int nt = 0; nt < 2; nt++) {
            int n = bx * 64 + wn * 16 + nt * 8 + (lane & 3) * 2;
            float v0 = c[mt][nt][0], v1 = c[mt][nt][1];
            float v2 = c[mt][nt][2], v3 = c[mt][nt][3];
            if (mode == 0) {
                if (n < 128) {
                    v0 *= qscale; v1 *= qscale; v2 *= qscale; v3 *= qscale;
                } else if (n >= 384) {
                    float b0 = bias[n - 384], b1 = bias[n - 383];
                    v0 = 1.f / (1.f + fast_exp(-(v0 + b0)));
                    v1 = 1.f / (1.f + fast_exp(-(v1 + b1)));
                    v2 = 1.f / (1.f + fast_exp(-(v2 + b0)));
                    v3 = 1.f / (1.f + fast_exp(-(v3 + b1)));
                }
                *(float2*)&g_qkvg[(size_t)r0 * 512 + n] = make_float2(v0, v1);
                *(float2*)&g_qkvg[(size_t)(r0 + 8) * 512 + n] = make_float2(v2, v3);
            } else {
                float b0 = bias[n], b1 = bias[n + 1];
                float mk0 = mask[r0], mk1 = mask[r0 + 8];
                *(float2*)&out[(size_t)r0 * 128 + n] =
                    make_float2((v0 + b0) * mk0, (v1 + b1) * mk0);
                *(float2*)&out[(size_t)(r0 + 8) * 128 + n] =
                    make_float2((v2 + b0) * mk1, (v3 + b1) * mk1);
            }
        }
    }
}

// ---------------------------------------------------------------------------
// Kernel 3: attention per (r, h). 256 threads, thread i = query i.
// k/v staged in smem (two 128-key tiles). Single-pass softmax (clamped exp).
// Epilogue: gate, normalize, emit packed split-bf16 og.
// ---------------------------------------------------------------------------
__global__ __launch_bounds__(256) void attn_kernel(const float* __restrict__ mask) {
    __shared__ float ksm[128 * 32];
    __shared__ float vsm[128 * 32];
    __shared__ float bsm[256];
    int h = blockIdx.x, r = blockIdx.y;
    int tid = threadIdx.x;
    size_t rowbase = (size_t)(r * 256) * 512;

    bsm[tid] = 32768.f * (mask[r * 256 + tid] - 1.f);

    int i = tid;
    float q[32];
    {
        const float4* qp = (const float4*)&g_qkvg[rowbase + (size_t)i * 512 + h * 32];
#pragma unroll
        for (int c4 = 0; c4 < 8; c4++) {
            float4 t = qp[c4];
            q[c4 * 4 + 0] = t.x; q[c4 * 4 + 1] = t.y;
            q[c4 * 4 + 2] = t.z; q[c4 * 4 + 3] = t.w;
        }
    }
    float acc[32];
#pragma unroll
    for (int c = 0; c < 32; c++) acc[c] = 0.f;
    float l = 0.f;
    const float* nbp = g_nbT + h * 65536 + i;

    for (int jt = 0; jt < 2; jt++) {
        __syncthreads();
#pragma unroll
        for (int it = 0; it < 16; it++) {
            int idx = tid + it * 256;
            int j = idx >> 5, c = idx & 31;
            size_t gidx = rowbase + (size_t)(jt * 128 + j) * 512 + h * 32 + c;
            ksm[idx] = g_qkvg[gidx + 128];
            vsm[idx] = g_qkvg[gidx + 256];
        }
        __syncthreads();
#pragma unroll 2
        for (int lj = 0; lj < 128; lj++) {
            int j = jt * 128 + lj;
            float s = bsm[j] + nbp[(size_t)j * 256];
            const float4* kp = (const float4*)&ksm[lj * 32];
#pragma unroll
            for (int c4 = 0; c4 < 8; c4++) {
                float4 kk = kp[c4];
                s = fmaf(q[c4 * 4 + 0], kk.x, s);
                s = fmaf(q[c4 * 4 + 1], kk.y, s);
                s = fmaf(q[c4 * 4 + 2], kk.z, s);
                s = fmaf(q[c4 * 4 + 3], kk.w, s);
            }
            float p = fast_exp(s);
            l += p;
            const float4* vp = (const float4*)&vsm[lj * 32];
#pragma unroll
            for (int c4 = 0; c4 < 8; c4++) {
                float4 vv = vp[c4];
                acc[c4 * 4 + 0] = fmaf(p, vv.x, acc[c4 * 4 + 0]);
                acc[c4 * 4 + 1] = fmaf(p, vv.y, acc[c4 * 4 + 1]);
                acc[c4 * 4 + 2] = fmaf(p, vv.z, acc[c4 * 4 + 2]);
                acc[c4 * 4 + 3] = fmaf(p, vv.w, acc[c4 * 4 + 3]);
            }
        }
    }

    float rl = 1.f / l;
    const float4* gp = (const float4*)&g_qkvg[rowbase + (size_t)i * 512 + 384 + h * 32];
    uint4* op = (uint4*)&g_og2[(size_t)(r * 256 + i) * 128 + h * 32];
#pragma unroll
    for (int c4 = 0; c4 < 8; c4++) {
        float4 gv = gp[c4];
        uint4 st;
        st.x = pack_split(acc[c4 * 4 + 0] * rl * gv.x);
        st.y = pack_split(acc[c4 * 4 + 1] * rl * gv.y);
        st.z = pack_split(acc[c4 * 4 + 2] * rl * gv.z);
        st.w = pack_split(acc[c4 * 4 + 3] * rl * gv.w);
        op[c4] = st;
    }
}

// ---------------------------------------------------------------------------

extern "C" void kernel_launch(void* const* d_in, const int* in_sizes, int n_in,
                              void* d_out, int out_size) {
    const float* pa  = (const float*)d_in[0];   // pair_act  [1,256,256,128]
    const float* pm  = (const float*)d_in[1];   // pair_mask [1,256,256]
    const float* lns = (const float*)d_in[2];   // ln_scale  [128]
    const float* lnb = (const float*)d_in[3];   // ln_bias   [128]
    const float* w2d = (const float*)d_in[4];   // w2d       [4,128]
    const float* wq  = (const float*)d_in[5];
    const float* wk  = (const float*)d_in[6];
    const float* wv  = (const float*)d_in[7];
    const float* wg  = (const float*)d_in[8];
    const float* bg  = (const float*)d_in[9];
    const float* wo  = (const float*)d_in[10];
    const float* bo  = (const float*)d_in[11];
    float* out = (float*)d_out;

    prep_w_kernel<<<160, 512>>>(wq, wk, wv, wg, wo);
    ln_nb_kernel<<<65536, 128>>>(pa, lns, lnb, w2d);
    mma_gemm_kernel<<<dim3(8, 512), 256>>>(0, bg, nullptr, nullptr);
    attn_kernel<<<dim3(4, 256), 256>>>(pm);
    mma_gemm_kernel<<<dim3(2, 512), 256>>>(1, bo, pm, out);
}

// round 4
// speedup vs baseline: 2.6189x; 1.6962x over previous
#include <cuda_runtime.h>
#include <cuda_bf16.h>

// TriangleAttention: B=1, N=256, D=128, H=4, kd=32
//   0. prep_w      : split wq|wk|wv|wg|wo into bf16 hi/lo planes
//   1. ln_nb       : LayerNorm -> packed split-bf16 x ; nb*log2e -> g_nb[h][i][j]
//   2. mma_gemm(0) : g_qkvg = x @ [wq|wk|wv|wg]^T  (q pre-scaled by 1/sqrt(kd)*log2e)
//   3. attn_mma    : per (r,h) flash attention on tensor cores, gated -> packed og
//   4. mma_gemm(1) : out = (og @ wo^T + bo) * mask

#define MTOT 65536
#define L2E 1.4426950408889634f

__device__ unsigned int g_x2[MTOT * 128];      // packed: lo16=hi bf16, hi16=lo bf16
__device__ unsigned int g_og2[MTOT * 128];
__device__ float g_qkvg[MTOT * 512];           // q*scale*log2e | k | v | sigmoid(g)
__device__ float g_nb[4 * MTOT];               // [h][i*256+j], pre-scaled by log2e
__device__ __nv_bfloat16 g_wh[5 * 16384];
__device__ __nv_bfloat16 g_wl[5 * 16384];

__device__ __forceinline__ float ex2(float x) {
    float y; asm("ex2.approx.ftz.f32 %0, %1;" : "=f"(y) : "f"(x)); return y;
}
__device__ __forceinline__ unsigned pack2bf(float lo, float hi) {
    unsigned d; asm("cvt.rn.bf16x2.f32 %0, %1, %2;" : "=r"(d) : "f"(hi), "f"(lo));
    return d;
}
__device__ __forceinline__ float bflo(unsigned u) { return __uint_as_float(u << 16); }
__device__ __forceinline__ float bfhi(unsigned u) { return __uint_as_float(u & 0xffff0000u); }

__device__ __forceinline__ unsigned int pack_split(float v) {
    __nv_bfloat16 h = __float2bfloat16(v);
    float res = v - __bfloat162float(h);
    __nv_bfloat16 l = __float2bfloat16(res);
    return ((unsigned int)__bfloat16_as_ushort(l) << 16) |
           (unsigned int)__bfloat16_as_ushort(h);
}
__device__ __forceinline__ void split4(float4 u, uint2& hv, uint2& lv) {
    __nv_bfloat16 hx = __float2bfloat16(u.x), hy = __float2bfloat16(u.y),
                  hz = __float2bfloat16(u.z), hw = __float2bfloat16(u.w);
    hv.x = ((unsigned)__bfloat16_as_ushort(hy) << 16) | __bfloat16_as_ushort(hx);
    hv.y = ((unsigned)__bfloat16_as_ushort(hw) << 16) | __bfloat16_as_ushort(hz);
    lv.x = pack2bf(u.x - __bfloat162float(hx), u.y - __bfloat162float(hy));
    lv.y = pack2bf(u.z - __bfloat162float(hz), u.w - __bfloat162float(hw));
}
__device__ __forceinline__ void ldsm4(unsigned int* r, const void* p) {
    unsigned int a = (unsigned int)__cvta_generic_to_shared(p);
    asm volatile("ldmatrix.sync.aligned.m8n8.x4.shared.b16 {%0,%1,%2,%3}, [%4];"
                 : "=r"(r[0]), "=r"(r[1]), "=r"(r[2]), "=r"(r[3]) : "r"(a));
}
__device__ __forceinline__ void ldsm4t(unsigned int* r, const void* p) {
    unsigned int a = (unsigned int)__cvta_generic_to_shared(p);
    asm volatile("ldmatrix.sync.aligned.m8n8.x4.trans.shared.b16 {%0,%1,%2,%3}, [%4];"
                 : "=r"(r[0]), "=r"(r[1]), "=r"(r[2]), "=r"(r[3]) : "r"(a));
}
__device__ __forceinline__ void mma16816(float* c, const unsigned int* a,
                                         const unsigned int* b) {
    asm volatile(
        "mma.sync.aligned.m16n8k16.row.col.f32.bf16.bf16.f32 "
        "{%0,%1,%2,%3}, {%4,%5,%6,%7}, {%8,%9}, {%0,%1,%2,%3};"
        : "+f"(c[0]), "+f"(c[1]), "+f"(c[2]), "+f"(c[3])
        : "r"(a[0]), "r"(a[1]), "r"(a[2]), "r"(a[3]), "r"(b[0]), "r"(b[1]));
}

// ---------------------------------------------------------------------------
// Kernel 0: weight split
// ---------------------------------------------------------------------------
__global__ __launch_bounds__(512) void prep_w_kernel(
    const float* __restrict__ wq, const float* __restrict__ wk,
    const float* __restrict__ wv, const float* __restrict__ wg,
    const float* __restrict__ wo) {
    int idx = blockIdx.x * 512 + threadIdx.x;
    int which = idx >> 14, off = idx & 16383;
    float w;
    if (which == 0) w = wq[off];
    else if (which == 1) w = wk[off];
    else if (which == 2) w = wv[off];
    else if (which == 3) w = wg[off];
    else w = wo[off];
    __nv_bfloat16 h = __float2bfloat16(w);
    g_wh[idx] = h;
    g_wl[idx] = __float2bfloat16(w - __bfloat162float(h));
}

// ---------------------------------------------------------------------------
// Kernel 1: LayerNorm + nb. One block (128 threads) per pair row m = i*256+j.
// ---------------------------------------------------------------------------
__global__ __launch_bounds__(128) void ln_nb_kernel(
    const float* __restrict__ pa, const float* __restrict__ sc,
    const float* __restrict__ bi, const float* __restrict__ w2d) {
    __shared__ float ws1[4], ws2[4], wnb[16];
    int m = blockIdx.x, d = threadIdx.x;
    int lane = d & 31, wid = d >> 5;

    float v = pa[(size_t)m * 128 + d];
    float s1 = v, s2 = v * v;
#pragma unroll
    for (int o = 16; o > 0; o >>= 1) {
        s1 += __shfl_xor_sync(0xffffffffu, s1, o);
        s2 += __shfl_xor_sync(0xffffffffu, s2, o);
    }
    if (lane == 0) { ws1[wid] = s1; ws2[wid] = s2; }
    __syncthreads();
    float mean = (ws1[0] + ws1[1] + ws1[2] + ws1[3]) * 0.0078125f;
    float ex2m = (ws2[0] + ws2[1] + ws2[2] + ws2[3]) * 0.0078125f;
    float var = ex2m - mean * mean;
    float x = (v - mean) * rsqrtf(var + 1e-5f) * sc[d] + bi[d];
    g_x2[(size_t)m * 128 + d] = pack_split(x);

    float p0 = x * w2d[d];
    float p1 = x * w2d[128 + d];
    float p2 = x * w2d[256 + d];
    float p3 = x * w2d[384 + d];
#pragma unroll
    for (int o = 16; o > 0; o >>= 1) {
        p0 += __shfl_xor_sync(0xffffffffu, p0, o);
        p1 += __shfl_xor_sync(0xffffffffu, p1, o);
        p2 += __shfl_xor_sync(0xffffffffu, p2, o);
        p3 += __shfl_xor_sync(0xffffffffu, p3, o);
    }
    if (lane == 0) {
        wnb[0 + wid] = p0; wnb[4 + wid] = p1;
        wnb[8 + wid] = p2; wnb[12 + wid] = p3;
    }
    __syncthreads();
    if (d < 4) {
        float nb = wnb[d * 4] + wnb[d * 4 + 1] + wnb[d * 4 + 2] + wnb[d * 4 + 3];
        g_nb[d * 65536 + m] = nb * L2E;   // [h][i*256+j], log2e folded
    }
}

// ---------------------------------------------------------------------------
// Kernels 2/4: split-bf16 tensor-core GEMM, C = A @ W^T (+ epilogue).
// Block 128(M) x 64(N), k-tile 32, 8 warps 2x4; C = Ah*Wh + Ah*Wl + Al*Wh.
// ---------------------------------------------------------------------------
__global__ __launch_bounds__(256) void mma_gemm_kernel(
    int mode, const float* __restrict__ bias,
    const float* __restrict__ mask, float* __restrict__ out) {
    __shared__ __align__(16) char smb[30720];
    const int AH = 0, AL = 10240, BH = 20480, BL = 25600;
    int tid = threadIdx.x, lane = tid & 31, wid = tid >> 5;
    int wm = wid & 1, wn = wid >> 1;
    int bx = blockIdx.x, m0 = blockIdx.y * 128;
    const unsigned int* Apk = (mode == 0) ? g_x2 : g_og2;
    int widx = (mode == 0) ? (bx >> 1) : 4;
    int nloc = (mode == 0) ? ((bx & 1) * 64) : bx * 64;
    int woff = widx * 16384;

    float c[4][2][4];
#pragma unroll
    for (int a = 0; a < 4; a++)
#pragma unroll
        for (int b = 0; b < 2; b++)
#pragma unroll
            for (int d = 0; d < 4; d++) c[a][b][d] = 0.f;

    int rowA = ((lane >> 3) & 1) * 8 + (lane & 7);
    int kofA = (lane >> 4) * 8;
    int rowB = (lane & 7) + ((lane >> 4) & 1) * 8;
    int kofB = ((lane >> 3) & 1) * 8;

    for (int kt = 0; kt < 128; kt += 32) {
        __syncthreads();
#pragma unroll
        for (int p = 0; p < 4; p++) {
            int idx = tid + p * 256;
            int r = idx >> 3, g = idx & 7;
            uint4 u = *(const uint4*)&Apk[(size_t)(m0 + r) * 128 + kt + g * 4];
            uint2 hv, lv;
            hv.x = (u.x & 0xffffu) | (u.y << 16);
            hv.y = (u.z & 0xffffu) | (u.w << 16);
            lv.x = (u.x >> 16) | (u.y & 0xffff0000u);
            lv.y = (u.z >> 16) | (u.w & 0xffff0000u);
            *(uint2*)(smb + AH + r * 80 + g * 8) = hv;
            *(uint2*)(smb + AL + r * 80 + g * 8) = lv;
        }
        {
            int r = tid >> 2, g = tid & 3;
            *(uint4*)(smb + BH + r * 80 + g * 16) =
                *(const uint4*)&g_wh[woff + (nloc + r) * 128 + kt + g * 8];
            *(uint4*)(smb + BL + r * 80 + g * 16) =
                *(const uint4*)&g_wl[woff + (nloc + r) * 128 + kt + g * 8];
        }
        __syncthreads();
#pragma unroll
        for (int ks = 0; ks < 2; ks++) {
            unsigned int ah[4][4], al[4][4], bh[4], bl[4];
#pragma unroll
            for (int mt = 0; mt < 4; mt++) {
                const char* pa = smb + AH + (wm * 64 + mt * 16 + rowA) * 80 +
                                 (ks * 16 + kofA) * 2;
                ldsm4(ah[mt], pa);
                ldsm4(al[mt], pa + (AL - AH));
            }
            const char* pb = smb + BH + (wn * 16 + rowB) * 80 +
                             (ks * 16 + kofB) * 2;
            ldsm4(bh, pb);
            ldsm4(bl, pb + (BL - BH));
#pragma unroll
            for (int mt = 0; mt < 4; mt++)
#pragma unroll
                for (int nt = 0; nt < 2; nt++) {
                    mma16816(c[mt][nt], ah[mt], &bh[nt * 2]);
                    mma16816(c[mt][nt], ah[mt], &bl[nt * 2]);
                    mma16816(c[mt][nt], al[mt], &bh[nt * 2]);
                }
        }
    }

    const float qscale = 0.17677669529663687f * L2E;  // 1/sqrt(32) * log2e
#pragma unroll
    for (int mt = 0; mt < 4; mt++) {
        int r0 = m0 + wm * 64 + mt * 16 + (lane >> 2);
#pragma unroll
        for (int nt = 0; nt < 2; nt++) {
            int n = bx * 64 + wn * 16 + nt * 8 + (lane & 3) * 2;
            float v0 = c[mt][nt][0], v1 = c[mt][nt][1];
            float v2 = c[mt][nt][2], v3 = c[mt][nt][3];
            if (mode == 0) {
                if (n < 128) {
                    v0 *= qscale; v1 *= qscale; v2 *= qscale; v3 *= qscale;
                } else if (n >= 384) {
                    float b0 = bias[n - 384], b1 = bias[n - 383];
                    v0 = 1.f / (1.f + ex2(-(v0 + b0) * L2E));
                    v1 = 1.f / (1.f + ex2(-(v1 + b1) * L2E));
                    v2 = 1.f / (1.f + ex2(-(v2 + b0) * L2E));
                    v3 = 1.f / (1.f + ex2(-(v3 + b1) * L2E));
                }
                *(float2*)&g_qkvg[(size_t)r0 * 512 + n] = make_float2(v0, v1);
                *(float2*)&g_qkvg[(size_t)(r0 + 8) * 512 + n] = make_float2(v2, v3);
            } else {
                float b0 = bias[n], b1 = bias[n + 1];
                float mk0 = mask[r0], mk1 = mask[r0 + 8];
                *(float2*)&out[(size_t)r0 * 128 + n] =
                    make_float2((v0 + b0) * mk0, (v1 + b1) * mk0);
                *(float2*)&out[(size_t)(r0 + 8) * 128 + n] =
                    make_float2((v2 + b0) * mk1, (v3 + b1) * mk1);
            }
        }
    }
}

// ---------------------------------------------------------------------------
// Kernel 3: tensor-core flash attention per (r, h). 8 warps; warp w owns
// query rows [w*32, w*32+32). Four 64-key tiles. Split-bf16 QK^T and PV.
// Logits base-2 (log2e pre-folded); softmax = single EX2 per logit.
// ---------------------------------------------------------------------------
__global__ __launch_bounds__(256, 1) void attn_mma_kernel(const float* __restrict__ mask) {
    __shared__ __align__(16) char smb[41984];
    const int QH = 0, QL = 20480;                      // 256 x 80B each (init)
    const int KH = 0, KL = 5120, VH = 10240, VL = 15360;  // 64 x 80B each (loop)
    float* bsm = (float*)(smb + 40960);                // 256 floats

    int h = blockIdx.x, r = blockIdx.y;
    int tid = threadIdx.x, lane = tid & 31, w = tid >> 5;
    size_t rowbase = (size_t)(r * 256) * 512;

    bsm[tid] = (mask[r * 256 + tid] - 1.f) * (32768.f * L2E);

    // ---- stage Q (split) and load fragments ----
#pragma unroll
    for (int p = 0; p < 8; p++) {
        int idx = tid + p * 256;            // 2048 float4 = 256 rows x 8
        int row = idx >> 3, c4 = idx & 7;
        float4 u = *(const float4*)&g_qkvg[rowbase + (size_t)row * 512 + h * 32 + c4 * 4];
        uint2 hv, lv; split4(u, hv, lv);
        *(uint2*)(smb + QH + row * 80 + c4 * 8) = hv;
        *(uint2*)(smb + QL + row * 80 + c4 * 8) = lv;
    }
    __syncthreads();

    int rowA = ((lane >> 3) & 1) * 8 + (lane & 7);
    int kofA = (lane >> 4) * 8;
    int rowB = (lane & 7) + ((lane >> 4) & 1) * 8;
    int kofB = ((lane >> 3) & 1) * 8;

    unsigned qh[2][2][4], ql[2][2][4];
#pragma unroll
    for (int mt = 0; mt < 2; mt++)
#pragma unroll
        for (int ks = 0; ks < 2; ks++) {
            const char* pq = smb + QH + (w * 32 + mt * 16 + rowA) * 80 +
                             (ks * 16 + kofA) * 2;
            ldsm4(qh[mt][ks], pq);
            ldsm4(ql[mt][ks], pq + (QL - QH));
        }

    float o[2][4][4];
#pragma unroll
    for (int mt = 0; mt < 2; mt++)
#pragma unroll
        for (int nt = 0; nt < 4; nt++)
#pragma unroll
            for (int d = 0; d < 4; d++) o[mt][nt][d] = 0.f;
    float lacc[2][2] = {{0.f, 0.f}, {0.f, 0.f}};

    for (int jt = 0; jt < 4; jt++) {
        __syncthreads();   // smem reuse barrier (Q region on first iter)
        // ---- stage K/V tile (64 keys), split hi/lo ----
#pragma unroll
        for (int p = 0; p < 2; p++) {
            int idx = tid + p * 256;        // 512 float4 = 64 rows x 8
            int row = idx >> 3, c4 = idx & 7;
            size_t base = rowbase + (size_t)(jt * 64 + row) * 512 + h * 32 + c4 * 4;
            float4 ku = *(const float4*)&g_qkvg[base + 128];
            float4 vu = *(const float4*)&g_qkvg[base + 256];
            uint2 hv, lv;
            split4(ku, hv, lv);
            *(uint2*)(smb + KH + row * 80 + c4 * 8) = hv;
            *(uint2*)(smb + KL + row * 80 + c4 * 8) = lv;
            split4(vu, hv, lv);
            *(uint2*)(smb + VH + row * 80 + c4 * 8) = hv;
            *(uint2*)(smb + VL + row * 80 + c4 * 8) = lv;
        }
        __syncthreads();

        // ---- S init = mask bias + nb ----
        float s[2][8][4];
#pragma unroll
        for (int mt = 0; mt < 2; mt++) {
            int i1 = w * 32 + mt * 16 + (lane >> 2);
            const float* nbp = g_nb + h * 65536 + i1 * 256 + jt * 64;
#pragma unroll
            for (int nt = 0; nt < 8; nt++) {
                int j0l = nt * 8 + (lane & 3) * 2;
                float2 b2 = *(float2*)&bsm[jt * 64 + j0l];
                float2 na = *(const float2*)&nbp[j0l];
                float2 nb2 = *(const float2*)&nbp[8 * 256 + j0l];
                s[mt][nt][0] = b2.x + na.x;
                s[mt][nt][1] = b2.y + na.y;
                s[mt][nt][2] = b2.x + nb2.x;
                s[mt][nt][3] = b2.y + nb2.y;
            }
        }

        // ---- QK^T (3-term split) ----
#pragma unroll
        for (int ks = 0; ks < 2; ks++)
#pragma unroll
            for (int np = 0; np < 4; np++) {
                unsigned kh4[4], kl4[4];
                const char* pk = smb + KH + (np * 16 + rowB) * 80 +
                                 (ks * 16 + kofB) * 2;
                ldsm4(kh4, pk);
                ldsm4(kl4, pk + (KL - KH));
#pragma unroll
                for (int mt = 0; mt < 2; mt++) {
                    mma16816(s[mt][np * 2], qh[mt][ks], kh4);
                    mma16816(s[mt][np * 2], qh[mt][ks], kl4);
                    mma16816(s[mt][np * 2], ql[mt][ks], kh4);
                    mma16816(s[mt][np * 2 + 1], qh[mt][ks], kh4 + 2);
                    mma16816(s[mt][np * 2 + 1], qh[mt][ks], kl4 + 2);
                    mma16816(s[mt][np * 2 + 1], ql[mt][ks], kh4 + 2);
                }
            }

        // ---- softmax exp (base-2) + pack P into A-fragments (split) ----
        unsigned ph[2][4][4], pl[2][4][4];
#pragma unroll
        for (int mt = 0; mt < 2; mt++)
#pragma unroll
            for (int kk = 0; kk < 4; kk++) {
                float e[8];
#pragma unroll
                for (int ntl = 0; ntl < 2; ntl++) {
                    int nt = kk * 2 + ntl;
                    float e0 = ex2(s[mt][nt][0]);
                    float e1 = ex2(s[mt][nt][1]);
                    float e2 = ex2(s[mt][nt][2]);
                    float e3 = ex2(s[mt][nt][3]);
                    lacc[mt][0] += e0 + e1;
                    lacc[mt][1] += e2 + e3;
                    e[ntl * 4 + 0] = e0; e[ntl * 4 + 1] = e1;
                    e[ntl * 4 + 2] = e2; e[ntl * 4 + 3] = e3;
                }
                // A-frag: a0=(r1,k0..7) a1=(r1+8,k0..7) a2=(r1,k8..15) a3=(r1+8,k8..15)
                unsigned p0 = pack2bf(e[0], e[1]);
                unsigned p1 = pack2bf(e[2], e[3]);
                unsigned p2 = pack2bf(e[4], e[5]);
                unsigned p3 = pack2bf(e[6], e[7]);
                ph[mt][kk][0] = p0; ph[mt][kk][1] = p1;
                ph[mt][kk][2] = p2; ph[mt][kk][3] = p3;
                pl[mt][kk][0] = pack2bf(e[0] - bflo(p0), e[1] - bfhi(p0));
                pl[mt][kk][1] = pack2bf(e[2] - bflo(p1), e[3] - bfhi(p1));
                pl[mt][kk][2] = pack2bf(e[4] - bflo(p2), e[5] - bfhi(p2));
                pl[mt][kk][3] = pack2bf(e[6] - bflo(p3), e[7] - bfhi(p3));
            }

        // ---- P @ V (3-term split), V^T fragments via ldmatrix.trans ----
#pragma unroll
        for (int kk = 0; kk < 4; kk++)
#pragma unroll
            for (int vg = 0; vg < 2; vg++) {
                unsigned vh4[4], vl4[4];
                const char* pv = smb + VH + (kk * 16 + (lane & 15)) * 80 +
                                 (vg * 16 + (lane >> 4) * 8) * 2;
                ldsm4t(vh4, pv);
                ldsm4t(vl4, pv + (VL - VH));
#pragma unroll
                for (int mt = 0; mt < 2; mt++) {
                    mma16816(o[mt][vg * 2], ph[mt][kk], vh4);
                    mma16816(o[mt][vg * 2], ph[mt][kk], vl4);
                    mma16816(o[mt][vg * 2], pl[mt][kk], vh4);
                    mma16816(o[mt][vg * 2 + 1], ph[mt][kk], vh4 + 2);
                    mma16816(o[mt][vg * 2 + 1], ph[mt][kk], vl4 + 2);
                    mma16816(o[mt][vg * 2 + 1], pl[mt][kk], vh4 + 2);
                }
            }
    }

    // ---- row-sum reduce (4 lanes per row) + gated epilogue ----
#pragma unroll
    for (int mt = 0; mt < 2; mt++) {
        float l0 = lacc[mt][0], l1 = lacc[mt][1];
        l0 += __shfl_xor_sync(0xffffffffu, l0, 1);
        l0 += __shfl_xor_sync(0xffffffffu, l0, 2);
        l1 += __shfl_xor_sync(0xffffffffu, l1, 1);
        l1 += __shfl_xor_sync(0xffffffffu, l1, 2);
        float rl0 = 1.f / l0, rl1 = 1.f / l1;
        int i1 = w * 32 + mt * 16 + (lane >> 2);
        size_t m0g = (size_t)(r * 256 + i1);
#pragma unroll
        for (int nt = 0; nt < 4; nt++) {
            int vd0 = nt * 8 + (lane & 3) * 2;
            float2 g0 = *(const float2*)&g_qkvg[m0g * 512 + 384 + h * 32 + vd0];
            float2 g1 = *(const float2*)&g_qkvg[(m0g + 8) * 512 + 384 + h * 32 + vd0];
            uint2 o0, o1;
            o0.x = pack_split(o[mt][nt][0] * rl0 * g0.x);
            o0.y = pack_split(o[mt][nt][1] * rl0 * g0.y);
            o1.x = pack_split(o[mt][nt][2] * rl1 * g1.x);
            o1.y = pack_split(o[mt][nt][3] * rl1 * g1.y);
            *(uint2*)&g_og2[m0g * 128 + h * 32 + vd0] = o0;
            *(uint2*)&g_og2[(m0g + 8) * 128 + h * 32 + vd0] = o1;
        }
    }
}

// ---------------------------------------------------------------------------

extern "C" void kernel_launch(void* const* d_in, const int* in_sizes, int n_in,
                              void* d_out, int out_size) {
    const float* pa  = (const float*)d_in[0];
    const float* pm  = (const float*)d_in[1];
    const float* lns = (const float*)d_in[2];
    const float* lnb = (const float*)d_in[3];
    const float* w2d = (const float*)d_in[4];
    const float* wq  = (const float*)d_in[5];
    const float* wk  = (const float*)d_in[6];
    const float* wv  = (const float*)d_in[7];
    const float* wg  = (const float*)d_in[8];
    const float* bg  = (const float*)d_in[9];
    const float* wo  = (const float*)d_in[10];
    const float* bo  = (const float*)d_in[11];
    float* out = (float*)d_out;

    prep_w_kernel<<<160, 512>>>(wq, wk, wv, wg, wo);
    ln_nb_kernel<<<65536, 128>>>(pa, lns, lnb, w2d);
    mma_gemm_kernel<<<dim3(8, 512), 256>>>(0, bg, nullptr, nullptr);
    attn_mma_kernel<<<dim3(4, 256), 256>>>(pm);
    mma_gemm_kernel<<<dim3(2, 512), 256>>>(1, bo, pm, out);
}

// round 6
// speedup vs baseline: 2.6872x; 1.0261x over previous
#include <cuda_runtime.h>
#include <cuda_bf16.h>

// TriangleAttention: B=1, N=256, D=128, H=4, kd=32
//   0. prep_w      : split wq|wk|wv|wg|wo into bf16 hi/lo planes
//   1. ln_nb       : LayerNorm -> packed split-bf16 x ; nb*log2e -> g_nb[h][i][j]
//   2. mma_gemm(0) : packed-split q|k|v -> g_qkvp, sigmoid gate -> g_gate
//   3. attn_mma    : per (r,h,qchunk) flash attention on tensor cores -> packed og
//   4. mma_gemm(1) : out = (og @ wo^T + bo) * mask

#define MTOT 65536
#define L2E 1.4426950408889634f

__device__ unsigned int g_x2[MTOT * 128];      // packed: lo16=hi bf16, hi16=lo bf16
__device__ unsigned int g_og2[MTOT * 128];
__device__ unsigned int g_qkvp[MTOT * 384];    // packed split q|k|v (q pre-scaled)
__device__ float g_gate[MTOT * 128];           // sigmoid(g+bg)
__device__ float g_nb[4 * MTOT];               // [h][i*256+j], log2e folded
__device__ __nv_bfloat16 g_wh[5 * 16384];
__device__ __nv_bfloat16 g_wl[5 * 16384];

__device__ __forceinline__ float ex2(float x) {
    float y; asm("ex2.approx.ftz.f32 %0, %1;" : "=f"(y) : "f"(x)); return y;
}
__device__ __forceinline__ unsigned pack2bf(float lo, float hi) {
    unsigned d; asm("cvt.rn.bf16x2.f32 %0, %1, %2;" : "=r"(d) : "f"(hi), "f"(lo));
    return d;
}
__device__ __forceinline__ float bflo(unsigned u) { return __uint_as_float(u << 16); }
__device__ __forceinline__ float bfhi(unsigned u) { return __uint_as_float(u & 0xffff0000u); }

__device__ __forceinline__ unsigned int pack_split(float v) {
    __nv_bfloat16 h = __float2bfloat16(v);
    float res = v - __bfloat162float(h);
    __nv_bfloat16 l = __float2bfloat16(res);
    return ((unsigned int)__bfloat16_as_ushort(l) << 16) |
           (unsigned int)__bfloat16_as_ushort(h);
}
__device__ __forceinline__ void ldsm4(unsigned int* r, const void* p) {
    unsigned int a = (unsigned int)__cvta_generic_to_shared(p);
    asm volatile("ldmatrix.sync.aligned.m8n8.x4.shared.b16 {%0,%1,%2,%3}, [%4];"
                 : "=r"(r[0]), "=r"(r[1]), "=r"(r[2]), "=r"(r[3]) : "r"(a));
}
__device__ __forceinline__ void ldsm4t(unsigned int* r, const void* p) {
    unsigned int a = (unsigned int)__cvta_generic_to_shared(p);
    asm volatile("ldmatrix.sync.aligned.m8n8.x4.trans.shared.b16 {%0,%1,%2,%3}, [%4];"
                 : "=r"(r[0]), "=r"(r[1]), "=r"(r[2]), "=r"(r[3]) : "r"(a));
}
__device__ __forceinline__ void mma16816(float* c, const unsigned int* a,
                                         const unsigned int* b) {
    asm volatile(
        "mma.sync.aligned.m16n8k16.row.col.f32.bf16.bf16.f32 "
        "{%0,%1,%2,%3}, {%4,%5,%6,%7}, {%8,%9}, {%0,%1,%2,%3};"
        : "+f"(c[0]), "+f"(c[1]), "+f"(c[2]), "+f"(c[3])
        : "r"(a[0]), "r"(a[1]), "r"(a[2]), "r"(a[3]), "r"(b[0]), "r"(b[1]));
}
// unpack packed uint4 (4 vals) -> hi-plane uint2 + lo-plane uint2
__device__ __forceinline__ void unzip4(uint4 u, uint2& hv, uint2& lv) {
    hv.x = (u.x & 0xffffu) | (u.y << 16);
    hv.y = (u.z & 0xffffu) | (u.w << 16);
    lv.x = (u.x >> 16) | (u.y & 0xffff0000u);
    lv.y = (u.z >> 16) | (u.w & 0xffff0000u);
}

// ---------------------------------------------------------------------------
// Kernel 0: weight split
// ---------------------------------------------------------------------------
__global__ __launch_bounds__(512) void prep_w_kernel(
    const float* __restrict__ wq, const float* __restrict__ wk,
    const float* __restrict__ wv, const float* __restrict__ wg,
    const float* __restrict__ wo) {
    int idx = blockIdx.x * 512 + threadIdx.x;
    int which = idx >> 14, off = idx & 16383;
    float w;
    if (which == 0) w = wq[off];
    else if (which == 1) w = wk[off];
    else if (which == 2) w = wv[off];
    else if (which == 3) w = wg[off];
    else w = wo[off];
    __nv_bfloat16 h = __float2bfloat16(w);
    g_wh[idx] = h;
    g_wl[idx] = __float2bfloat16(w - __bfloat162float(h));
}

// ---------------------------------------------------------------------------
// Kernel 1: LayerNorm + nb. One block (128 threads) per pair row m = i*256+j.
// ---------------------------------------------------------------------------
__global__ __launch_bounds__(128) void ln_nb_kernel(
    const float* __restrict__ pa, const float* __restrict__ sc,
    const float* __restrict__ bi, const float* __restrict__ w2d) {
    __shared__ float ws1[4], ws2[4], wnb[16];
    int m = blockIdx.x, d = threadIdx.x;
    int lane = d & 31, wid = d >> 5;

    float v = pa[(size_t)m * 128 + d];
    float s1 = v, s2 = v * v;
#pragma unroll
    for (int o = 16; o > 0; o >>= 1) {
        s1 += __shfl_xor_sync(0xffffffffu, s1, o);
        s2 += __shfl_xor_sync(0xffffffffu, s2, o);
    }
    if (lane == 0) { ws1[wid] = s1; ws2[wid] = s2; }
    __syncthreads();
    float mean = (ws1[0] + ws1[1] + ws1[2] + ws1[3]) * 0.0078125f;
    float ex2m = (ws2[0] + ws2[1] + ws2[2] + ws2[3]) * 0.0078125f;
    float var = ex2m - mean * mean;
    float x = (v - mean) * rsqrtf(var + 1e-5f) * sc[d] + bi[d];
    g_x2[(size_t)m * 128 + d] = pack_split(x);

    float p0 = x * w2d[d];
    float p1 = x * w2d[128 + d];
    float p2 = x * w2d[256 + d];
    float p3 = x * w2d[384 + d];
#pragma unroll
    for (int o = 16; o > 0; o >>= 1) {
        p0 += __shfl_xor_sync(0xffffffffu, p0, o);
        p1 += __shfl_xor_sync(0xffffffffu, p1, o);
        p2 += __shfl_xor_sync(0xffffffffu, p2, o);
        p3 += __shfl_xor_sync(0xffffffffu, p3, o);
    }
    if (lane == 0) {
        wnb[0 + wid] = p0; wnb[4 + wid] = p1;
        wnb[8 + wid] = p2; wnb[12 + wid] = p3;
    }
    __syncthreads();
    if (d < 4) {
        float nb = wnb[d * 4] + wnb[d * 4 + 1] + wnb[d * 4 + 2] + wnb[d * 4 + 3];
        g_nb[d * 65536 + m] = nb * L2E;
    }
}

// ---------------------------------------------------------------------------
// Kernels 2/4: split-bf16 tensor-core GEMM, C = A @ W^T (+ epilogue).
// Block 128(M) x 64(N), k-tile 32, 8 warps 2x4; C = Ah*Wh + Ah*Wl + Al*Wh.
// mode 0: q*scale*log2e|k|v -> packed split g_qkvp ; sigmoid gate -> g_gate
// mode 1: (c + bo) * mask -> out
// ---------------------------------------------------------------------------
__global__ __launch_bounds__(256) void mma_gemm_kernel(
    int mode, const float* __restrict__ bias,
    const float* __restrict__ mask, float* __restrict__ out) {
    __shared__ __align__(16) char smb[30720];
    const int AH = 0, AL = 10240, BH = 20480, BL = 25600;
    int tid = threadIdx.x, lane = tid & 31, wid = tid >> 5;
    int wm = wid & 1, wn = wid >> 1;
    int bx = blockIdx.x, m0 = blockIdx.y * 128;
    const unsigned int* Apk = (mode == 0) ? g_x2 : g_og2;
    int widx = (mode == 0) ? (bx >> 1) : 4;
    int nloc = (mode == 0) ? ((bx & 1) * 64) : bx * 64;
    int woff = widx * 16384;

    float c[4][2][4];
#pragma unroll
    for (int a = 0; a < 4; a++)
#pragma unroll
        for (int b = 0; b < 2; b++)
#pragma unroll
            for (int d = 0; d < 4; d++) c[a][b][d] = 0.f;

    int rowA = ((lane >> 3) & 1) * 8 + (lane & 7);
    int kofA = (lane >> 4) * 8;
    int rowB = (lane & 7) + ((lane >> 4) & 1) * 8;
    int kofB = ((lane >> 3) & 1) * 8;

    for (int kt = 0; kt < 128; kt += 32) {
        __syncthreads();
#pragma unroll
        for (int p = 0; p < 4; p++) {
            int idx = tid + p * 256;
            int r = idx >> 3, g = idx & 7;
            uint4 u = *(const uint4*)&Apk[(size_t)(m0 + r) * 128 + kt + g * 4];
            uint2 hv, lv; unzip4(u, hv, lv);
            *(uint2*)(smb + AH + r * 80 + g * 8) = hv;
            *(uint2*)(smb + AL + r * 80 + g * 8) = lv;
        }
        {
            int r = tid >> 2, g = tid & 3;
            *(uint4*)(smb + BH + r * 80 + g * 16) =
                *(const uint4*)&g_wh[woff + (nloc + r) * 128 + kt + g * 8];
            *(uint4*)(smb + BL + r * 80 + g * 16) =
                *(const uint4*)&g_wl[woff + (nloc + r) * 128 + kt + g * 8];
        }
        __syncthreads();
#pragma unroll
        for (int ks = 0; ks < 2; ks++) {
            unsigned int ah[4][4], al[4][4], bh[4], bl[4];
#pragma unroll
            for (int mt = 0; mt < 4; mt++) {
                const char* pa = smb + AH + (wm * 64 + mt * 16 + rowA) * 80 +
                                 (ks * 16 + kofA) * 2;
                ldsm4(ah[mt], pa);
                ldsm4(al[mt], pa + (AL - AH));
            }
            const char* pb = smb + BH + (wn * 16 + rowB) * 80 +
                             (ks * 16 + kofB) * 2;
            ldsm4(bh, pb);
            ldsm4(bl, pb + (BL - BH));
#pragma unroll
            for (int mt = 0; mt < 4; mt++)
#pragma unroll
                for (int nt = 0; nt < 2; nt++) {
                    mma16816(c[mt][nt], ah[mt], &bh[nt * 2]);
                    mma16816(c[mt][nt], ah[mt], &bl[nt * 2]);
                    mma16816(c[mt][nt], al[mt], &bh[nt * 2]);
                }
        }
    }

    const float qscale = 0.17677669529663687f * L2E;
#pragma unroll
    for (int mt = 0; mt < 4; mt++) {
        int r0 = m0 + wm * 64 + mt * 16 + (lane >> 2);
#pragma unroll
        for (int nt = 0; nt < 2; nt++) {
            int n = bx * 64 + wn * 16 + nt * 8 + (lane & 3) * 2;
            float v0 = c[mt][nt][0], v1 = c[mt][nt][1];
            float v2 = c[mt][nt][2], v3 = c[mt][nt][3];
            if (mode == 0) {
                if (n >= 384) {
                    float b0 = bias[n - 384], b1 = bias[n - 383];
                    v0 = 1.f / (1.f + ex2(-(v0 + b0) * L2E));
                    v1 = 1.f / (1.f + ex2(-(v1 + b1) * L2E));
                    v2 = 1.f / (1.f + ex2(-(v2 + b0) * L2E));
                    v3 = 1.f / (1.f + ex2(-(v3 + b1) * L2E));
                    *(float2*)&g_gate[(size_t)r0 * 128 + n - 384] = make_float2(v0, v1);
                    *(float2*)&g_gate[(size_t)(r0 + 8) * 128 + n - 384] = make_float2(v2, v3);
                } else {
                    if (n < 128) {
                        v0 *= qscale; v1 *= qscale; v2 *= qscale; v3 *= qscale;
                    }
                    uint2 s0, s1;
                    s0.x = pack_split(v0); s0.y = pack_split(v1);
                    s1.x = pack_split(v2); s1.y = pack_split(v3);
                    *(uint2*)&g_qkvp[(size_t)r0 * 384 + n] = s0;
                    *(uint2*)&g_qkvp[(size_t)(r0 + 8) * 384 + n] = s1;
                }
            } else {
                float b0 = bias[n], b1 = bias[n + 1];
                float mk0 = mask[r0], mk1 = mask[r0 + 8];
                *(float2*)&out[(size_t)r0 * 128 + n] =
                    make_float2((v0 + b0) * mk0, (v1 + b1) * mk0);
                *(float2*)&out[(size_t)(r0 + 8) * 128 + n] =
                    make_float2((v2 + b0) * mk1, (v3 + b1) * mk1);
            }
        }
    }
}

// ---------------------------------------------------------------------------
// Kernel 3: tensor-core flash attention. CTA = 128 threads (4 warps),
// 64 query rows; warp w owns rows [w*16, w*16+16). grid (4, 1024):
// h = bx, r = by>>2, qchunk = by&3. Four 64-key tiles; split-bf16 MMA;
// base-2 logits -> single EX2 per element.
// ---------------------------------------------------------------------------
__global__ __launch_bounds__(128, 3) void attn_mma_kernel(const float* __restrict__ mask) {
    __shared__ __align__(16) char smb[21504];
    const int KH = 0, KL = 5120, VH = 10240, VL = 15360;   // 64 x 80B each
    const int QH = 0, QL = 5120;                           // Q staging (pre-loop)
    float* bsm = (float*)(smb + 20480);                    // 256 floats

    int h = blockIdx.x;
    int r = blockIdx.y >> 2, qc = blockIdx.y & 3;
    int tid = threadIdx.x, lane = tid & 31, w = tid >> 5;
    int q0 = qc * 64;
    size_t rowbase = (size_t)(r * 256) * 384;

    bsm[tid] = (mask[r * 256 + tid] - 1.f) * (32768.f * L2E);
    bsm[tid + 128] = (mask[r * 256 + tid + 128] - 1.f) * (32768.f * L2E);

    // ---- stage this CTA's 64 Q rows (packed -> hi/lo planes) ----
#pragma unroll
    for (int p = 0; p < 4; p++) {
        int idx = tid + p * 128;            // 512 = 64 rows x 8 groups
        int row = idx >> 3, c4 = idx & 7;
        uint4 u = *(const uint4*)&g_qkvp[rowbase + (size_t)(q0 + row) * 384 +
                                         h * 32 + c4 * 4];
        uint2 hv, lv; unzip4(u, hv, lv);
        *(uint2*)(smb + QH + row * 80 + c4 * 8) = hv;
        *(uint2*)(smb + QL + row * 80 + c4 * 8) = lv;
    }
    __syncthreads();

    int rowA = ((lane >> 3) & 1) * 8 + (lane & 7);
    int kofA = (lane >> 4) * 8;
    int rowB = (lane & 7) + ((lane >> 4) & 1) * 8;
    int kofB = ((lane >> 3) & 1) * 8;

    unsigned qh[2][4], ql[2][4];
#pragma unroll
    for (int ks = 0; ks < 2; ks++) {
        const char* pq = smb + QH + (w * 16 + rowA) * 80 + (ks * 16 + kofA) * 2;
        ldsm4(qh[ks], pq);
        ldsm4(ql[ks], pq + (QL - QH));
    }

    float o[4][4];
#pragma unroll
    for (int nt = 0; nt < 4; nt++)
#pragma unroll
        for (int d = 0; d < 4; d++) o[nt][d] = 0.f;
    float lacc[2] = {0.f, 0.f};

    int i1 = q0 + w * 16 + (lane >> 2);
    const float* nbrow = g_nb + h * 65536 + i1 * 256;

    for (int jt = 0; jt < 4; jt++) {
        __syncthreads();   // protects Q region (first iter) / prev tile
        // ---- stage K/V tile (64 keys, packed -> hi/lo planes) ----
#pragma unroll
        for (int p = 0; p < 4; p++) {
            int idx = tid + p * 128;
            int row = idx >> 3, c4 = idx & 7;
            size_t base = rowbase + (size_t)(jt * 64 + row) * 384 + h * 32 + c4 * 4;
            uint2 hv, lv;
            unzip4(*(const uint4*)&g_qkvp[base + 128], hv, lv);
            *(uint2*)(smb + KH + row * 80 + c4 * 8) = hv;
            *(uint2*)(smb + KL + row * 80 + c4 * 8) = lv;
            unzip4(*(const uint4*)&g_qkvp[base + 256], hv, lv);
            *(uint2*)(smb + VH + row * 80 + c4 * 8) = hv;
            *(uint2*)(smb + VL + row * 80 + c4 * 8) = lv;
        }
        __syncthreads();

        // ---- S init = mask bias + nb ----
        float s[8][4];
#pragma unroll
        for (int nt = 0; nt < 8; nt++) {
            int j0l = nt * 8 + (lane & 3) * 2;
            float2 b2 = *(float2*)&bsm[jt * 64 + j0l];
            float2 na = *(const float2*)&nbrow[jt * 64 + j0l];
            float2 nb2 = *(const float2*)&nbrow[8 * 256 + jt * 64 + j0l];
            s[nt][0] = b2.x + na.x;
            s[nt][1] = b2.y + na.y;
            s[nt][2] = b2.x + nb2.x;
            s[nt][3] = b2.y + nb2.y;
        }

        // ---- QK^T (3-term split) ----
#pragma unroll
        for (int ks = 0; ks < 2; ks++)
#pragma unroll
            for (int np = 0; np < 4; np++) {
                unsigned kh4[4], kl4[4];
                const char* pk = smb + KH + (np * 16 + rowB) * 80 +
                                 (ks * 16 + kofB) * 2;
                ldsm4(kh4, pk);
                ldsm4(kl4, pk + (KL - KH));
                mma16816(s[np * 2], qh[ks], kh4);
                mma16816(s[np * 2], qh[ks], kl4);
                mma16816(s[np * 2], ql[ks], kh4);
                mma16816(s[np * 2 + 1], qh[ks], kh4 + 2);
                mma16816(s[np * 2 + 1], qh[ks], kl4 + 2);
                mma16816(s[np * 2 + 1], ql[ks], kh4 + 2);
            }

        // ---- EX2 softmax + pack P A-fragments (split) ----
        unsigned ph[4][4], pl[4][4];
#pragma unroll
        for (int kk = 0; kk < 4; kk++) {
            float e[8];
#pragma unroll
            for (int ntl = 0; ntl < 2; ntl++) {
                int nt = kk * 2 + ntl;
                float e0 = ex2(s[nt][0]);
                float e1 = ex2(s[nt][1]);
                float e2 = ex2(s[nt][2]);
                float e3 = ex2(s[nt][3]);
                lacc[0] += e0 + e1;
                lacc[1] += e2 + e3;
                e[ntl * 4 + 0] = e0; e[ntl * 4 + 1] = e1;
                e[ntl * 4 + 2] = e2; e[ntl * 4 + 3] = e3;
            }
            unsigned p0 = pack2bf(e[0], e[1]);
            unsigned p1 = pack2bf(e[2], e[3]);
            unsigned p2 = pack2bf(e[4], e[5]);
            unsigned p3 = pack2bf(e[6], e[7]);
            ph[kk][0] = p0; ph[kk][1] = p1; ph[kk][2] = p2; ph[kk][3] = p3;
            pl[kk][0] = pack2bf(e[0] - bflo(p0), e[1] - bfhi(p0));
            pl[kk][1] = pack2bf(e[2] - bflo(p1), e[3] - bfhi(p1));
            pl[kk][2] = pack2bf(e[4] - bflo(p2), e[5] - bfhi(p2));
            pl[kk][3] = pack2bf(e[6] - bflo(p3), e[7] - bfhi(p3));
        }

        // ---- P @ V (3-term split), V^T via ldmatrix.trans ----
#pragma unroll
        for (int kk = 0; kk < 4; kk++)
#pragma unroll
            for (int vg = 0; vg < 2; vg++) {
                unsigned vh4[4], vl4[4];
                const char* pv = smb + VH + (kk * 16 + (lane & 15)) * 80 +
                                 (vg * 16 + (lane >> 4) * 8) * 2;
                ldsm4t(vh4, pv);
                ldsm4t(vl4, pv + (VL - VH));
                mma16816(o[vg * 2], ph[kk], vh4);
                mma16816(o[vg * 2], ph[kk], vl4);
                mma16816(o[vg * 2], pl[kk], vh4);
                mma16816(o[vg * 2 + 1], ph[kk], vh4 + 2);
                mma16816(o[vg * 2 + 1], ph[kk], vl4 + 2);
                mma16816(o[vg * 2 + 1], pl[kk], vh4 + 2);
            }
    }

    // ---- row-sum reduce + gated epilogue ----
    float l0 = lacc[0], l1 = lacc[1];
    l0 += __shfl_xor_sync(0xffffffffu, l0, 1);
    l0 += __shfl_xor_sync(0xffffffffu, l0, 2);
    l1 += __shfl_xor_sync(0xffffffffu, l1, 1);
    l1 += __shfl_xor_sync(0xffffffffu, l1, 2);
    float rl0 = 1.f / l0, rl1 = 1.f / l1;
    size_t m0g = (size_t)(r * 256 + i1);
#pragma unroll
    for (int nt = 0; nt < 4; nt++) {
        int vd0 = nt * 8 + (lane & 3) * 2;
        float2 g0 = *(const float2*)&g_gate[m0g * 128 + h * 32 + vd0];
        float2 g1 = *(const float2*)&g_gate[(m0g + 8) * 128 + h * 32 + vd0];
        uint2 o0, o1;
        o0.x = pack_split(o[nt][0] * rl0 * g0.x);
        o0.y = pack_split(o[nt][1] * rl0 * g0.y);
        o1.x = pack_split(o[nt][2] * rl1 * g1.x);
        o1.y = pack_split(o[nt][3] * rl1 * g1.y);
        *(uint2*)&g_og2[m0g * 128 + h * 32 + vd0] = o0;
        *(uint2*)&g_og2[(m0g + 8) * 128 + h * 32 + vd0] = o1;
    }
}

// ---------------------------------------------------------------------------

extern "C" void kernel_launch(void* const* d_in, const int* in_sizes, int n_in,
                              void* d_out, int out_size) {
    const float* pa  = (const float*)d_in[0];
    const float* pm  = (const float*)d_in[1];
    const float* lns = (const float*)d_in[2];
    const float* lnb = (const float*)d_in[3];
    const float* w2d = (const float*)d_in[4];
    const float* wq  = (const float*)d_in[5];
    const float* wk  = (const float*)d_in[6];
    const float* wv  = (const float*)d_in[7];
    const float* wg  = (const float*)d_in[8];
    const float* bg  = (const float*)d_in[9];
    const float* wo  = (const float*)d_in[10];
    const float* bo  = (const float*)d_in[11];
    float* out = (float*)d_out;

    prep_w_kernel<<<160, 512>>>(wq, wk, wv, wg, wo);
    ln_nb_kernel<<<65536, 128>>>(pa, lns, lnb, w2d);
    mma_gemm_kernel<<<dim3(8, 512), 256>>>(0, bg, nullptr, nullptr);
    attn_mma_kernel<<<dim3(4, 1024), 128>>>(pm);
    mma_gemm_kernel<<<dim3(2, 512), 256>>>(1, bo, pm, out);
}

// round 7
// speedup vs baseline: 2.7201x; 1.0123x over previous
#include <cuda_runtime.h>
#include <cuda_bf16.h>

// TriangleAttention: B=1, N=256, D=128, H=4, kd=32
//   0. prep_w      : split wq|wk|wv|wg|wo into bf16 hi/lo planes
//   1. ln_nb       : LayerNorm -> packed split-bf16 x ; nb*log2e -> g_nb[h][i][j]
//   2. mma_gemm(0) : packed-split q|k|v -> g_qkvp, sigmoid gate -> g_gate
//   3. attn_mma    : per (r,h,qhalf) flash attention on tensor cores -> packed og
//                    (warp = 32 q-rows: K/V fragments reused across 2 M-tiles)
//   4. mma_gemm(1) : out = (og @ wo^T + bo) * mask

#define MTOT 65536
#define L2E 1.4426950408889634f

__device__ unsigned int g_x2[MTOT * 128];      // packed: lo16=hi bf16, hi16=lo bf16
__device__ unsigned int g_og2[MTOT * 128];
__device__ unsigned int g_qkvp[MTOT * 384];    // packed split q|k|v (q pre-scaled)
__device__ float g_gate[MTOT * 128];           // sigmoid(g+bg)
__device__ float g_nb[4 * MTOT];               // [h][i*256+j], log2e folded
__device__ __nv_bfloat16 g_wh[5 * 16384];
__device__ __nv_bfloat16 g_wl[5 * 16384];

__device__ __forceinline__ float ex2(float x) {
    float y; asm("ex2.approx.ftz.f32 %0, %1;" : "=f"(y) : "f"(x)); return y;
}
__device__ __forceinline__ unsigned pack2bf(float lo, float hi) {
    unsigned d; asm("cvt.rn.bf16x2.f32 %0, %1, %2;" : "=r"(d) : "f"(hi), "f"(lo));
    return d;
}
__device__ __forceinline__ float bflo(unsigned u) { return __uint_as_float(u << 16); }
__device__ __forceinline__ float bfhi(unsigned u) { return __uint_as_float(u & 0xffff0000u); }

__device__ __forceinline__ unsigned int pack_split(float v) {
    __nv_bfloat16 h = __float2bfloat16(v);
    float res = v - __bfloat162float(h);
    __nv_bfloat16 l = __float2bfloat16(res);
    return ((unsigned int)__bfloat16_as_ushort(l) << 16) |
           (unsigned int)__bfloat16_as_ushort(h);
}
__device__ __forceinline__ void ldsm4(unsigned int* r, const void* p) {
    unsigned int a = (unsigned int)__cvta_generic_to_shared(p);
    asm volatile("ldmatrix.sync.aligned.m8n8.x4.shared.b16 {%0,%1,%2,%3}, [%4];"
                 : "=r"(r[0]), "=r"(r[1]), "=r"(r[2]), "=r"(r[3]) : "r"(a));
}
__device__ __forceinline__ void ldsm4t(unsigned int* r, const void* p) {
    unsigned int a = (unsigned int)__cvta_generic_to_shared(p);
    asm volatile("ldmatrix.sync.aligned.m8n8.x4.trans.shared.b16 {%0,%1,%2,%3}, [%4];"
                 : "=r"(r[0]), "=r"(r[1]), "=r"(r[2]), "=r"(r[3]) : "r"(a));
}
__device__ __forceinline__ void mma16816(float* c, const unsigned int* a,
                                         const unsigned int* b) {
    asm volatile(
        "mma.sync.aligned.m16n8k16.row.col.f32.bf16.bf16.f32 "
        "{%0,%1,%2,%3}, {%4,%5,%6,%7}, {%8,%9}, {%0,%1,%2,%3};"
        : "+f"(c[0]), "+f"(c[1]), "+f"(c[2]), "+f"(c[3])
        : "r"(a[0]), "r"(a[1]), "r"(a[2]), "r"(a[3]), "r"(b[0]), "r"(b[1]));
}
// unpack packed uint4 (4 vals) -> hi-plane uint2 + lo-plane uint2
__device__ __forceinline__ void unzip4(uint4 u, uint2& hv, uint2& lv) {
    hv.x = (u.x & 0xffffu) | (u.y << 16);
    hv.y = (u.z & 0xffffu) | (u.w << 16);
    lv.x = (u.x >> 16) | (u.y & 0xffff0000u);
    lv.y = (u.z >> 16) | (u.w & 0xffff0000u);
}

// ---------------------------------------------------------------------------
// Kernel 0: weight split
// ---------------------------------------------------------------------------
__global__ __launch_bounds__(512) void prep_w_kernel(
    const float* __restrict__ wq, const float* __restrict__ wk,
    const float* __restrict__ wv, const float* __restrict__ wg,
    const float* __restrict__ wo) {
    int idx = blockIdx.x * 512 + threadIdx.x;
    int which = idx >> 14, off = idx & 16383;
    float w;
    if (which == 0) w = wq[off];
    else if (which == 1) w = wk[off];
    else if (which == 2) w = wv[off];
    else if (which == 3) w = wg[off];
    else w = wo[off];
    __nv_bfloat16 h = __float2bfloat16(w);
    g_wh[idx] = h;
    g_wl[idx] = __float2bfloat16(w - __bfloat162float(h));
}

// ---------------------------------------------------------------------------
// Kernel 1: LayerNorm + nb. One block (128 threads) per pair row m = i*256+j.
// ---------------------------------------------------------------------------
__global__ __launch_bounds__(128) void ln_nb_kernel(
    const float* __restrict__ pa, const float* __restrict__ sc,
    const float* __restrict__ bi, const float* __restrict__ w2d) {
    __shared__ float ws1[4], ws2[4], wnb[16];
    int m = blockIdx.x, d = threadIdx.x;
    int lane = d & 31, wid = d >> 5;

    float v = pa[(size_t)m * 128 + d];
    float s1 = v, s2 = v * v;
#pragma unroll
    for (int o = 16; o > 0; o >>= 1) {
        s1 += __shfl_xor_sync(0xffffffffu, s1, o);
        s2 += __shfl_xor_sync(0xffffffffu, s2, o);
    }
    if (lane == 0) { ws1[wid] = s1; ws2[wid] = s2; }
    __syncthreads();
    float mean = (ws1[0] + ws1[1] + ws1[2] + ws1[3]) * 0.0078125f;
    float ex2m = (ws2[0] + ws2[1] + ws2[2] + ws2[3]) * 0.0078125f;
    float var = ex2m - mean * mean;
    float x = (v - mean) * rsqrtf(var + 1e-5f) * sc[d] + bi[d];
    g_x2[(size_t)m * 128 + d] = pack_split(x);

    float p0 = x * w2d[d];
    float p1 = x * w2d[128 + d];
    float p2 = x * w2d[256 + d];
    float p3 = x * w2d[384 + d];
#pragma unroll
    for (int o = 16; o > 0; o >>= 1) {
        p0 += __shfl_xor_sync(0xffffffffu, p0, o);
        p1 += __shfl_xor_sync(0xffffffffu, p1, o);
        p2 += __shfl_xor_sync(0xffffffffu, p2, o);
        p3 += __shfl_xor_sync(0xffffffffu, p3, o);
    }
    if (lane == 0) {
        wnb[0 + wid] = p0; wnb[4 + wid] = p1;
        wnb[8 + wid] = p2; wnb[12 + wid] = p3;
    }
    __syncthreads();
    if (d < 4) {
        float nb = wnb[d * 4] + wnb[d * 4 + 1] + wnb[d * 4 + 2] + wnb[d * 4 + 3];
        g_nb[d * 65536 + m] = nb * L2E;
    }
}

// ---------------------------------------------------------------------------
// Kernels 2/4: split-bf16 tensor-core GEMM, C = A @ W^T (+ epilogue).
// Block 128(M) x 64(N), k-tile 32, 8 warps 2x4; C = Ah*Wh + Ah*Wl + Al*Wh.
// mode 0: q*scale*log2e|k|v -> packed split g_qkvp ; sigmoid gate -> g_gate
// mode 1: (c + bo) * mask -> out
// ---------------------------------------------------------------------------
__global__ __launch_bounds__(256) void mma_gemm_kernel(
    int mode, const float* __restrict__ bias,
    const float* __restrict__ mask, float* __restrict__ out) {
    __shared__ __align__(16) char smb[30720];
    const int AH = 0, AL = 10240, BH = 20480, BL = 25600;
    int tid = threadIdx.x, lane = tid & 31, wid = tid >> 5;
    int wm = wid & 1, wn = wid >> 1;
    int bx = blockIdx.x, m0 = blockIdx.y * 128;
    const unsigned int* Apk = (mode == 0) ? g_x2 : g_og2;
    int widx = (mode == 0) ? (bx >> 1) : 4;
    int nloc = (mode == 0) ? ((bx & 1) * 64) : bx * 64;
    int woff = widx * 16384;

    float c[4][2][4];
#pragma unroll
    for (int a = 0; a < 4; a++)
#pragma unroll
        for (int b = 0; b < 2; b++)
#pragma unroll
            for (int d = 0; d < 4; d++) c[a][b][d] = 0.f;

    int rowA = ((lane >> 3) & 1) * 8 + (lane & 7);
    int kofA = (lane >> 4) * 8;
    int rowB = (lane & 7) + ((lane >> 4) & 1) * 8;
    int kofB = ((lane >> 3) & 1) * 8;

    for (int kt = 0; kt < 128; kt += 32) {
        __syncthreads();
#pragma unroll
        for (int p = 0; p < 4; p++) {
            int idx = tid + p * 256;
            int r = idx >> 3, g = idx & 7;
            uint4 u = *(const uint4*)&Apk[(size_t)(m0 + r) * 128 + kt + g * 4];
            uint2 hv, lv; unzip4(u, hv, lv);
            *(uint2*)(smb + AH + r * 80 + g * 8) = hv;
            *(uint2*)(smb + AL + r * 80 + g * 8) = lv;
        }
        {
            int r = tid >> 2, g = tid & 3;
            *(uint4*)(smb + BH + r * 80 + g * 16) =
                *(const uint4*)&g_wh[woff + (nloc + r) * 128 + kt + g * 8];
            *(uint4*)(smb + BL + r * 80 + g * 16) =
                *(const uint4*)&g_wl[woff + (nloc + r) * 128 + kt + g * 8];
        }
        __syncthreads();
#pragma unroll
        for (int ks = 0; ks < 2; ks++) {
            unsigned int ah[4][4], al[4][4], bh[4], bl[4];
#pragma unroll
            for (int mt = 0; mt < 4; mt++) {
                const char* pa = smb + AH + (wm * 64 + mt * 16 + rowA) * 80 +
                                 (ks * 16 + kofA) * 2;
                ldsm4(ah[mt], pa);
                ldsm4(al[mt], pa + (AL - AH));
            }
            const char* pb = smb + BH + (wn * 16 + rowB) * 80 +
                             (ks * 16 + kofB) * 2;
            ldsm4(bh, pb);
            ldsm4(bl, pb + (BL - BH));
#pragma unroll
            for (int mt = 0; mt < 4; mt++)
#pragma unroll
                for (int nt = 0; nt < 2; nt++) {
                    mma16816(c[mt][nt], ah[mt], &bh[nt * 2]);
                    mma16816(c[mt][nt], ah[mt], &bl[nt * 2]);
                    mma16816(c[mt][nt], al[mt], &bh[nt * 2]);
                }
        }
    }

    const float qscale = 0.17677669529663687f * L2E;
#pragma unroll
    for (int mt = 0; mt < 4; mt++) {
        int r0 = m0 + wm * 64 + mt * 16 + (lane >> 2);
#pragma unroll
        for (int nt = 0; nt < 2; nt++) {
            int n = bx * 64 + wn * 16 + nt * 8 + (lane & 3) * 2;
            float v0 = c[mt][nt][0], v1 = c[mt][nt][1];
            float v2 = c[mt][nt][2], v3 = c[mt][nt][3];
            if (mode == 0) {
                if (n >= 384) {
                    float b0 = bias[n - 384], b1 = bias[n - 383];
                    v0 = 1.f / (1.f + ex2(-(v0 + b0) * L2E));
                    v1 = 1.f / (1.f + ex2(-(v1 + b1) * L2E));
                    v2 = 1.f / (1.f + ex2(-(v2 + b0) * L2E));
                    v3 = 1.f / (1.f + ex2(-(v3 + b1) * L2E));
                    *(float2*)&g_gate[(size_t)r0 * 128 + n - 384] = make_float2(v0, v1);
                    *(float2*)&g_gate[(size_t)(r0 + 8) * 128 + n - 384] = make_float2(v2, v3);
                } else {
                    if (n < 128) {
                        v0 *= qscale; v1 *= qscale; v2 *= qscale; v3 *= qscale;
                    }
                    uint2 s0, s1;
                    s0.x = pack_split(v0); s0.y = pack_split(v1);
                    s1.x = pack_split(v2); s1.y = pack_split(v3);
                    *(uint2*)&g_qkvp[(size_t)r0 * 384 + n] = s0;
                    *(uint2*)&g_qkvp[(size_t)(r0 + 8) * 384 + n] = s1;
                }
            } else {
                float b0 = bias[n], b1 = bias[n + 1];
                float mk0 = mask[r0], mk1 = mask[r0 + 8];
                *(float2*)&out[(size_t)r0 * 128 + n] =
                    make_float2((v0 + b0) * mk0, (v1 + b1) * mk0);
                *(float2*)&out[(size_t)(r0 + 8) * 128 + n] =
                    make_float2((v2 + b0) * mk1, (v3 + b1) * mk1);
            }
        }
    }
}

// ---------------------------------------------------------------------------
// Kernel 3: tensor-core flash attention. CTA = 128 threads (4 warps),
// 128 query rows; warp w owns rows [w*32, w*32+32) (two 16-row M-tiles ->
// K/V fragments reused twice). grid (4, 512): h = bx, r = by>>1, qhalf = by&1.
// Four 64-key tiles; split-bf16 MMA; base-2 logits -> single EX2 per element.
// Q staged in smem (20KB) then register-resident; K/V overlay the Q region.
// ---------------------------------------------------------------------------
__global__ __launch_bounds__(128, 2) void attn_mma_kernel(const float* __restrict__ mask) {
    __shared__ __align__(16) char smb[21504];
    const int KH = 0, KL = 5120, VH = 10240, VL = 15360;   // 64 x 80B each
    const int QH = 0, QL = 10240;                          // 128 x 80B each (init)
    float* bsm = (float*)(smb + 20480);                    // 256 floats

    int h = blockIdx.x;
    int r = blockIdx.y >> 1, qc = blockIdx.y & 1;
    int tid = threadIdx.x, lane = tid & 31, w = tid >> 5;
    int q0 = qc * 128;
    size_t rowbase = (size_t)(r * 256) * 384;

    bsm[tid] = (mask[r * 256 + tid] - 1.f) * (32768.f * L2E);
    bsm[tid + 128] = (mask[r * 256 + tid + 128] - 1.f) * (32768.f * L2E);

    // ---- stage this CTA's 128 Q rows (packed -> hi/lo planes) ----
#pragma unroll
    for (int p = 0; p < 8; p++) {
        int idx = tid + p * 128;            // 1024 = 128 rows x 8 groups
        int row = idx >> 3, c4 = idx & 7;
        uint4 u = *(const uint4*)&g_qkvp[rowbase + (size_t)(q0 + row) * 384 +
                                         h * 32 + c4 * 4];
        uint2 hv, lv; unzip4(u, hv, lv);
        *(uint2*)(smb + QH + row * 80 + c4 * 8) = hv;
        *(uint2*)(smb + QL + row * 80 + c4 * 8) = lv;
    }
    __syncthreads();

    int rowA = ((lane >> 3) & 1) * 8 + (lane & 7);
    int kofA = (lane >> 4) * 8;
    int rowB = (lane & 7) + ((lane >> 4) & 1) * 8;
    int kofB = ((lane >> 3) & 1) * 8;

    unsigned qh[2][2][4], ql[2][2][4];
#pragma unroll
    for (int mt = 0; mt < 2; mt++)
#pragma unroll
        for (int ks = 0; ks < 2; ks++) {
            const char* pq = smb + QH + (w * 32 + mt * 16 + rowA) * 80 +
                             (ks * 16 + kofA) * 2;
            ldsm4(qh[mt][ks], pq);
            ldsm4(ql[mt][ks], pq + (QL - QH));
        }

    float o[2][4][4];
#pragma unroll
    for (int mt = 0; mt < 2; mt++)
#pragma unroll
        for (int nt = 0; nt < 4; nt++)
#pragma unroll
            for (int d = 0; d < 4; d++) o[mt][nt][d] = 0.f;
    float lacc[2][2] = {{0.f, 0.f}, {0.f, 0.f}};

    int i1 = q0 + w * 32 + (lane >> 2);                 // mt=0 row; mt=1 is +16
    const float* nbrow = g_nb + h * 65536 + i1 * 256;

    for (int jt = 0; jt < 4; jt++) {
        __syncthreads();   // protects Q region (first iter) / prev tile
        // ---- stage K/V tile (64 keys, packed -> hi/lo planes) ----
#pragma unroll
        for (int p = 0; p < 4; p++) {
            int idx = tid + p * 128;
            int row = idx >> 3, c4 = idx & 7;
            size_t base = rowbase + (size_t)(jt * 64 + row) * 384 + h * 32 + c4 * 4;
            uint2 hv, lv;
            unzip4(*(const uint4*)&g_qkvp[base + 128], hv, lv);
            *(uint2*)(smb + KH + row * 80 + c4 * 8) = hv;
            *(uint2*)(smb + KL + row * 80 + c4 * 8) = lv;
            unzip4(*(const uint4*)&g_qkvp[base + 256], hv, lv);
            *(uint2*)(smb + VH + row * 80 + c4 * 8) = hv;
            *(uint2*)(smb + VL + row * 80 + c4 * 8) = lv;
        }
        __syncthreads();

        // ---- S init = mask bias + nb ----
        float s[2][8][4];
#pragma unroll
        for (int mt = 0; mt < 2; mt++) {
            const float* nbp = nbrow + mt * (16 * 256) + jt * 64;
#pragma unroll
            for (int nt = 0; nt < 8; nt++) {
                int j0l = nt * 8 + (lane & 3) * 2;
                float2 b2 = *(float2*)&bsm[jt * 64 + j0l];
                float2 na = *(const float2*)&nbp[j0l];
                float2 nb2 = *(const float2*)&nbp[8 * 256 + j0l];
                s[mt][nt][0] = b2.x + na.x;
                s[mt][nt][1] = b2.y + na.y;
                s[mt][nt][2] = b2.x + nb2.x;
                s[mt][nt][3] = b2.y + nb2.y;
            }
        }

        // ---- QK^T (3-term split); K frags reused across both M-tiles ----
#pragma unroll
        for (int ks = 0; ks < 2; ks++)
#pragma unroll
            for (int np = 0; np < 4; np++) {
                unsigned kh4[4], kl4[4];
                const char* pk = smb + KH + (np * 16 + rowB) * 80 +
                                 (ks * 16 + kofB) * 2;
                ldsm4(kh4, pk);
                ldsm4(kl4, pk + (KL - KH));
#pragma unroll
                for (int mt = 0; mt < 2; mt++) {
                    mma16816(s[mt][np * 2], qh[mt][ks], kh4);
                    mma16816(s[mt][np * 2], qh[mt][ks], kl4);
                    mma16816(s[mt][np * 2], ql[mt][ks], kh4);
                    mma16816(s[mt][np * 2 + 1], qh[mt][ks], kh4 + 2);
                    mma16816(s[mt][np * 2 + 1], qh[mt][ks], kl4 + 2);
                    mma16816(s[mt][np * 2 + 1], ql[mt][ks], kh4 + 2);
                }
            }

        // ---- EX2 softmax + pack P A-fragments (split) ----
        unsigned ph[2][4][4], pl[2][4][4];
#pragma unroll
        for (int mt = 0; mt < 2; mt++)
#pragma unroll
            for (int kk = 0; kk < 4; kk++) {
                float e[8];
#pragma unroll
                for (int ntl = 0; ntl < 2; ntl++) {
                    int nt = kk * 2 + ntl;
                    float e0 = ex2(s[mt][nt][0]);
                    float e1 = ex2(s[mt][nt][1]);
                    float e2 = ex2(s[mt][nt][2]);
                    float e3 = ex2(s[mt][nt][3]);
                    lacc[mt][0] += e0 + e1;
                    lacc[mt][1] += e2 + e3;
                    e[ntl * 4 + 0] = e0; e[ntl * 4 + 1] = e1;
                    e[ntl * 4 + 2] = e2; e[ntl * 4 + 3] = e3;
                }
                unsigned p0 = pack2bf(e[0], e[1]);
                unsigned p1 = pack2bf(e[2], e[3]);
                unsigned p2 = pack2bf(e[4], e[5]);
                unsigned p3 = pack2bf(e[6], e[7]);
                ph[mt][kk][0] = p0; ph[mt][kk][1] = p1;
                ph[mt][kk][2] = p2; ph[mt][kk][3] = p3;
                pl[mt][kk][0] = pack2bf(e[0] - bflo(p0), e[1] - bfhi(p0));
                pl[mt][kk][1] = pack2bf(e[2] - bflo(p1), e[3] - bfhi(p1));
                pl[mt][kk][2] = pack2bf(e[4] - bflo(p2), e[5] - bfhi(p2));
                pl[mt][kk][3] = pack2bf(e[6] - bflo(p3), e[7] - bfhi(p3));
            }

        // ---- P @ V (3-term split); V frags reused across both M-tiles ----
#pragma unroll
        for (int kk = 0; kk < 4; kk++)
#pragma unroll
            for (int vg = 0; vg < 2; vg++) {
                unsigned vh4[4], vl4[4];
                const char* pv = smb + VH + (kk * 16 + (lane & 15)) * 80 +
                                 (vg * 16 + (lane >> 4) * 8) * 2;
                ldsm4t(vh4, pv);
                ldsm4t(vl4, pv + (VL - VH));
#pragma unroll
                for (int mt = 0; mt < 2; mt++) {
                    mma16816(o[mt][vg * 2], ph[mt][kk], vh4);
                    mma16816(o[mt][vg * 2], ph[mt][kk], vl4);
                    mma16816(o[mt][vg * 2], pl[mt][kk], vh4);
                    mma16816(o[mt][vg * 2 + 1], ph[mt][kk], vh4 + 2);
                    mma16816(o[mt][vg * 2 + 1], ph[mt][kk], vl4 + 2);
                    mma16816(o[mt][vg * 2 + 1], pl[mt][kk], vh4 + 2);
                }
            }
    }

    // ---- row-sum reduce (4 lanes per row) + gated epilogue ----
#pragma unroll
    for (int mt = 0; mt < 2; mt++) {
        float l0 = lacc[mt][0], l1 = lacc[mt][1];
        l0 += __shfl_xor_sync(0xffffffffu, l0, 1);
        l0 += __shfl_xor_sync(0xffffffffu, l0, 2);
        l1 += __shfl_xor_sync(0xffffffffu, l1, 1);
        l1 += __shfl_xor_sync(0xffffffffu, l1, 2);
        float rl0 = 1.f / l0, rl1 = 1.f / l1;
        size_t m0g = (size_t)(r * 256 + i1 + mt * 16);
#pragma unroll
        for (int nt = 0; nt < 4; nt++) {
            int vd0 = nt * 8 + (lane & 3) * 2;
            float2 g0 = *(const float2*)&g_gate[m0g * 128 + h * 32 + vd0];
            float2 g1 = *(const float2*)&g_gate[(m0g + 8) * 128 + h * 32 + vd0];
            uint2 o0, o1;
            o0.x = pack_split(o[mt][nt][0] * rl0 * g0.x);
            o0.y = pack_split(o[mt][nt][1] * rl0 * g0.y);
            o1.x = pack_split(o[mt][nt][2] * rl1 * g1.x);
            o1.y = pack_split(o[mt][nt][3] * rl1 * g1.y);
            *(uint2*)&g_og2[m0g * 128 + h * 32 + vd0] = o0;
            *(uint2*)&g_og2[(m0g + 8) * 128 + h * 32 + vd0] = o1;
        }
    }
}

// ---------------------------------------------------------------------------

extern "C" void kernel_launch(void* const* d_in, const int* in_sizes, int n_in,
                              void* d_out, int out_size) {
    const float* pa  = (const float*)d_in[0];
    const float* pm  = (const float*)d_in[1];
    const float* lns = (const float*)d_in[2];
    const float* lnb = (const float*)d_in[3];
    const float* w2d = (const float*)d_in[4];
    const float* wq  = (const float*)d_in[5];
    const float* wk  = (const float*)d_in[6];
    const float* wv  = (const float*)d_in[7];
    const float* wg  = (const float*)d_in[8];
    const float* bg  = (const float*)d_in[9];
    const float* wo  = (const float*)d_in[10];
    const float* bo  = (const float*)d_in[11];
    float* out = (float*)d_out;

    prep_w_kernel<<<160, 512>>>(wq, wk, wv, wg, wo);
    ln_nb_kernel<<<65536, 128>>>(pa, lns, lnb, w2d);
    mma_gemm_kernel<<<dim3(8, 512), 256>>>(0, bg, nullptr, nullptr);
    attn_mma_kernel<<<dim3(4, 512), 128>>>(pm);
    mma_gemm_kernel<<<dim3(2, 512), 256>>>(1, bo, pm, out);
}

// round 8
// speedup vs baseline: 2.8238x; 1.0381x over previous
#include <cuda_runtime.h>
#include <cuda_bf16.h>

// TriangleAttention: B=1, N=256, D=128, H=4, kd=32
//   0. prep_w      : split wq|wk|wv|wg|wo into bf16 hi/lo planes
//   1. ln_nb       : LayerNorm -> packed split-bf16 x ; nb*log2e -> g_nb[h][i][j]
//   2. mma_gemm(0) : packed-split q|k|v -> g_qkvp, sigmoid gate -> g_gate
//   3. attn_mma    : per (r,h,qhalf) flash attention, fused per-keygroup
//                    QK->EX2->PV pipeline, double-buffered K/V staging
//   4. mma_gemm(1) : out = (og @ wo^T + bo) * mask

#define MTOT 65536
#define L2E 1.4426950408889634f

__device__ unsigned int g_x2[MTOT * 128];      // packed: lo16=hi bf16, hi16=lo bf16
__device__ unsigned int g_og2[MTOT * 128];
__device__ unsigned int g_qkvp[MTOT * 384];    // packed split q|k|v (q pre-scaled)
__device__ float g_gate[MTOT * 128];           // sigmoid(g+bg)
__device__ float g_nb[4 * MTOT];               // [h][i*256+j], log2e folded
__device__ __nv_bfloat16 g_wh[5 * 16384];
__device__ __nv_bfloat16 g_wl[5 * 16384];

__device__ __forceinline__ float ex2(float x) {
    float y; asm("ex2.approx.ftz.f32 %0, %1;" : "=f"(y) : "f"(x)); return y;
}
__device__ __forceinline__ unsigned pack2bf(float lo, float hi) {
    unsigned d; asm("cvt.rn.bf16x2.f32 %0, %1, %2;" : "=r"(d) : "f"(hi), "f"(lo));
    return d;
}
__device__ __forceinline__ float bflo(unsigned u) { return __uint_as_float(u << 16); }
__device__ __forceinline__ float bfhi(unsigned u) { return __uint_as_float(u & 0xffff0000u); }

__device__ __forceinline__ unsigned int pack_split(float v) {
    __nv_bfloat16 h = __float2bfloat16(v);
    float res = v - __bfloat162float(h);
    __nv_bfloat16 l = __float2bfloat16(res);
    return ((unsigned int)__bfloat16_as_ushort(l) << 16) |
           (unsigned int)__bfloat16_as_ushort(h);
}
__device__ __forceinline__ void ldsm4(unsigned int* r, const void* p) {
    unsigned int a = (unsigned int)__cvta_generic_to_shared(p);
    asm volatile("ldmatrix.sync.aligned.m8n8.x4.shared.b16 {%0,%1,%2,%3}, [%4];"
                 : "=r"(r[0]), "=r"(r[1]), "=r"(r[2]), "=r"(r[3]) : "r"(a));
}
__device__ __forceinline__ void ldsm4t(unsigned int* r, const void* p) {
    unsigned int a = (unsigned int)__cvta_generic_to_shared(p);
    asm volatile("ldmatrix.sync.aligned.m8n8.x4.trans.shared.b16 {%0,%1,%2,%3}, [%4];"
                 : "=r"(r[0]), "=r"(r[1]), "=r"(r[2]), "=r"(r[3]) : "r"(a));
}
__device__ __forceinline__ void mma16816(float* c, const unsigned int* a,
                                         const unsigned int* b) {
    asm volatile(
        "mma.sync.aligned.m16n8k16.row.col.f32.bf16.bf16.f32 "
        "{%0,%1,%2,%3}, {%4,%5,%6,%7}, {%8,%9}, {%0,%1,%2,%3};"
        : "+f"(c[0]), "+f"(c[1]), "+f"(c[2]), "+f"(c[3])
        : "r"(a[0]), "r"(a[1]), "r"(a[2]), "r"(a[3]), "r"(b[0]), "r"(b[1]));
}
// unpack packed uint4 (4 vals) -> hi-plane uint2 + lo-plane uint2
__device__ __forceinline__ void unzip4(uint4 u, uint2& hv, uint2& lv) {
    hv.x = (u.x & 0xffffu) | (u.y << 16);
    hv.y = (u.z & 0xffffu) | (u.w << 16);
    lv.x = (u.x >> 16) | (u.y & 0xffff0000u);
    lv.y = (u.z >> 16) | (u.w & 0xffff0000u);
}

// ---------------------------------------------------------------------------
// Kernel 0: weight split
// ---------------------------------------------------------------------------
__global__ __launch_bounds__(512) void prep_w_kernel(
    const float* __restrict__ wq, const float* __restrict__ wk,
    const float* __restrict__ wv, const float* __restrict__ wg,
    const float* __restrict__ wo) {
    int idx = blockIdx.x * 512 + threadIdx.x;
    int which = idx >> 14, off = idx & 16383;
    float w;
    if (which == 0) w = wq[off];
    else if (which == 1) w = wk[off];
    else if (which == 2) w = wv[off];
    else if (which == 3) w = wg[off];
    else w = wo[off];
    __nv_bfloat16 h = __float2bfloat16(w);
    g_wh[idx] = h;
    g_wl[idx] = __float2bfloat16(w - __bfloat162float(h));
}

// ---------------------------------------------------------------------------
// Kernel 1: LayerNorm + nb. One block (128 threads) per pair row m = i*256+j.
// ---------------------------------------------------------------------------
__global__ __launch_bounds__(128) void ln_nb_kernel(
    const float* __restrict__ pa, const float* __restrict__ sc,
    const float* __restrict__ bi, const float* __restrict__ w2d) {
    __shared__ float ws1[4], ws2[4], wnb[16];
    int m = blockIdx.x, d = threadIdx.x;
    int lane = d & 31, wid = d >> 5;

    float v = pa[(size_t)m * 128 + d];
    float s1 = v, s2 = v * v;
#pragma unroll
    for (int o = 16; o > 0; o >>= 1) {
        s1 += __shfl_xor_sync(0xffffffffu, s1, o);
        s2 += __shfl_xor_sync(0xffffffffu, s2, o);
    }
    if (lane == 0) { ws1[wid] = s1; ws2[wid] = s2; }
    __syncthreads();
    float mean = (ws1[0] + ws1[1] + ws1[2] + ws1[3]) * 0.0078125f;
    float ex2m = (ws2[0] + ws2[1] + ws2[2] + ws2[3]) * 0.0078125f;
    float var = ex2m - mean * mean;
    float x = (v - mean) * rsqrtf(var + 1e-5f) * sc[d] + bi[d];
    g_x2[(size_t)m * 128 + d] = pack_split(x);

    float p0 = x * w2d[d];
    float p1 = x * w2d[128 + d];
    float p2 = x * w2d[256 + d];
    float p3 = x * w2d[384 + d];
#pragma unroll
    for (int o = 16; o > 0; o >>= 1) {
        p0 += __shfl_xor_sync(0xffffffffu, p0, o);
        p1 += __shfl_xor_sync(0xffffffffu, p1, o);
        p2 += __shfl_xor_sync(0xffffffffu, p2, o);
        p3 += __shfl_xor_sync(0xffffffffu, p3, o);
    }
    if (lane == 0) {
        wnb[0 + wid] = p0; wnb[4 + wid] = p1;
        wnb[8 + wid] = p2; wnb[12 + wid] = p3;
    }
    __syncthreads();
    if (d < 4) {
        float nb = wnb[d * 4] + wnb[d * 4 + 1] + wnb[d * 4 + 2] + wnb[d * 4 + 3];
        g_nb[d * 65536 + m] = nb * L2E;
    }
}

// ---------------------------------------------------------------------------
// Kernels 2/4: split-bf16 tensor-core GEMM, C = A @ W^T (+ epilogue).
// Block 128(M) x 64(N), k-tile 32, 8 warps 2x4; C = Ah*Wh + Ah*Wl + Al*Wh.
// mode 0: q*scale*log2e|k|v -> packed split g_qkvp ; sigmoid gate -> g_gate
// mode 1: (c + bo) * mask -> out
// ---------------------------------------------------------------------------
__global__ __launch_bounds__(256) void mma_gemm_kernel(
    int mode, const float* __restrict__ bias,
    const float* __restrict__ mask, float* __restrict__ out) {
    __shared__ __align__(16) char smb[30720];
    const int AH = 0, AL = 10240, BH = 20480, BL = 25600;
    int tid = threadIdx.x, lane = tid & 31, wid = tid >> 5;
    int wm = wid & 1, wn = wid >> 1;
    int bx = blockIdx.x, m0 = blockIdx.y * 128;
    const unsigned int* Apk = (mode == 0) ? g_x2 : g_og2;
    int widx = (mode == 0) ? (bx >> 1) : 4;
    int nloc = (mode == 0) ? ((bx & 1) * 64) : bx * 64;
    int woff = widx * 16384;

    float c[4][2][4];
#pragma unroll
    for (int a = 0; a < 4; a++)
#pragma unroll
        for (int b = 0; b < 2; b++)
#pragma unroll
            for (int d = 0; d < 4; d++) c[a][b][d] = 0.f;

    int rowA = ((lane >> 3) & 1) * 8 + (lane & 7);
    int kofA = (lane >> 4) * 8;
    int rowB = (lane & 7) + ((lane >> 4) & 1) * 8;
    int kofB = ((lane >> 3) & 1) * 8;

    for (int kt = 0; kt < 128; kt += 32) {
        __syncthreads();
#pragma unroll
        for (int p = 0; p < 4; p++) {
            int idx = tid + p * 256;
            int r = idx >> 3, g = idx & 7;
            uint4 u = *(const uint4*)&Apk[(size_t)(m0 + r) * 128 + kt + g * 4];
            uint2 hv, lv; unzip4(u, hv, lv);
            *(uint2*)(smb + AH + r * 80 + g * 8) = hv;
            *(uint2*)(smb + AL + r * 80 + g * 8) = lv;
        }
        {
            int r = tid >> 2, g = tid & 3;
            *(uint4*)(smb + BH + r * 80 + g * 16) =
                *(const uint4*)&g_wh[woff + (nloc + r) * 128 + kt + g * 8];
            *(uint4*)(smb + BL + r * 80 + g * 16) =
                *(const uint4*)&g_wl[woff + (nloc + r) * 128 + kt + g * 8];
        }
        __syncthreads();
#pragma unroll
        for (int ks = 0; ks < 2; ks++) {
            unsigned int ah[4][4], al[4][4], bh[4], bl[4];
#pragma unroll
            for (int mt = 0; mt < 4; mt++) {
                const char* pa = smb + AH + (wm * 64 + mt * 16 + rowA) * 80 +
                                 (ks * 16 + kofA) * 2;
                ldsm4(ah[mt], pa);
                ldsm4(al[mt], pa + (AL - AH));
            }
            const char* pb = smb + BH + (wn * 16 + rowB) * 80 +
                             (ks * 16 + kofB) * 2;
            ldsm4(bh, pb);
            ldsm4(bl, pb + (BL - BH));
#pragma unroll
            for (int mt = 0; mt < 4; mt++)
#pragma unroll
                for (int nt = 0; nt < 2; nt++) {
                    mma16816(c[mt][nt], ah[mt], &bh[nt * 2]);
                    mma16816(c[mt][nt], ah[mt], &bl[nt * 2]);
                    mma16816(c[mt][nt], al[mt], &bh[nt * 2]);
                }
        }
    }

    const float qscale = 0.17677669529663687f * L2E;
#pragma unroll
    for (int mt = 0; mt < 4; mt++) {
        int r0 = m0 + wm * 64 + mt * 16 + (lane >> 2);
#pragma unroll
        for (int nt = 0; nt < 2; nt++) {
            int n = bx * 64 + wn * 16 + nt * 8 + (lane & 3) * 2;
            float v0 = c[mt][nt][0], v1 = c[mt][nt][1];
            float v2 = c[mt][nt][2], v3 = c[mt][nt][3];
            if (mode == 0) {
                if (n >= 384) {
                    float b0 = bias[n - 384], b1 = bias[n - 383];
                    v0 = 1.f / (1.f + ex2(-(v0 + b0) * L2E));
                    v1 = 1.f / (1.f + ex2(-(v1 + b1) * L2E));
                    v2 = 1.f / (1.f + ex2(-(v2 + b0) * L2E));
                    v3 = 1.f / (1.f + ex2(-(v3 + b1) * L2E));
                    *(float2*)&g_gate[(size_t)r0 * 128 + n - 384] = make_float2(v0, v1);
                    *(float2*)&g_gate[(size_t)(r0 + 8) * 128 + n - 384] = make_float2(v2, v3);
                } else {
                    if (n < 128) {
                        v0 *= qscale; v1 *= qscale; v2 *= qscale; v3 *= qscale;
                    }
                    uint2 s0, s1;
                    s0.x = pack_split(v0); s0.y = pack_split(v1);
                    s1.x = pack_split(v2); s1.y = pack_split(v3);
                    *(uint2*)&g_qkvp[(size_t)r0 * 384 + n] = s0;
                    *(uint2*)&g_qkvp[(size_t)(r0 + 8) * 384 + n] = s1;
                }
            } else {
                float b0 = bias[n], b1 = bias[n + 1];
                float mk0 = mask[r0], mk1 = mask[r0 + 8];
                *(float2*)&out[(size_t)r0 * 128 + n] =
                    make_float2((v0 + b0) * mk0, (v1 + b1) * mk0);
                *(float2*)&out[(size_t)(r0 + 8) * 128 + n] =
                    make_float2((v2 + b0) * mk1, (v3 + b1) * mk1);
            }
        }
    }
}

// ---------------------------------------------------------------------------
// Kernel 3: tensor-core flash attention. CTA = 128 threads (4 warps),
// 128 query rows; warp w owns rows [w*32, w*32+32) (two 16-row M-tiles).
// grid (4, 512): h = bx, r = by>>1, qhalf = by&1.
// Fused per-16-key-group pipeline: QK MMAs -> EX2 -> pack -> PV MMAs, so
// MUFU/ALU work interleaves with tensor work across warps. K/V staging is
// double-buffered: LDG for tile jt+1 issued at top of iter jt, STS into the
// idle buffer after the first key group's MMAs; ONE syncthreads per tile.
// ---------------------------------------------------------------------------
__global__ __launch_bounds__(128, 3) void attn_mma_kernel(const float* __restrict__ mask) {
    __shared__ __align__(16) char smb[41984];
    // buffer b at b*20480: KH +0, KL +5120, VH +10240, VL +15360 (64 rows x 80B)
    // Q staged once at 0/10240 (overwritten by buffer 0 after frags load)
    float* bsm = (float*)(smb + 40960);                    // 256 floats

    int h = blockIdx.x;
    int r = blockIdx.y >> 1, qc = blockIdx.y & 1;
    int tid = threadIdx.x, lane = tid & 31, w = tid >> 5;
    int q0 = qc * 128;
    size_t rowbase = (size_t)(r * 256) * 384;

    bsm[tid] = (mask[r * 256 + tid] - 1.f) * (32768.f * L2E);
    bsm[tid + 128] = (mask[r * 256 + tid + 128] - 1.f) * (32768.f * L2E);

    // ---- stage this CTA's 128 Q rows (packed -> hi/lo planes) ----
#pragma unroll
    for (int p = 0; p < 8; p++) {
        int idx = tid + p * 128;            // 1024 = 128 rows x 8 groups
        int row = idx >> 3, c4 = idx & 7;
        uint4 u = *(const uint4*)&g_qkvp[rowbase + (size_t)(q0 + row) * 384 +
                                         h * 32 + c4 * 4];
        uint2 hv, lv; unzip4(u, hv, lv);
        *(uint2*)(smb + row * 80 + c4 * 8) = hv;
        *(uint2*)(smb + 10240 + row * 80 + c4 * 8) = lv;
    }
    __syncthreads();

    int rowA = ((lane >> 3) & 1) * 8 + (lane & 7);
    int kofA = (lane >> 4) * 8;
    int rowB = (lane & 7) + ((lane >> 4) & 1) * 8;
    int kofB = ((lane >> 3) & 1) * 8;

    unsigned qh[2][2][4], ql[2][2][4];
#pragma unroll
    for (int mt = 0; mt < 2; mt++)
#pragma unroll
        for (int ks = 0; ks < 2; ks++) {
            const char* pq = smb + (w * 32 + mt * 16 + rowA) * 80 +
                             (ks * 16 + kofA) * 2;
            ldsm4(qh[mt][ks], pq);
            ldsm4(ql[mt][ks], pq + 10240);
        }

    // ---- prefetch tile 0 into registers ----
    uint4 pk[4], pv_[4];
#pragma unroll
    for (int p = 0; p < 4; p++) {
        int idx = tid + p * 128;
        int row = idx >> 3, c4 = idx & 7;
        size_t base = rowbase + (size_t)row * 384 + h * 32 + c4 * 4;
        pk[p] = *(const uint4*)&g_qkvp[base + 128];
        pv_[p] = *(const uint4*)&g_qkvp[base + 256];
    }
    __syncthreads();   // all warps done reading Q region
    // ---- stage tile 0 into buffer 0 ----
#pragma unroll
    for (int p = 0; p < 4; p++) {
        int idx = tid + p * 128;
        int row = idx >> 3, c4 = idx & 7;
        uint2 hv, lv;
        unzip4(pk[p], hv, lv);
        *(uint2*)(smb + row * 80 + c4 * 8) = hv;
        *(uint2*)(smb + 5120 + row * 80 + c4 * 8) = lv;
        unzip4(pv_[p], hv, lv);
        *(uint2*)(smb + 10240 + row * 80 + c4 * 8) = hv;
        *(uint2*)(smb + 15360 + row * 80 + c4 * 8) = lv;
    }

    float o[2][4][4];
#pragma unroll
    for (int mt = 0; mt < 2; mt++)
#pragma unroll
        for (int nt = 0; nt < 4; nt++)
#pragma unroll
            for (int d = 0; d < 4; d++) o[mt][nt][d] = 0.f;
    float lacc[2][2] = {{0.f, 0.f}, {0.f, 0.f}};

    int i1 = q0 + w * 32 + (lane >> 2);                 // mt=0 row; mt=1 is +16
    const float* nbrow = g_nb + h * 65536 + i1 * 256;

    for (int jt = 0; jt < 4; jt++) {
        __syncthreads();   // buf[jt&1] staged & visible; prior compute complete
        const char* B = smb + (jt & 1) * 20480;

        // prefetch next tile (latency hidden behind this tile's compute)
        if (jt < 3) {
#pragma unroll
            for (int p = 0; p < 4; p++) {
                int idx = tid + p * 128;
                int row = idx >> 3, c4 = idx & 7;
                size_t base = rowbase + (size_t)((jt + 1) * 64 + row) * 384 +
                              h * 32 + c4 * 4;
                pk[p] = *(const uint4*)&g_qkvp[base + 128];
                pv_[p] = *(const uint4*)&g_qkvp[base + 256];
            }
        }

#pragma unroll
        for (int np = 0; np < 4; np++) {
            // ---- K fragments for this 16-key group ----
            unsigned kh4[2][4], kl4[2][4];
#pragma unroll
            for (int ks = 0; ks < 2; ks++) {
                const char* pkm = B + (np * 16 + rowB) * 80 + (ks * 16 + kofB) * 2;
                ldsm4(kh4[ks], pkm);
                ldsm4(kl4[ks], pkm + 5120);
            }
            // ---- S init = mask bias + nb ----
            float s[2][2][4];
#pragma unroll
            for (int mt = 0; mt < 2; mt++) {
                const float* nbp = nbrow + mt * 4096 + jt * 64 + np * 16;
#pragma unroll
                for (int ntl = 0; ntl < 2; ntl++) {
                    int j0l = ntl * 8 + (lane & 3) * 2;
                    float2 b2 = *(float2*)&bsm[jt * 64 + np * 16 + j0l];
                    float2 na = *(const float2*)&nbp[j0l];
                    float2 nb2 = *(const float2*)&nbp[2048 + j0l];
                    s[mt][ntl][0] = b2.x + na.x;
                    s[mt][ntl][1] = b2.y + na.y;
                    s[mt][ntl][2] = b2.x + nb2.x;
                    s[mt][ntl][3] = b2.y + nb2.y;
                }
            }
            // ---- QK^T (3-term split) ----
#pragma unroll
            for (int ks = 0; ks < 2; ks++)
#pragma unroll
                for (int mt = 0; mt < 2; mt++) {
                    mma16816(s[mt][0], qh[mt][ks], kh4[ks]);
                    mma16816(s[mt][0], qh[mt][ks], kl4[ks]);
                    mma16816(s[mt][0], ql[mt][ks], kh4[ks]);
                    mma16816(s[mt][1], qh[mt][ks], kh4[ks] + 2);
                    mma16816(s[mt][1], qh[mt][ks], kl4[ks] + 2);
                    mma16816(s[mt][1], ql[mt][ks], kh4[ks] + 2);
                }

            // ---- stage next tile into idle buffer (once per tile) ----
            if (np == 0 && jt < 3) {
                char* NB = smb + ((jt + 1) & 1) * 20480;
#pragma unroll
                for (int p = 0; p < 4; p++) {
                    int idx = tid + p * 128;
                    int row = idx >> 3, c4 = idx & 7;
                    uint2 hv, lv;
                    unzip4(pk[p], hv, lv);
                    *(uint2*)(NB + row * 80 + c4 * 8) = hv;
                    *(uint2*)(NB + 5120 + row * 80 + c4 * 8) = lv;
                    unzip4(pv_[p], hv, lv);
                    *(uint2*)(NB + 10240 + row * 80 + c4 * 8) = hv;
                    *(uint2*)(NB + 15360 + row * 80 + c4 * 8) = lv;
                }
            }

            // ---- EX2 softmax + pack P A-fragments (split) ----
            unsigned ph[2][4], pl[2][4];
#pragma unroll
            for (int mt = 0; mt < 2; mt++) {
                float e[8];
#pragma unroll
                for (int ntl = 0; ntl < 2; ntl++) {
                    float e0 = ex2(s[mt][ntl][0]);
                    float e1 = ex2(s[mt][ntl][1]);
                    float e2 = ex2(s[mt][ntl][2]);
                    float e3 = ex2(s[mt][ntl][3]);
                    lacc[mt][0] += e0 + e1;
                    lacc[mt][1] += e2 + e3;
                    e[ntl * 4 + 0] = e0; e[ntl * 4 + 1] = e1;
                    e[ntl * 4 + 2] = e2; e[ntl * 4 + 3] = e3;
                }
                unsigned p0 = pack2bf(e[0], e[1]);
                unsigned p1 = pack2bf(e[2], e[3]);
                unsigned p2 = pack2bf(e[4], e[5]);
                unsigned p3 = pack2bf(e[6], e[7]);
                ph[mt][0] = p0; ph[mt][1] = p1; ph[mt][2] = p2; ph[mt][3] = p3;
                pl[mt][0] = pack2bf(e[0] - bflo(p0), e[1] - bfhi(p0));
                pl[mt][1] = pack2bf(e[2] - bflo(p1), e[3] - bfhi(p1));
                pl[mt][2] = pack2bf(e[4] - bflo(p2), e[5] - bfhi(p2));
                pl[mt][3] = pack2bf(e[6] - bflo(p3), e[7] - bfhi(p3));
            }

            // ---- P @ V for this key group (V rows np*16..+16) ----
#pragma unroll
            for (int vg = 0; vg < 2; vg++) {
                unsigned vh4[4], vl4[4];
                const char* pvm = B + 10240 + (np * 16 + (lane & 15)) * 80 +
                                  (vg * 16 + (lane >> 4) * 8) * 2;
                ldsm4t(vh4, pvm);
                ldsm4t(vl4, pvm + 5120);
#pragma unroll
                for (int mt = 0; mt < 2; mt++) {
                    mma16816(o[mt][vg * 2], ph[mt], vh4);
                    mma16816(o[mt][vg * 2], ph[mt], vl4);
                    mma16816(o[mt][vg * 2], pl[mt], vh4);
                    mma16816(o[mt][vg * 2 + 1], ph[mt], vh4 + 2);
                    mma16816(o[mt][vg * 2 + 1], ph[mt], vl4 + 2);
                    mma16816(o[mt][vg * 2 + 1], pl[mt], vh4 + 2);
                }
            }
        }
    }

    // ---- row-sum reduce (4 lanes per row) + gated epilogue ----
#pragma unroll
    for (int mt = 0; mt < 2; mt++) {
        float l0 = lacc[mt][0], l1 = lacc[mt][1];
        l0 += __shfl_xor_sync(0xffffffffu, l0, 1);
        l0 += __shfl_xor_sync(0xffffffffu, l0, 2);
        l1 += __shfl_xor_sync(0xffffffffu, l1, 1);
        l1 += __shfl_xor_sync(0xffffffffu, l1, 2);
        float rl0 = 1.f / l0, rl1 = 1.f / l1;
        size_t m0g = (size_t)(r * 256 + i1 + mt * 16);
#pragma unroll
        for (int nt = 0; nt < 4; nt++) {
            int vd0 = nt * 8 + (lane & 3) * 2;
            float2 g0 = *(const float2*)&g_gate[m0g * 128 + h * 32 + vd0];
            float2 g1 = *(const float2*)&g_gate[(m0g + 8) * 128 + h * 32 + vd0];
            uint2 o0, o1;
            o0.x = pack_split(o[mt][nt][0] * rl0 * g0.x);
            o0.y = pack_split(o[mt][nt][1] * rl0 * g0.y);
            o1.x = pack_split(o[mt][nt][2] * rl1 * g1.x);
            o1.y = pack_split(o[mt][nt][3] * rl1 * g1.y);
            *(uint2*)&g_og2[m0g * 128 + h * 32 + vd0] = o0;
            *(uint2*)&g_og2[(m0g + 8) * 128 + h * 32 + vd0] = o1;
        }
    }
}

// ---------------------------------------------------------------------------

extern "C" void kernel_launch(void* const* d_in, const int* in_sizes, int n_in,
                              void* d_out, int out_size) {
    const float* pa  = (const float*)d_in[0];
    const float* pm  = (const float*)d_in[1];
    const float* lns = (const float*)d_in[2];
    const float* lnb = (const float*)d_in[3];
    const float* w2d = (const float*)d_in[4];
    const float* wq  = (const float*)d_in[5];
    const float* wk  = (const float*)d_in[6];
    const float* wv  = (const float*)d_in[7];
    const float* wg  = (const float*)d_in[8];
    const float* bg  = (const float*)d_in[9];
    const float* wo  = (const float*)d_in[10];
    const float* bo  = (const float*)d_in[11];
    float* out = (float*)d_out;

    prep_w_kernel<<<160, 512>>>(wq, wk, wv, wg, wo);
    ln_nb_kernel<<<65536, 128>>>(pa, lns, lnb, w2d);
    mma_gemm_kernel<<<dim3(8, 512), 256>>>(0, bg, nullptr, nullptr);
    attn_mma_kernel<<<dim3(4, 512), 128>>>(pm);
    mma_gemm_kernel<<<dim3(2, 512), 256>>>(1, bo, pm, out);
}

// round 10
// speedup vs baseline: 3.3696x; 1.1933x over previous
#include <cuda_runtime.h>
#include <cuda_bf16.h>

// TriangleAttention: B=1, N=256, D=128, H=4, kd=32
//   0. prep_w      : split wq|wk|wv|wg|wo into bf16 hi/lo planes
//   1. ln_nb       : warp-per-row LayerNorm -> bf16 hi/lo planes; nb*log2e
//   2. mma_gemm(0) : q|k|v hi/lo planes -> g_kvh/g_kvl, sigmoid gate -> g_gate
//   3. attn_mma    : flash attention, cp.async-staged K/V double buffer
//   4. mma_gemm(1) : out = (og @ wo^T + bo) * mask
// All split operands stored as SEPARATE hi/lo bf16 planes in gmem so every
// smem staging step is a pure cp.async.cg (no registers, no unzip ALU).

#define MTOT 65536
#define L2E 1.4426950408889634f

__device__ __align__(16) __nv_bfloat16 g_xh[MTOT * 128], g_xl[MTOT * 128];
__device__ __align__(16) __nv_bfloat16 g_kvh[MTOT * 384], g_kvl[MTOT * 384];
__device__ __align__(16) __nv_bfloat16 g_ogh[MTOT * 128], g_ogl[MTOT * 128];
__device__ __align__(16) float g_gate[MTOT * 128];   // sigmoid(g+bg)
__device__ __align__(16) float g_nb[4 * MTOT];       // [h][i*256+j], log2e folded
__device__ __align__(16) __nv_bfloat16 g_wh[5 * 16384];
__device__ __align__(16) __nv_bfloat16 g_wl[5 * 16384];

__device__ __forceinline__ float ex2(float x) {
    float y; asm("ex2.approx.ftz.f32 %0, %1;" : "=f"(y) : "f"(x)); return y;
}
__device__ __forceinline__ unsigned pack2bf(float lo, float hi) {
    unsigned d; asm("cvt.rn.bf16x2.f32 %0, %1, %2;" : "=r"(d) : "f"(hi), "f"(lo));
    return d;
}
__device__ __forceinline__ float bflo(unsigned u) { return __uint_as_float(u << 16); }
__device__ __forceinline__ float bfhi(unsigned u) { return __uint_as_float(u & 0xffff0000u); }

__device__ __forceinline__ void cpa16(void* dst, const void* src) {
    unsigned d = (unsigned)__cvta_generic_to_shared(dst);
    asm volatile("cp.async.cg.shared.global [%0], [%1], 16;" :: "r"(d), "l"(src));
}
__device__ __forceinline__ void cpa_commit() {
    asm volatile("cp.async.commit_group;");
}
template <int N> __device__ __forceinline__ void cpa_wait() {
    asm volatile("cp.async.wait_group %0;" :: "n"(N));
}

__device__ __forceinline__ void ldsm4(unsigned int* r, const void* p) {
    unsigned int a = (unsigned int)__cvta_generic_to_shared(p);
    asm volatile("ldmatrix.sync.aligned.m8n8.x4.shared.b16 {%0,%1,%2,%3}, [%4];"
                 : "=r"(r[0]), "=r"(r[1]), "=r"(r[2]), "=r"(r[3]) : "r"(a));
}
__device__ __forceinline__ void ldsm4t(unsigned int* r, const void* p) {
    unsigned int a = (unsigned int)__cvta_generic_to_shared(p);
    asm volatile("ldmatrix.sync.aligned.m8n8.x4.trans.shared.b16 {%0,%1,%2,%3}, [%4];"
                 : "=r"(r[0]), "=r"(r[1]), "=r"(r[2]), "=r"(r[3]) : "r"(a));
}
__device__ __forceinline__ void mma16816(float* c, const unsigned int* a,
                                         const unsigned int* b) {
    asm volatile(
        "mma.sync.aligned.m16n8k16.row.col.f32.bf16.bf16.f32 "
        "{%0,%1,%2,%3}, {%4,%5,%6,%7}, {%8,%9}, {%0,%1,%2,%3};"
        : "+f"(c[0]), "+f"(c[1]), "+f"(c[2]), "+f"(c[3])
        : "r"(a[0]), "r"(a[1]), "r"(a[2]), "r"(a[3]), "r"(b[0]), "r"(b[1]));
}

// ---------------------------------------------------------------------------
// Kernel 0: weight split
// ---------------------------------------------------------------------------
__global__ __launch_bounds__(512) void prep_w_kernel(
    const float* __restrict__ wq, const float* __restrict__ wk,
    const float* __restrict__ wv, const float* __restrict__ wg,
    const float* __restrict__ wo) {
    int idx = blockIdx.x * 512 + threadIdx.x;
    int which = idx >> 14, off = idx & 16383;
    float w;
    if (which == 0) w = wq[off];
    else if (which == 1) w = wk[off];
    else if (which == 2) w = wv[off];
    else if (which == 3) w = wg[off];
    else w = wo[off];
    __nv_bfloat16 h = __float2bfloat16(w);
    g_wh[idx] = h;
    g_wl[idx] = __float2bfloat16(w - __bfloat162float(h));
}

// ---------------------------------------------------------------------------
// Kernel 1: warp-per-row LayerNorm + nb. 256 threads = 8 rows; shuffle-only.
// ---------------------------------------------------------------------------
__global__ __launch_bounds__(256) void ln_nb_kernel(
    const float* __restrict__ pa, const float* __restrict__ sc,
    const float* __restrict__ bi, const float* __restrict__ w2d) {
    int lane = threadIdx.x & 31, wid = threadIdx.x >> 5;
    int m = blockIdx.x * 8 + wid;

    float4 v = *(const float4*)&pa[(size_t)m * 128 + lane * 4];
    float s1 = v.x + v.y + v.z + v.w;
    float s2 = v.x * v.x + v.y * v.y + v.z * v.z + v.w * v.w;
#pragma unroll
    for (int o = 16; o; o >>= 1) {
        s1 += __shfl_xor_sync(0xffffffffu, s1, o);
        s2 += __shfl_xor_sync(0xffffffffu, s2, o);
    }
    float mean = s1 * 0.0078125f;
    float var = s2 * 0.0078125f - mean * mean;
    float rs = rsqrtf(var + 1e-5f);
    float4 scv = *(const float4*)&sc[lane * 4];
    float4 biv = *(const float4*)&bi[lane * 4];
    float x0 = (v.x - mean) * rs * scv.x + biv.x;
    float x1 = (v.y - mean) * rs * scv.y + biv.y;
    float x2 = (v.z - mean) * rs * scv.z + biv.z;
    float x3 = (v.w - mean) * rs * scv.w + biv.w;

    unsigned h01 = pack2bf(x0, x1), h23 = pack2bf(x2, x3);
    unsigned l01 = pack2bf(x0 - bflo(h01), x1 - bfhi(h01));
    unsigned l23 = pack2bf(x2 - bflo(h23), x3 - bfhi(h23));
    *(uint2*)&g_xh[(size_t)m * 128 + lane * 4] = make_uint2(h01, h23);
    *(uint2*)&g_xl[(size_t)m * 128 + lane * 4] = make_uint2(l01, l23);

    float p[4];
#pragma unroll
    for (int hh = 0; hh < 4; hh++) {
        float4 wv4 = *(const float4*)&w2d[hh * 128 + lane * 4];
        float t = x0 * wv4.x + x1 * wv4.y + x2 * wv4.z + x3 * wv4.w;
#pragma unroll
        for (int o = 16; o; o >>= 1) t += __shfl_xor_sync(0xffffffffu, t, o);
        p[hh] = t;
    }
    if (lane < 4) {
        float sel = (lane == 0) ? p[0] : (lane == 1) ? p[1] : (lane == 2) ? p[2] : p[3];
        g_nb[lane * 65536 + m] = sel * L2E;
    }
}

// ---------------------------------------------------------------------------
// Kernels 2/4: split-bf16 tensor-core GEMM, C = A @ W^T (+ epilogue).
// Block 128(M) x 64(N), k-tile 32, 8 warps 2x4; C = Ah*Wh + Ah*Wl + Al*Wh.
// All staging via cp.async.cg from the hi/lo plane arrays.
// ---------------------------------------------------------------------------
__global__ __launch_bounds__(256) void mma_gemm_kernel(
    int mode, const float* __restrict__ bias,
    const float* __restrict__ mask, float* __restrict__ out) {
    __shared__ __align__(16) char smb[30720];
    const int AH = 0, AL = 10240, BH = 20480, BL = 25600;
    int tid = threadIdx.x, lane = tid & 31, wid = tid >> 5;
    int wm = wid & 1, wn = wid >> 1;
    int bx = blockIdx.x, m0 = blockIdx.y * 128;
    const __nv_bfloat16* Ah = (mode == 0) ? g_xh : g_ogh;
    const __nv_bfloat16* Al = (mode == 0) ? g_xl : g_ogl;
    int widx = (mode == 0) ? (bx >> 1) : 4;
    int nloc = (mode == 0) ? ((bx & 1) * 64) : bx * 64;
    int woff = widx * 16384;

    float c[4][2][4];
#pragma unroll
    for (int a = 0; a < 4; a++)
#pragma unroll
        for (int b = 0; b < 2; b++)
#pragma unroll
            for (int d = 0; d < 4; d++) c[a][b][d] = 0.f;

    int rowA = ((lane >> 3) & 1) * 8 + (lane & 7);
    int kofA = (lane >> 4) * 8;
    int rowB = (lane & 7) + ((lane >> 4) & 1) * 8;
    int kofB = ((lane >> 3) & 1) * 8;

    for (int kt = 0; kt < 128; kt += 32) {
        __syncthreads();
        // A: 128 rows x 64B per plane = 512 chunks/plane
#pragma unroll
        for (int p = 0; p < 2; p++) {
            int cix = tid + p * 256;
            int row = cix >> 2, g = cix & 3;
            size_t src = (size_t)(m0 + row) * 128 + kt + g * 8;
            cpa16(smb + AH + row * 80 + g * 16, Ah + src);
            cpa16(smb + AL + row * 80 + g * 16, Al + src);
        }
        // B: 64 rows x 64B per plane = 256 chunks/plane
        {
            int row = tid >> 2, g = tid & 3;
            size_t src = (size_t)woff + (nloc + row) * 128 + kt + g * 8;
            cpa16(smb + BH + row * 80 + g * 16, g_wh + src);
            cpa16(smb + BL + row * 80 + g * 16, g_wl + src);
        }
        cpa_commit();
        cpa_wait<0>();
        __syncthreads();
#pragma unroll
        for (int ks = 0; ks < 2; ks++) {
            unsigned int ah[4][4], al[4][4], bh[4], bl[4];
#pragma unroll
            for (int mt = 0; mt < 4; mt++) {
                const char* pa = smb + AH + (wm * 64 + mt * 16 + rowA) * 80 +
                                 (ks * 16 + kofA) * 2;
                ldsm4(ah[mt], pa);
                ldsm4(al[mt], pa + (AL - AH));
            }
            const char* pb = smb + BH + (wn * 16 + rowB) * 80 +
                             (ks * 16 + kofB) * 2;
            ldsm4(bh, pb);
            ldsm4(bl, pb + (BL - BH));
#pragma unroll
            for (int mt = 0; mt < 4; mt++)
#pragma unroll
                for (int nt = 0; nt < 2; nt++) {
                    mma16816(c[mt][nt], ah[mt], &bh[nt * 2]);
                    mma16816(c[mt][nt], ah[mt], &bl[nt * 2]);
                    mma16816(c[mt][nt], al[mt], &bh[nt * 2]);
                }
        }
    }

    const float qscale = 0.17677669529663687f * L2E;
#pragma unroll
    for (int mt = 0; mt < 4; mt++) {
        int r0 = m0 + wm * 64 + mt * 16 + (lane >> 2);
#pragma unroll
        for (int nt = 0; nt < 2; nt++) {
            int n = bx * 64 + wn * 16 + nt * 8 + (lane & 3) * 2;
            float v0 = c[mt][nt][0], v1 = c[mt][nt][1];
            float v2 = c[mt][nt][2], v3 = c[mt][nt][3];
            if (mode == 0) {
                if (n >= 384) {
                    float b0 = bias[n - 384], b1 = bias[n - 383];
                    v0 = 1.f / (1.f + ex2(-(v0 + b0) * L2E));
                    v1 = 1.f / (1.f + ex2(-(v1 + b1) * L2E));
                    v2 = 1.f / (1.f + ex2(-(v2 + b0) * L2E));
                    v3 = 1.f / (1.f + ex2(-(v3 + b1) * L2E));
                    *(float2*)&g_gate[(size_t)r0 * 128 + n - 384] = make_float2(v0, v1);
                    *(float2*)&g_gate[(size_t)(r0 + 8) * 128 + n - 384] = make_float2(v2, v3);
                } else {
                    if (n < 128) {
                        v0 *= qscale; v1 *= qscale; v2 *= qscale; v3 *= qscale;
                    }
                    unsigned h0 = pack2bf(v0, v1), h1 = pack2bf(v2, v3);
                    unsigned l0 = pack2bf(v0 - bflo(h0), v1 - bfhi(h0));
                    unsigned l1 = pack2bf(v2 - bflo(h1), v3 - bfhi(h1));
                    *(unsigned*)&g_kvh[(size_t)r0 * 384 + n] = h0;
                    *(unsigned*)&g_kvl[(size_t)r0 * 384 + n] = l0;
                    *(unsigned*)&g_kvh[(size_t)(r0 + 8) * 384 + n] = h1;
                    *(unsigned*)&g_kvl[(size_t)(r0 + 8) * 384 + n] = l1;
                }
            } else {
                float b0 = bias[n], b1 = bias[n + 1];
                float mk0 = mask[r0], mk1 = mask[r0 + 8];
                *(float2*)&out[(size_t)r0 * 128 + n] =
                    make_float2((v0 + b0) * mk0, (v1 + b1) * mk0);
                *(float2*)&out[(size_t)(r0 + 8) * 128 + n] =
                    make_float2((v2 + b0) * mk1, (v3 + b1) * mk1);
            }
        }
    }
}

// ---------------------------------------------------------------------------
// Kernel 3: tensor-core flash attention. CTA = 128 threads (4 warps),
// 128 query rows; warp w owns rows [w*32, w*32+32) (two 16-row M-tiles).
// grid (4, 512): h = bx, r = by>>1, qhalf = by&1.
// K/V staged by cp.async.cg into a double buffer (tile jt lives in
// buf[(jt+1)&1]); Q overlays buffer 0 during the prologue. Fused
// per-16-key-group QK -> EX2 -> pack -> PV pipeline.
// ---------------------------------------------------------------------------
__global__ __launch_bounds__(128, 4) void attn_mma_kernel(const float* __restrict__ mask) {
    __shared__ __align__(16) char smb[41984];
    // buffer b at b*20480: KH +0, KL +5120, VH +10240, VL +15360 (64 x 80B)
    float* bsm = (float*)(smb + 40960);

    int h = blockIdx.x;
    int r = blockIdx.y >> 1, qc = blockIdx.y & 1;
    int tid = threadIdx.x, lane = tid & 31, w = tid >> 5;
    int q0 = qc * 128;
    size_t rowbase = (size_t)(r * 256) * 384;

    bsm[tid] = (mask[r * 256 + tid] - 1.f) * (32768.f * L2E);
    bsm[tid + 128] = (mask[r * 256 + tid + 128] - 1.f) * (32768.f * L2E);

    // ---- prologue: Q -> buf0 (overlay), tile0 -> buf1 ----
#pragma unroll
    for (int p = 0; p < 4; p++) {
        int cix = tid + p * 128;            // 512 chunks/plane
        int row = cix >> 2, g = cix & 3;
        size_t src = rowbase + (size_t)(q0 + row) * 384 + h * 32 + g * 8;
        cpa16(smb + row * 80 + g * 16, g_kvh + src);
        cpa16(smb + 10240 + row * 80 + g * 16, g_kvl + src);
    }
    cpa_commit();
#pragma unroll
    for (int p = 0; p < 8; p++) {
        int cix = tid + p * 128;            // 1024 chunks: 4 planes x 256
        int pl = cix >> 8, rg = cix & 255;
        int row = rg >> 2, g = rg & 3;
        size_t src = rowbase + (size_t)row * 384 + ((pl >> 1) ? 256 : 128) +
                     h * 32 + g * 8;
        const __nv_bfloat16* sp = (pl & 1) ? g_kvl : g_kvh;
        cpa16(smb + 20480 + pl * 5120 + row * 80 + g * 16, sp + src);
    }
    cpa_commit();
    cpa_wait<1>();      // Q done (tile0 may be in flight)
    __syncthreads();

    int rowA = ((lane >> 3) & 1) * 8 + (lane & 7);
    int kofA = (lane >> 4) * 8;
    int rowB = (lane & 7) + ((lane >> 4) & 1) * 8;
    int kofB = ((lane >> 3) & 1) * 8;

    unsigned qh[2][2][4], ql[2][2][4];
#pragma unroll
    for (int mt = 0; mt < 2; mt++)
#pragma unroll
        for (int ks = 0; ks < 2; ks++) {
            const char* pq = smb + (w * 32 + mt * 16 + rowA) * 80 +
                             (ks * 16 + kofA) * 2;
            ldsm4(qh[mt][ks], pq);
            ldsm4(ql[mt][ks], pq + 10240);
        }
    __syncthreads();    // all warps done with Q region (buf0)

    float o[2][4][4];
#pragma unroll
    for (int mt = 0; mt < 2; mt++)
#pragma unroll
        for (int nt = 0; nt < 4; nt++)
#pragma unroll
            for (int d = 0; d < 4; d++) o[mt][nt][d] = 0.f;
    float lacc[2][2] = {{0.f, 0.f}, {0.f, 0.f}};

    int i1 = q0 + w * 32 + (lane >> 2);                 // mt=0 row; mt=1 is +16
    const float* nbrow = g_nb + h * 65536 + i1 * 256;

    for (int jt = 0; jt < 4; jt++) {
        if (jt < 3) {
            char* NB = smb + (jt & 1) * 20480;
#pragma unroll
            for (int p = 0; p < 8; p++) {
                int cix = tid + p * 128;
                int pl = cix >> 8, rg = cix & 255;
                int row = rg >> 2, g = rg & 3;
                size_t src = rowbase + (size_t)((jt + 1) * 64 + row) * 384 +
                             ((pl >> 1) ? 256 : 128) + h * 32 + g * 8;
                const __nv_bfloat16* sp = (pl & 1) ? g_kvl : g_kvh;
                cpa16(NB + pl * 5120 + row * 80 + g * 16, sp + src);
            }
            cpa_commit();
            cpa_wait<1>();
        } else {
            cpa_wait<0>();
        }
        __syncthreads();
        const char* B = smb + ((jt + 1) & 1) * 20480;   // tile jt's buffer

#pragma unroll
        for (int np = 0; np < 4; np++) {
            // ---- K fragments for this 16-key group ----
            unsigned kh4[2][4], kl4[2][4];
#pragma unroll
            for (int ks = 0; ks < 2; ks++) {
                const char* pkm = B + (np * 16 + rowB) * 80 + (ks * 16 + kofB) * 2;
                ldsm4(kh4[ks], pkm);
                ldsm4(kl4[ks], pkm + 5120);
            }
            // ---- S init = mask bias + nb ----
            float s[2][2][4];
#pragma unroll
            for (int mt = 0; mt < 2; mt++) {
                const float* nbp = nbrow + mt * 4096 + jt * 64 + np * 16;
#pragma unroll
                for (int ntl = 0; ntl < 2; ntl++) {
                    int j0l = ntl * 8 + (lane & 3) * 2;
                    float2 b2 = *(float2*)&bsm[jt * 64 + np * 16 + j0l];
                    float2 na = *(const float2*)&nbp[j0l];
                    float2 nb2 = *(const float2*)&nbp[2048 + j0l];
                    s[mt][ntl][0] = b2.x + na.x;
                    s[mt][ntl][1] = b2.y + na.y;
                    s[mt][ntl][2] = b2.x + nb2.x;
                    s[mt][ntl][3] = b2.y + nb2.y;
                }
            }
            // ---- QK^T (3-term split) ----
#pragma unroll
            for (int ks = 0; ks < 2; ks++)
#pragma unroll
                for (int mt = 0; mt < 2; mt++) {
                    mma16816(s[mt][0], qh[mt][ks], kh4[ks]);
                    mma16816(s[mt][0], qh[mt][ks], kl4[ks]);
                    mma16816(s[mt][0], ql[mt][ks], kh4[ks]);
                    mma16816(s[mt][1], qh[mt][ks], kh4[ks] + 2);
                    mma16816(s[mt][1], qh[mt][ks], kl4[ks] + 2);
                    mma16816(s[mt][1], ql[mt][ks], kh4[ks] + 2);
                }

            // ---- EX2 softmax + pack P A-fragments (split) ----
            unsigned ph[2][4], pl2[2][4];
#pragma unroll
            for (int mt = 0; mt < 2; mt++) {
                float e[8];
#pragma unroll
                for (int ntl = 0; ntl < 2; ntl++) {
                    float e0 = ex2(s[mt][ntl][0]);
                    float e1 = ex2(s[mt][ntl][1]);
                    float e2 = ex2(s[mt][ntl][2]);
                    float e3 = ex2(s[mt][ntl][3]);
                    lacc[mt][0] += e0 + e1;
                    lacc[mt][1] += e2 + e3;
                    e[ntl * 4 + 0] = e0; e[ntl * 4 + 1] = e1;
                    e[ntl * 4 + 2] = e2; e[ntl * 4 + 3] = e3;
                }
                unsigned p0 = pack2bf(e[0], e[1]);
                unsigned p1 = pack2bf(e[2], e[3]);
                unsigned p2 = pack2bf(e[4], e[5]);
                unsigned p3 = pack2bf(e[6], e[7]);
                ph[mt][0] = p0; ph[mt][1] = p1; ph[mt][2] = p2; ph[mt][3] = p3;
                pl2[mt][0] = pack2bf(e[0] - bflo(p0), e[1] - bfhi(p0));
                pl2[mt][1] = pack2bf(e[2] - bflo(p1), e[3] - bfhi(p1));
                pl2[mt][2] = pack2bf(e[4] - bflo(p2), e[5] - bfhi(p2));
                pl2[mt][3] = pack2bf(e[6] - bflo(p3), e[7] - bfhi(p3));
            }

            // ---- P @ V for this key group (3-term split) ----
#pragma unroll
            for (int vg = 0; vg < 2; vg++) {
                unsigned vh4[4], vl4[4];
                const char* pvm = B + 10240 + (np * 16 + (lane & 15)) * 80 +
                                  (vg * 16 + (lane >> 4) * 8) * 2;
                ldsm4t(vh4, pvm);
                ldsm4t(vl4, pvm + 5120);
#pragma unroll
                for (int mt = 0; mt < 2; mt++) {
                    mma16816(o[mt][vg * 2], ph[mt], vh4);
                    mma16816(o[mt][vg * 2], ph[mt], vl4);
                    mma16816(o[mt][vg * 2], pl2[mt], vh4);
                    mma16816(o[mt][vg * 2 + 1], ph[mt], vh4 + 2);
                    mma16816(o[mt][vg * 2 + 1], ph[mt], vl4 + 2);
                    mma16816(o[mt][vg * 2 + 1], pl2[mt], vh4 + 2);
                }
            }
        }
        __syncthreads();   // all warps done with this buffer before next issue
    }

    // ---- row-sum reduce (4 lanes per row) + gated epilogue ----
#pragma unroll
    for (int mt = 0; mt < 2; mt++) {
        float l0 = lacc[mt][0], l1 = lacc[mt][1];
        l0 += __shfl_xor_sync(0xffffffffu, l0, 1);
        l0 += __shfl_xor_sync(0xffffffffu, l0, 2);
        l1 += __shfl_xor_sync(0xffffffffu, l1, 1);
        l1 += __shfl_xor_sync(0xffffffffu, l1, 2);
        float rl0 = 1.f / l0, rl1 = 1.f / l1;
        size_t m0g = (size_t)(r * 256 + i1 + mt * 16);
#pragma unroll
        for (int nt = 0; nt < 4; nt++) {
            int vd0 = nt * 8 + (lane & 3) * 2;
            float2 g0 = *(const float2*)&g_gate[m0g * 128 + h * 32 + vd0];
            float2 g1 = *(const float2*)&g_gate[(m0g + 8) * 128 + h * 32 + vd0];
            float a0 = o[mt][nt][0] * rl0 * g0.x, a1 = o[mt][nt][1] * rl0 * g0.y;
            float a2 = o[mt][nt][2] * rl1 * g1.x, a3 = o[mt][nt][3] * rl1 * g1.y;
            unsigned h0 = pack2bf(a0, a1), h1 = pack2bf(a2, a3);
            unsigned l0p = pack2bf(a0 - bflo(h0), a1 - bfhi(h0));
            unsigned l1p = pack2bf(a2 - bflo(h1), a3 - bfhi(h1));
            *(unsigned*)&g_ogh[m0g * 128 + h * 32 + vd0] = h0;
            *(unsigned*)&g_ogl[m0g * 128 + h * 32 + vd0] = l0p;
            *(unsigned*)&g_ogh[(m0g + 8) * 128 + h * 32 + vd0] = h1;
            *(unsigned*)&g_ogl[(m0g + 8) * 128 + h * 32 + vd0] = l1p;
        }
    }
}

// ---------------------------------------------------------------------------

extern "C" void kernel_launch(void* const* d_in, const int* in_sizes, int n_in,
                              void* d_out, int out_size) {
    const float* pa  = (const float*)d_in[0];
    const float* pm  = (const float*)d_in[1];
    const float* lns = (const float*)d_in[2];
    const float* lnb = (const float*)d_in[3];
    const float* w2d = (const float*)d_in[4];
    const float* wq  = (const float*)d_in[5];
    const float* wk  = (const float*)d_in[6];
    const float* wv  = (const float*)d_in[7];
    const float* wg  = (const float*)d_in[8];
    const float* bg  = (const float*)d_in[9];
    const float* wo  = (const float*)d_in[10];
    const float* bo  = (const float*)d_in[11];
    float* out = (float*)d_out;

    prep_w_kernel<<<160, 512>>>(wq, wk, wv, wg, wo);
    ln_nb_kernel<<<8192, 256>>>(pa, lns, lnb, w2d);
    mma_gemm_kernel<<<dim3(8, 512), 256>>>(0, bg, nullptr, nullptr);
    attn_mma_kernel<<<dim3(4, 512), 128>>>(pm);
    mma_gemm_kernel<<<dim3(2, 512), 256>>>(1, bo, pm, out);
}

// round 12
// speedup vs baseline: 3.4326x; 1.0187x over previous
#include <cuda_runtime.h>
#include <cuda_bf16.h>
#include <cuda_fp16.h>

// TriangleAttention: B=1, N=256, D=128, H=4, kd=32
//   0. prep_w      : split wq|wk|wv|wg|wo into bf16 hi/lo planes
//   1. ln_nb       : warp-per-row LayerNorm -> bf16 hi/lo planes; nb*log2e
//   2. mma_gemm(0) : q|k|v hi/lo planes -> g_kvh/g_kvl, fp16 gate -> g_gate
//   3. attn_mma    : flash attention, cp.async-staged K/V double buffer
//   4. mma_gemm(1) : out = (og @ wo^T + bo) * mask
// Split operands stored as SEPARATE hi/lo bf16 planes; all smem staging is
// cp.async.cg. GEMM k-loop is double-buffered (latency hidden).

#define MTOT 65536
#define L2E 1.4426950408889634f

__device__ __align__(16) __nv_bfloat16 g_xh[MTOT * 128], g_xl[MTOT * 128];
__device__ __align__(16) __nv_bfloat16 g_kvh[MTOT * 384], g_kvl[MTOT * 384];
__device__ __align__(16) __nv_bfloat16 g_ogh[MTOT * 128], g_ogl[MTOT * 128];
__device__ __align__(16) __half g_gate[MTOT * 128];  // sigmoid(g+bg), fp16
__device__ __align__(16) float g_nb[4 * MTOT];       // [h][i*256+j], log2e folded
__device__ __align__(16) __nv_bfloat16 g_wh[5 * 16384];
__device__ __align__(16) __nv_bfloat16 g_wl[5 * 16384];

__device__ __forceinline__ float ex2(float x) {
    float y; asm("ex2.approx.ftz.f32 %0, %1;" : "=f"(y) : "f"(x)); return y;
}
__device__ __forceinline__ unsigned pack2bf(float lo, float hi) {
    unsigned d; asm("cvt.rn.bf16x2.f32 %0, %1, %2;" : "=r"(d) : "f"(hi), "f"(lo));
    return d;
}
__device__ __forceinline__ float bflo(unsigned u) { return __uint_as_float(u << 16); }
__device__ __forceinline__ float bfhi(unsigned u) { return __uint_as_float(u & 0xffff0000u); }

__device__ __forceinline__ void cpa16(void* dst, const void* src) {
    unsigned d = (unsigned)__cvta_generic_to_shared(dst);
    asm volatile("cp.async.cg.shared.global [%0], [%1], 16;" :: "r"(d), "l"(src));
}
__device__ __forceinline__ void cpa_commit() {
    asm volatile("cp.async.commit_group;");
}
template <int N> __device__ __forceinline__ void cpa_wait() {
    asm volatile("cp.async.wait_group %0;" :: "n"(N));
}

__device__ __forceinline__ void ldsm4(unsigned int* r, const void* p) {
    unsigned int a = (unsigned int)__cvta_generic_to_shared(p);
    asm volatile("ldmatrix.sync.aligned.m8n8.x4.shared.b16 {%0,%1,%2,%3}, [%4];"
                 : "=r"(r[0]), "=r"(r[1]), "=r"(r[2]), "=r"(r[3]) : "r"(a));
}
__device__ __forceinline__ void ldsm4t(unsigned int* r, const void* p) {
    unsigned int a = (unsigned int)__cvta_generic_to_shared(p);
    asm volatile("ldmatrix.sync.aligned.m8n8.x4.trans.shared.b16 {%0,%1,%2,%3}, [%4];"
                 : "=r"(r[0]), "=r"(r[1]), "=r"(r[2]), "=r"(r[3]) : "r"(a));
}
__device__ __forceinline__ void mma16816(float* c, const unsigned int* a,
                                         const unsigned int* b) {
    asm volatile(
        "mma.sync.aligned.m16n8k16.row.col.f32.bf16.bf16.f32 "
        "{%0,%1,%2,%3}, {%4,%5,%6,%7}, {%8,%9}, {%0,%1,%2,%3};"
        : "+f"(c[0]), "+f"(c[1]), "+f"(c[2]), "+f"(c[3])
        : "r"(a[0]), "r"(a[1]), "r"(a[2]), "r"(a[3]), "r"(b[0]), "r"(b[1]));
}

// ---------------------------------------------------------------------------
// Kernel 0: weight split
// ---------------------------------------------------------------------------
__global__ __launch_bounds__(512) void prep_w_kernel(
    const float* __restrict__ wq, const float* __restrict__ wk,
    const float* __restrict__ wv, const float* __restrict__ wg,
    const float* __restrict__ wo) {
    int idx = blockIdx.x * 512 + threadIdx.x;
    int which = idx >> 14, off = idx & 16383;
    float w;
    if (which == 0) w = wq[off];
    else if (which == 1) w = wk[off];
    else if (which == 2) w = wv[off];
    else if (which == 3) w = wg[off];
    else w = wo[off];
    __nv_bfloat16 h = __float2bfloat16(w);
    g_wh[idx] = h;
    g_wl[idx] = __float2bfloat16(w - __bfloat162float(h));
}

// ---------------------------------------------------------------------------
// Kernel 1: warp-per-row LayerNorm + nb. 256 threads = 8 rows; shuffle-only.
// ---------------------------------------------------------------------------
__global__ __launch_bounds__(256) void ln_nb_kernel(
    const float* __restrict__ pa, const float* __restrict__ sc,
    const float* __restrict__ bi, const float* __restrict__ w2d) {
    int lane = threadIdx.x & 31, wid = threadIdx.x >> 5;
    int m = blockIdx.x * 8 + wid;

    float4 v = *(const float4*)&pa[(size_t)m * 128 + lane * 4];
    float s1 = v.x + v.y + v.z + v.w;
    float s2 = v.x * v.x + v.y * v.y + v.z * v.z + v.w * v.w;
#pragma unroll
    for (int o = 16; o; o >>= 1) {
        s1 += __shfl_xor_sync(0xffffffffu, s1, o);
        s2 += __shfl_xor_sync(0xffffffffu, s2, o);
    }
    float mean = s1 * 0.0078125f;
    float var = s2 * 0.0078125f - mean * mean;
    float rs = rsqrtf(var + 1e-5f);
    float4 scv = *(const float4*)&sc[lane * 4];
    float4 biv = *(const float4*)&bi[lane * 4];
    float x0 = (v.x - mean) * rs * scv.x + biv.x;
    float x1 = (v.y - mean) * rs * scv.y + biv.y;
    float x2 = (v.z - mean) * rs * scv.z + biv.z;
    float x3 = (v.w - mean) * rs * scv.w + biv.w;

    unsigned h01 = pack2bf(x0, x1), h23 = pack2bf(x2, x3);
    unsigned l01 = pack2bf(x0 - bflo(h01), x1 - bfhi(h01));
    unsigned l23 = pack2bf(x2 - bflo(h23), x3 - bfhi(h23));
    *(uint2*)&g_xh[(size_t)m * 128 + lane * 4] = make_uint2(h01, h23);
    *(uint2*)&g_xl[(size_t)m * 128 + lane * 4] = make_uint2(l01, l23);

    float p[4];
#pragma unroll
    for (int hh = 0; hh < 4; hh++) {
        float4 wv4 = *(const float4*)&w2d[hh * 128 + lane * 4];
        float t = x0 * wv4.x + x1 * wv4.y + x2 * wv4.z + x3 * wv4.w;
#pragma unroll
        for (int o = 16; o; o >>= 1) t += __shfl_xor_sync(0xffffffffu, t, o);
        p[hh] = t;
    }
    if (lane < 4) {
        float sel = (lane == 0) ? p[0] : (lane == 1) ? p[1] : (lane == 2) ? p[2] : p[3];
        g_nb[lane * 65536 + m] = sel * L2E;
    }
}

// ---------------------------------------------------------------------------
// Kernels 2/4: split-bf16 tensor-core GEMM, C = A @ W^T (+ epilogue).
// Block 128(M) x 64(N), k-tile 32, 8 warps 2x4; C = Ah*Wh + Ah*Wl + Al*Wh.
// cp.async staging with DOUBLE-BUFFERED k-loop (wait_group 1 steady state).
// ---------------------------------------------------------------------------
__global__ __launch_bounds__(256) void mma_gemm_kernel(
    int mode, const float* __restrict__ bias,
    const float* __restrict__ mask, float* __restrict__ out) {
    __shared__ __align__(16) char smb[61440];     // 2 x 30720
    const int AH = 0, AL = 10240, BH = 20480, BL = 25600;
    int tid = threadIdx.x, lane = tid & 31, wid = tid >> 5;
    int wm = wid & 1, wn = wid >> 1;
    int bx = blockIdx.x, m0 = blockIdx.y * 128;
    const __nv_bfloat16* Ah = (mode == 0) ? g_xh : g_ogh;
    const __nv_bfloat16* Al = (mode == 0) ? g_xl : g_ogl;
    int widx = (mode == 0) ? (bx >> 1) : 4;
    int nloc = (mode == 0) ? ((bx & 1) * 64) : bx * 64;
    int woff = widx * 16384;

    float c[4][2][4];
#pragma unroll
    for (int a = 0; a < 4; a++)
#pragma unroll
        for (int b = 0; b < 2; b++)
#pragma unroll
            for (int d = 0; d < 4; d++) c[a][b][d] = 0.f;

    int rowA = ((lane >> 3) & 1) * 8 + (lane & 7);
    int kofA = (lane >> 4) * 8;
    int rowB = (lane & 7) + ((lane >> 4) & 1) * 8;
    int kofB = ((lane >> 3) & 1) * 8;

    // stage k-tile kt into buffer base SB
    auto stage = [&](int kt, char* SB) {
#pragma unroll
        for (int p = 0; p < 2; p++) {
            int cix = tid + p * 256;
            int row = cix >> 2, g = cix & 3;
            size_t src = (size_t)(m0 + row) * 128 + kt + g * 8;
            cpa16(SB + AH + row * 80 + g * 16, Ah + src);
            cpa16(SB + AL + row * 80 + g * 16, Al + src);
        }
        {
            int row = tid >> 2, g = tid & 3;
            size_t src = (size_t)woff + (nloc + row) * 128 + kt + g * 8;
            cpa16(SB + BH + row * 80 + g * 16, g_wh + src);
            cpa16(SB + BL + row * 80 + g * 16, g_wl + src);
        }
        cpa_commit();
    };

    stage(0, smb);                                 // prologue: tile 0 -> buf 0

    for (int ktile = 0; ktile < 4; ktile++) {
        if (ktile < 3) {
            stage((ktile + 1) * 32, smb + ((ktile + 1) & 1) * 30720);
            cpa_wait<1>();
        } else {
            cpa_wait<0>();
        }
        __syncthreads();
        const char* SB = smb + (ktile & 1) * 30720;
#pragma unroll
        for (int ks = 0; ks < 2; ks++) {
            unsigned int ah[4][4], al[4][4], bh[4], bl[4];
#pragma unroll
            for (int mt = 0; mt < 4; mt++) {
                const char* pa = SB + AH + (wm * 64 + mt * 16 + rowA) * 80 +
                                 (ks * 16 + kofA) * 2;
                ldsm4(ah[mt], pa);
                ldsm4(al[mt], pa + (AL - AH));
            }
            const char* pb = SB + BH + (wn * 16 + rowB) * 80 +
                             (ks * 16 + kofB) * 2;
            ldsm4(bh, pb);
            ldsm4(bl, pb + (BL - BH));
#pragma unroll
            for (int mt = 0; mt < 4; mt++)
#pragma unroll
                for (int nt = 0; nt < 2; nt++) {
                    mma16816(c[mt][nt], ah[mt], &bh[nt * 2]);
                    mma16816(c[mt][nt], ah[mt], &bl[nt * 2]);
                    mma16816(c[mt][nt], al[mt], &bh[nt * 2]);
                }
        }
        __syncthreads();   // done reading this buffer before it is re-staged
    }

    const float qscale = 0.17677669529663687f * L2E;
#pragma unroll
    for (int mt = 0; mt < 4; mt++) {
        int r0 = m0 + wm * 64 + mt * 16 + (lane >> 2);
#pragma unroll
        for (int nt = 0; nt < 2; nt++) {
            int n = bx * 64 + wn * 16 + nt * 8 + (lane & 3) * 2;
            float v0 = c[mt][nt][0], v1 = c[mt][nt][1];
            float v2 = c[mt][nt][2], v3 = c[mt][nt][3];
            if (mode == 0) {
                if (n >= 384) {
                    float b0 = bias[n - 384], b1 = bias[n - 383];
                    v0 = 1.f / (1.f + ex2(-(v0 + b0) * L2E));
                    v1 = 1.f / (1.f + ex2(-(v1 + b1) * L2E));
                    v2 = 1.f / (1.f + ex2(-(v2 + b0) * L2E));
                    v3 = 1.f / (1.f + ex2(-(v3 + b1) * L2E));
                    *(__half2*)&g_gate[(size_t)r0 * 128 + n - 384] =
                        __floats2half2_rn(v0, v1);
                    *(__half2*)&g_gate[(size_t)(r0 + 8) * 128 + n - 384] =
                        __floats2half2_rn(v2, v3);
                } else {
                    if (n < 128) {
                        v0 *= qscale; v1 *= qscale; v2 *= qscale; v3 *= qscale;
                    }
                    unsigned h0 = pack2bf(v0, v1), h1 = pack2bf(v2, v3);
                    unsigned l0 = pack2bf(v0 - bflo(h0), v1 - bfhi(h0));
                    unsigned l1 = pack2bf(v2 - bflo(h1), v3 - bfhi(h1));
                    *(unsigned*)&g_kvh[(size_t)r0 * 384 + n] = h0;
                    *(unsigned*)&g_kvl[(size_t)r0 * 384 + n] = l0;
                    *(unsigned*)&g_kvh[(size_t)(r0 + 8) * 384 + n] = h1;
                    *(unsigned*)&g_kvl[(size_t)(r0 + 8) * 384 + n] = l1;
                }
            } else {
                float b0 = bias[n], b1 = bias[n + 1];
                float mk0 = mask[r0], mk1 = mask[r0 + 8];
                *(float2*)&out[(size_t)r0 * 128 + n] =
                    make_float2((v0 + b0) * mk0, (v1 + b1) * mk0);
                *(float2*)&out[(size_t)(r0 + 8) * 128 + n] =
                    make_float2((v2 + b0) * mk1, (v3 + b1) * mk1);
            }
        }
    }
}

// ---------------------------------------------------------------------------
// Kernel 3: tensor-core flash attention. CTA = 128 threads (4 warps),
// 128 query rows; warp w owns rows [w*32, w*32+32) (two 16-row M-tiles).
// grid (4, 512): h = bx, r = by>>1, qhalf = by&1.
// K/V staged by cp.async.cg into a double buffer (tile jt lives in
// buf[(jt+1)&1]); Q overlays buffer 0 during the prologue. Fused
// per-16-key-group QK -> EX2 -> pack -> PV pipeline.
// ---------------------------------------------------------------------------
__global__ __launch_bounds__(128, 4) void attn_mma_kernel(const float* __restrict__ mask) {
    __shared__ __align__(16) char smb[41984];
    // buffer b at b*20480: KH +0, KL +5120, VH +10240, VL +15360 (64 x 80B)
    float* bsm = (float*)(smb + 40960);

    int h = blockIdx.x;
    int r = blockIdx.y >> 1, qc = blockIdx.y & 1;
    int tid = threadIdx.x, lane = tid & 31, w = tid >> 5;
    int q0 = qc * 128;
    size_t rowbase = (size_t)(r * 256) * 384;

    bsm[tid] = (mask[r * 256 + tid] - 1.f) * (32768.f * L2E);
    bsm[tid + 128] = (mask[r * 256 + tid + 128] - 1.f) * (32768.f * L2E);

    // ---- prologue: Q -> buf0 (overlay), tile0 -> buf1 ----
#pragma unroll
    for (int p = 0; p < 4; p++) {
        int cix = tid + p * 128;            // 512 chunks/plane
        int row = cix >> 2, g = cix & 3;
        size_t src = rowbase + (size_t)(q0 + row) * 384 + h * 32 + g * 8;
        cpa16(smb + row * 80 + g * 16, g_kvh + src);
        cpa16(smb + 10240 + row * 80 + g * 16, g_kvl + src);
    }
    cpa_commit();
#pragma unroll
    for (int p = 0; p < 8; p++) {
        int cix = tid + p * 128;            // 1024 chunks: 4 planes x 256
        int pl = cix >> 8, rg = cix & 255;
        int row = rg >> 2, g = rg & 3;
        size_t src = rowbase + (size_t)row * 384 + ((pl >> 1) ? 256 : 128) +
                     h * 32 + g * 8;
        const __nv_bfloat16* sp = (pl & 1) ? g_kvl : g_kvh;
        cpa16(smb + 20480 + pl * 5120 + row * 80 + g * 16, sp + src);
    }
    cpa_commit();
    cpa_wait<1>();      // Q done (tile0 may be in flight)
    __syncthreads();

    int rowA = ((lane >> 3) & 1) * 8 + (lane & 7);
    int kofA = (lane >> 4) * 8;
    int rowB = (lane & 7) + ((lane >> 4) & 1) * 8;
    int kofB = ((lane >> 3) & 1) * 8;

    unsigned qh[2][2][4], ql[2][2][4];
#pragma unroll
    for (int mt = 0; mt < 2; mt++)
#pragma unroll
        for (int ks = 0; ks < 2; ks++) {
            const char* pq = smb + (w * 32 + mt * 16 + rowA) * 80 +
                             (ks * 16 + kofA) * 2;
            ldsm4(qh[mt][ks], pq);
            ldsm4(ql[mt][ks], pq + 10240);
        }
    __syncthreads();    // all warps done with Q region (buf0)

    float o[2][4][4];
#pragma unroll
    for (int mt = 0; mt < 2; mt++)
#pragma unroll
        for (int nt = 0; nt < 4; nt++)
#pragma unroll
            for (int d = 0; d < 4; d++) o[mt][nt][d] = 0.f;
    float lacc[2][2] = {{0.f, 0.f}, {0.f, 0.f}};

    int i1 = q0 + w * 32 + (lane >> 2);                 // mt=0 row; mt=1 is +16
    const float* nbrow = g_nb + h * 65536 + i1 * 256;

    for (int jt = 0; jt < 4; jt++) {
        if (jt < 3) {
            char* NB = smb + (jt & 1) * 20480;
#pragma unroll
            for (int p = 0; p < 8; p++) {
                int cix = tid + p * 128;
                int pl = cix >> 8, rg = cix & 255;
                int row = rg >> 2, g = rg & 3;
                size_t src = rowbase + (size_t)((jt + 1) * 64 + row) * 384 +
                             ((pl >> 1) ? 256 : 128) + h * 32 + g * 8;
                const __nv_bfloat16* sp = (pl & 1) ? g_kvl : g_kvh;
                cpa16(NB + pl * 5120 + row * 80 + g * 16, sp + src);
            }
            cpa_commit();
            cpa_wait<1>();
        } else {
            cpa_wait<0>();
        }
        __syncthreads();
        const char* B = smb + ((jt + 1) & 1) * 20480;   // tile jt's buffer

#pragma unroll
        for (int np = 0; np < 4; np++) {
            // ---- K fragments for this 16-key group ----
            unsigned kh4[2][4], kl4[2][4];
#pragma unroll
            for (int ks = 0; ks < 2; ks++) {
                const char* pkm = B + (np * 16 + rowB) * 80 + (ks * 16 + kofB) * 2;
                ldsm4(kh4[ks], pkm);
                ldsm4(kl4[ks], pkm + 5120);
            }
            // ---- S init = mask bias + nb ----
            float s[2][2][4];
#pragma unroll
            for (int mt = 0; mt < 2; mt++) {
                const float* nbp = nbrow + mt * 4096 + jt * 64 + np * 16;
#pragma unroll
                for (int ntl = 0; ntl < 2; ntl++) {
                    int j0l = ntl * 8 + (lane & 3) * 2;
                    float2 b2 = *(float2*)&bsm[jt * 64 + np * 16 + j0l];
                    float2 na = *(const float2*)&nbp[j0l];
                    float2 nb2 = *(const float2*)&nbp[2048 + j0l];
                    s[mt][ntl][0] = b2.x + na.x;
                    s[mt][ntl][1] = b2.y + na.y;
                    s[mt][ntl][2] = b2.x + nb2.x;
                    s[mt][ntl][3] = b2.y + nb2.y;
                }
            }
            // ---- QK^T (3-term split) ----
#pragma unroll
            for (int ks = 0; ks < 2; ks++)
#pragma unroll
                for (int mt = 0; mt < 2; mt++) {
                    mma16816(s[mt][0], qh[mt][ks], kh4[ks]);
                    mma16816(s[mt][0], qh[mt][ks], kl4[ks]);
                    mma16816(s[mt][0], ql[mt][ks], kh4[ks]);
                    mma16816(s[mt][1], qh[mt][ks], kh4[ks] + 2);
                    mma16816(s[mt][1], qh[mt][ks], kl4[ks] + 2);
                    mma16816(s[mt][1], ql[mt][ks], kh4[ks] + 2);
                }

            // ---- EX2 softmax + pack P A-fragments (split) ----
            unsigned ph[2][4], pl2[2][4];
#pragma unroll
            for (int mt = 0; mt < 2; mt++) {
                float e[8];
#pragma unroll
                for (int ntl = 0; ntl < 2; ntl++) {
                    float e0 = ex2(s[mt][ntl][0]);
                    float e1 = ex2(s[mt][ntl][1]);
                    float e2 = ex2(s[mt][ntl][2]);
                    float e3 = ex2(s[mt][ntl][3]);
                    lacc[mt][0] += e0 + e1;
                    lacc[mt][1] += e2 + e3;
                    e[ntl * 4 + 0] = e0; e[ntl * 4 + 1] = e1;
                    e[ntl * 4 + 2] = e2; e[ntl * 4 + 3] = e3;
                }
                unsigned p0 = pack2bf(e[0], e[1]);
                unsigned p1 = pack2bf(e[2], e[3]);
                unsigned p2 = pack2bf(e[4], e[5]);
                unsigned p3 = pack2bf(e[6], e[7]);
                ph[mt][0] = p0; ph[mt][1] = p1; ph[mt][2] = p2; ph[mt][3] = p3;
                pl2[mt][0] = pack2bf(e[0] - bflo(p0), e[1] - bfhi(p0));
                pl2[mt][1] = pack2bf(e[2] - bflo(p1), e[3] - bfhi(p1));
                pl2[mt][2] = pack2bf(e[4] - bflo(p2), e[5] - bfhi(p2));
                pl2[mt][3] = pack2bf(e[6] - bflo(p3), e[7] - bfhi(p3));
            }

            // ---- P @ V for this key group (3-term split) ----
#pragma unroll
            for (int vg = 0; vg < 2; vg++) {
                unsigned vh4[4], vl4[4];
                const char* pvm = B + 10240 + (np * 16 + (lane & 15)) * 80 +
                                  (vg * 16 + (lane >> 4) * 8) * 2;
                ldsm4t(vh4, pvm);
                ldsm4t(vl4, pvm + 5120);
#pragma unroll
                for (int mt = 0; mt < 2; mt++) {
                    mma16816(o[mt][vg * 2], ph[mt], vh4);
                    mma16816(o[mt][vg * 2], ph[mt], vl4);
                    mma16816(o[mt][vg * 2], pl2[mt], vh4);
                    mma16816(o[mt][vg * 2 + 1], ph[mt], vh4 + 2);
                    mma16816(o[mt][vg * 2 + 1], ph[mt], vl4 + 2);
                    mma16816(o[mt][vg * 2 + 1], pl2[mt], vh4 + 2);
                }
            }
        }
        __syncthreads();   // all warps done with this buffer before next issue
    }

    // ---- row-sum reduce (4 lanes per row) + gated epilogue ----
#pragma unroll
    for (int mt = 0; mt < 2; mt++) {
        float l0 = lacc[mt][0], l1 = lacc[mt][1];
        l0 += __shfl_xor_sync(0xffffffffu, l0, 1);
        l0 += __shfl_xor_sync(0xffffffffu, l0, 2);
        l1 += __shfl_xor_sync(0xffffffffu, l1, 1);
        l1 += __shfl_xor_sync(0xffffffffu, l1, 2);
        float rl0 = 1.f / l0, rl1 = 1.f / l1;
        size_t m0g = (size_t)(r * 256 + i1 + mt * 16);
#pragma unroll
        for (int nt = 0; nt < 4; nt++) {
            int vd0 = nt * 8 + (lane & 3) * 2;
            float2 g0 = __half22float2(*(const __half2*)&g_gate[m0g * 128 + h * 32 + vd0]);
            float2 g1 = __half22float2(*(const __half2*)&g_gate[(m0g + 8) * 128 + h * 32 + vd0]);
            float a0 = o[mt][nt][0] * rl0 * g0.x, a1 = o[mt][nt][1] * rl0 * g0.y;
            float a2 = o[mt][nt][2] * rl1 * g1.x, a3 = o[mt][nt][3] * rl1 * g1.y;
            unsigned h0 = pack2bf(a0, a1), h1 = pack2bf(a2, a3);
            unsigned l0p = pack2bf(a0 - bflo(h0), a1 - bfhi(h0));
            unsigned l1p = pack2bf(a2 - bflo(h1), a3 - bfhi(h1));
            *(unsigned*)&g_ogh[m0g * 128 + h * 32 + vd0] = h0;
            *(unsigned*)&g_ogl[m0g * 128 + h * 32 + vd0] = l0p;
            *(unsigned*)&g_ogh[(m0g + 8) * 128 + h * 32 + vd0] = h1;
            *(unsigned*)&g_ogl[(m0g + 8) * 128 + h * 32 + vd0] = l1p;
        }
    }
}

// ---------------------------------------------------------------------------

extern "C" void kernel_launch(void* const* d_in, const int* in_sizes, int n_in,
                              void* d_out, int out_size) {
    const float* pa  = (const float*)d_in[0];
    const float* pm  = (const float*)d_in[1];
    const float* lns = (const float*)d_in[2];
    const float* lnb = (const float*)d_in[3];
    const float* w2d = (const float*)d_in[4];
    const float* wq  = (const float*)d_in[5];
    const float* wk  = (const float*)d_in[6];
    const float* wv  = (const float*)d_in[7];
    const float* wg  = (const float*)d_in[8];
    const float* bg  = (const float*)d_in[9];
    const float* wo  = (const float*)d_in[10];
    const float* bo  = (const float*)d_in[11];
    float* out = (float*)d_out;

    prep_w_kernel<<<160, 512>>>(wq, wk, wv, wg, wo);
    ln_nb_kernel<<<8192, 256>>>(pa, lns, lnb, w2d);
    mma_gemm_kernel<<<dim3(8, 512), 256>>>(0, bg, nullptr, nullptr);
    attn_mma_kernel<<<dim3(4, 512), 128>>>(pm);
    mma_gemm_kernel<<<dim3(2, 512), 256>>>(1, bo, pm, out);
}

// round 13
// speedup vs baseline: 3.4923x; 1.0174x over previous
#include <cuda_runtime.h>
#include <cuda_bf16.h>
#include <cuda_fp16.h>

// TriangleAttention: B=1, N=256, D=128, H=4, kd=32
//   0. prep_w      : split wq|wk|wv|wg|wo into bf16 hi/lo planes
//   1. ln_nb       : warp-per-row LayerNorm -> bf16 hi/lo planes; nb*log2e
//   2. mma_gemm(0) : q|k bf16 hi/lo planes, v fp16, fp16 gate
//   3. attn_mma    : flash attention; QK split-bf16 (3 MMA), PV fp16 (1 MMA)
//   4. mma_gemm(1) : out = (og @ wo^T + bo) * mask
// Softmax is base-2 with a -4 shift folded into the bias so fp16 P can't
// overflow; the shift cancels exactly in O/l.

#define MTOT 65536
#define L2E 1.4426950408889634f

__device__ __align__(16) __nv_bfloat16 g_xh[MTOT * 128], g_xl[MTOT * 128];
__device__ __align__(16) __nv_bfloat16 g_kvh[MTOT * 256], g_kvl[MTOT * 256]; // q|k
__device__ __align__(16) __half g_v16[MTOT * 128];                            // v fp16
__device__ __align__(16) __nv_bfloat16 g_ogh[MTOT * 128], g_ogl[MTOT * 128];
__device__ __align__(16) __half g_gate[MTOT * 128];  // sigmoid(g+bg), fp16
__device__ __align__(16) float g_nb[4 * MTOT];       // [h][i*256+j], log2e folded
__device__ __align__(16) __nv_bfloat16 g_wh[5 * 16384];
__device__ __align__(16) __nv_bfloat16 g_wl[5 * 16384];

__device__ __forceinline__ float ex2(float x) {
    float y; asm("ex2.approx.ftz.f32 %0, %1;" : "=f"(y) : "f"(x)); return y;
}
__device__ __forceinline__ unsigned pack2bf(float lo, float hi) {
    unsigned d; asm("cvt.rn.bf16x2.f32 %0, %1, %2;" : "=r"(d) : "f"(hi), "f"(lo));
    return d;
}
__device__ __forceinline__ unsigned pack2f16(float lo, float hi) {
    unsigned d; asm("cvt.rn.f16x2.f32 %0, %1, %2;" : "=r"(d) : "f"(hi), "f"(lo));
    return d;
}
__device__ __forceinline__ float bflo(unsigned u) { return __uint_as_float(u << 16); }
__device__ __forceinline__ float bfhi(unsigned u) { return __uint_as_float(u & 0xffff0000u); }

__device__ __forceinline__ void cpa16(void* dst, const void* src) {
    unsigned d = (unsigned)__cvta_generic_to_shared(dst);
    asm volatile("cp.async.cg.shared.global [%0], [%1], 16;" :: "r"(d), "l"(src));
}
__device__ __forceinline__ void cpa_commit() {
    asm volatile("cp.async.commit_group;");
}
template <int N> __device__ __forceinline__ void cpa_wait() {
    asm volatile("cp.async.wait_group %0;" :: "n"(N));
}

__device__ __forceinline__ void ldsm4(unsigned int* r, const void* p) {
    unsigned int a = (unsigned int)__cvta_generic_to_shared(p);
    asm volatile("ldmatrix.sync.aligned.m8n8.x4.shared.b16 {%0,%1,%2,%3}, [%4];"
                 : "=r"(r[0]), "=r"(r[1]), "=r"(r[2]), "=r"(r[3]) : "r"(a));
}
__device__ __forceinline__ void ldsm4t(unsigned int* r, const void* p) {
    unsigned int a = (unsigned int)__cvta_generic_to_shared(p);
    asm volatile("ldmatrix.sync.aligned.m8n8.x4.trans.shared.b16 {%0,%1,%2,%3}, [%4];"
                 : "=r"(r[0]), "=r"(r[1]), "=r"(r[2]), "=r"(r[3]) : "r"(a));
}
__device__ __forceinline__ void mma16816(float* c, const unsigned int* a,
                                         const unsigned int* b) {
    asm volatile(
        "mma.sync.aligned.m16n8k16.row.col.f32.bf16.bf16.f32 "
        "{%0,%1,%2,%3}, {%4,%5,%6,%7}, {%8,%9}, {%0,%1,%2,%3};"
        : "+f"(c[0]), "+f"(c[1]), "+f"(c[2]), "+f"(c[3])
        : "r"(a[0]), "r"(a[1]), "r"(a[2]), "r"(a[3]), "r"(b[0]), "r"(b[1]));
}
__device__ __forceinline__ void mma16816h(float* c, const unsigned int* a,
                                          const unsigned int* b) {
    asm volatile(
        "mma.sync.aligned.m16n8k16.row.col.f32.f16.f16.f32 "
        "{%0,%1,%2,%3}, {%4,%5,%6,%7}, {%8,%9}, {%0,%1,%2,%3};"
        : "+f"(c[0]), "+f"(c[1]), "+f"(c[2]), "+f"(c[3])
        : "r"(a[0]), "r"(a[1]), "r"(a[2]), "r"(a[3]), "r"(b[0]), "r"(b[1]));
}

// ---------------------------------------------------------------------------
// Kernel 0: weight split
// ---------------------------------------------------------------------------
__global__ __launch_bounds__(512) void prep_w_kernel(
    const float* __restrict__ wq, const float* __restrict__ wk,
    const float* __restrict__ wv, const float* __restrict__ wg,
    const float* __restrict__ wo) {
    int idx = blockIdx.x * 512 + threadIdx.x;
    int which = idx >> 14, off = idx & 16383;
    float w;
    if (which == 0) w = wq[off];
    else if (which == 1) w = wk[off];
    else if (which == 2) w = wv[off];
    else if (which == 3) w = wg[off];
    else w = wo[off];
    __nv_bfloat16 h = __float2bfloat16(w);
    g_wh[idx] = h;
    g_wl[idx] = __float2bfloat16(w - __bfloat162float(h));
}

// ---------------------------------------------------------------------------
// Kernel 1: warp-per-row LayerNorm + nb. 256 threads = 8 rows; shuffle-only.
// ---------------------------------------------------------------------------
__global__ __launch_bounds__(256) void ln_nb_kernel(
    const float* __restrict__ pa, const float* __restrict__ sc,
    const float* __restrict__ bi, const float* __restrict__ w2d) {
    int lane = threadIdx.x & 31, wid = threadIdx.x >> 5;
    int m = blockIdx.x * 8 + wid;

    float4 v = *(const float4*)&pa[(size_t)m * 128 + lane * 4];
    float s1 = v.x + v.y + v.z + v.w;
    float s2 = v.x * v.x + v.y * v.y + v.z * v.z + v.w * v.w;
#pragma unroll
    for (int o = 16; o; o >>= 1) {
        s1 += __shfl_xor_sync(0xffffffffu, s1, o);
        s2 += __shfl_xor_sync(0xffffffffu, s2, o);
    }
    float mean = s1 * 0.0078125f;
    float var = s2 * 0.0078125f - mean * mean;
    float rs = rsqrtf(var + 1e-5f);
    float4 scv = *(const float4*)&sc[lane * 4];
    float4 biv = *(const float4*)&bi[lane * 4];
    float x0 = (v.x - mean) * rs * scv.x + biv.x;
    float x1 = (v.y - mean) * rs * scv.y + biv.y;
    float x2 = (v.z - mean) * rs * scv.z + biv.z;
    float x3 = (v.w - mean) * rs * scv.w + biv.w;

    unsigned h01 = pack2bf(x0, x1), h23 = pack2bf(x2, x3);
    unsigned l01 = pack2bf(x0 - bflo(h01), x1 - bfhi(h01));
    unsigned l23 = pack2bf(x2 - bflo(h23), x3 - bfhi(h23));
    *(uint2*)&g_xh[(size_t)m * 128 + lane * 4] = make_uint2(h01, h23);
    *(uint2*)&g_xl[(size_t)m * 128 + lane * 4] = make_uint2(l01, l23);

    float p[4];
#pragma unroll
    for (int hh = 0; hh < 4; hh++) {
        float4 wv4 = *(const float4*)&w2d[hh * 128 + lane * 4];
        float t = x0 * wv4.x + x1 * wv4.y + x2 * wv4.z + x3 * wv4.w;
#pragma unroll
        for (int o = 16; o; o >>= 1) t += __shfl_xor_sync(0xffffffffu, t, o);
        p[hh] = t;
    }
    if (lane < 4) {
        float sel = (lane == 0) ? p[0] : (lane == 1) ? p[1] : (lane == 2) ? p[2] : p[3];
        g_nb[lane * 65536 + m] = sel * L2E;
    }
}

// ---------------------------------------------------------------------------
// Kernels 2/4: split-bf16 tensor-core GEMM, C = A @ W^T (+ epilogue).
// Block 128(M) x 64(N), k-tile 32, 8 warps 2x4; C = Ah*Wh + Ah*Wl + Al*Wh.
// cp.async staging with double-buffered k-loop.
// mode 0 epilogue: n<128 q*scale -> kv planes; n<256 k -> kv planes;
//                  n<384 v -> fp16 g_v16; else sigmoid gate -> fp16 g_gate
// ---------------------------------------------------------------------------
__global__ __launch_bounds__(256) void mma_gemm_kernel(
    int mode, const float* __restrict__ bias,
    const float* __restrict__ mask, float* __restrict__ out) {
    __shared__ __align__(16) char smb[61440];     // 2 x 30720
    const int AH = 0, AL = 10240, BH = 20480, BL = 25600;
    int tid = threadIdx.x, lane = tid & 31, wid = tid >> 5;
    int wm = wid & 1, wn = wid >> 1;
    int bx = blockIdx.x, m0 = blockIdx.y * 128;
    const __nv_bfloat16* Ah = (mode == 0) ? g_xh : g_ogh;
    const __nv_bfloat16* Al = (mode == 0) ? g_xl : g_ogl;
    int widx = (mode == 0) ? (bx >> 1) : 4;
    int nloc = (mode == 0) ? ((bx & 1) * 64) : bx * 64;
    int woff = widx * 16384;

    float c[4][2][4];
#pragma unroll
    for (int a = 0; a < 4; a++)
#pragma unroll
        for (int b = 0; b < 2; b++)
#pragma unroll
            for (int d = 0; d < 4; d++) c[a][b][d] = 0.f;

    int rowA = ((lane >> 3) & 1) * 8 + (lane & 7);
    int kofA = (lane >> 4) * 8;
    int rowB = (lane & 7) + ((lane >> 4) & 1) * 8;
    int kofB = ((lane >> 3) & 1) * 8;

    auto stage = [&](int kt, char* SB) {
#pragma unroll
        for (int p = 0; p < 2; p++) {
            int cix = tid + p * 256;
            int row = cix >> 2, g = cix & 3;
            size_t src = (size_t)(m0 + row) * 128 + kt + g * 8;
            cpa16(SB + AH + row * 80 + g * 16, Ah + src);
            cpa16(SB + AL + row * 80 + g * 16, Al + src);
        }
        {
            int row = tid >> 2, g = tid & 3;
            size_t src = (size_t)woff + (nloc + row) * 128 + kt + g * 8;
            cpa16(SB + BH + row * 80 + g * 16, g_wh + src);
            cpa16(SB + BL + row * 80 + g * 16, g_wl + src);
        }
        cpa_commit();
    };

    stage(0, smb);

    for (int ktile = 0; ktile < 4; ktile++) {
        if (ktile < 3) {
            stage((ktile + 1) * 32, smb + ((ktile + 1) & 1) * 30720);
            cpa_wait<1>();
        } else {
            cpa_wait<0>();
        }
        __syncthreads();
        const char* SB = smb + (ktile & 1) * 30720;
#pragma unroll
        for (int ks = 0; ks < 2; ks++) {
            unsigned int ah[4][4], al[4][4], bh[4], bl[4];
#pragma unroll
            for (int mt = 0; mt < 4; mt++) {
                const char* pa = SB + AH + (wm * 64 + mt * 16 + rowA) * 80 +
                                 (ks * 16 + kofA) * 2;
                ldsm4(ah[mt], pa);
                ldsm4(al[mt], pa + (AL - AH));
            }
            const char* pb = SB + BH + (wn * 16 + rowB) * 80 +
                             (ks * 16 + kofB) * 2;
            ldsm4(bh, pb);
            ldsm4(bl, pb + (BL - BH));
#pragma unroll
            for (int mt = 0; mt < 4; mt++)
#pragma unroll
                for (int nt = 0; nt < 2; nt++) {
                    mma16816(c[mt][nt], ah[mt], &bh[nt * 2]);
                    mma16816(c[mt][nt], ah[mt], &bl[nt * 2]);
                    mma16816(c[mt][nt], al[mt], &bh[nt * 2]);
                }
        }
        __syncthreads();
    }

    const float qscale = 0.17677669529663687f * L2E;
#pragma unroll
    for (int mt = 0; mt < 4; mt++) {
        int r0 = m0 + wm * 64 + mt * 16 + (lane >> 2);
#pragma unroll
        for (int nt = 0; nt < 2; nt++) {
            int n = bx * 64 + wn * 16 + nt * 8 + (lane & 3) * 2;
            float v0 = c[mt][nt][0], v1 = c[mt][nt][1];
            float v2 = c[mt][nt][2], v3 = c[mt][nt][3];
            if (mode == 0) {
                if (n >= 384) {
                    float b0 = bias[n - 384], b1 = bias[n - 383];
                    v0 = 1.f / (1.f + ex2(-(v0 + b0) * L2E));
                    v1 = 1.f / (1.f + ex2(-(v1 + b1) * L2E));
                    v2 = 1.f / (1.f + ex2(-(v2 + b0) * L2E));
                    v3 = 1.f / (1.f + ex2(-(v3 + b1) * L2E));
                    *(__half2*)&g_gate[(size_t)r0 * 128 + n - 384] =
                        __floats2half2_rn(v0, v1);
                    *(__half2*)&g_gate[(size_t)(r0 + 8) * 128 + n - 384] =
                        __floats2half2_rn(v2, v3);
                } else if (n >= 256) {
                    *(unsigned*)&g_v16[(size_t)r0 * 128 + n - 256] = pack2f16(v0, v1);
                    *(unsigned*)&g_v16[(size_t)(r0 + 8) * 128 + n - 256] = pack2f16(v2, v3);
                } else {
                    if (n < 128) {
                        v0 *= qscale; v1 *= qscale; v2 *= qscale; v3 *= qscale;
                    }
                    unsigned h0 = pack2bf(v0, v1), h1 = pack2bf(v2, v3);
                    unsigned l0 = pack2bf(v0 - bflo(h0), v1 - bfhi(h0));
                    unsigned l1 = pack2bf(v2 - bflo(h1), v3 - bfhi(h1));
                    *(unsigned*)&g_kvh[(size_t)r0 * 256 + n] = h0;
                    *(unsigned*)&g_kvl[(size_t)r0 * 256 + n] = l0;
                    *(unsigned*)&g_kvh[(size_t)(r0 + 8) * 256 + n] = h1;
                    *(unsigned*)&g_kvl[(size_t)(r0 + 8) * 256 + n] = l1;
                }
            } else {
                float b0 = bias[n], b1 = bias[n + 1];
                float mk0 = mask[r0], mk1 = mask[r0 + 8];
                *(float2*)&out[(size_t)r0 * 128 + n] =
                    make_float2((v0 + b0) * mk0, (v1 + b1) * mk0);
                *(float2*)&out[(size_t)(r0 + 8) * 128 + n] =
                    make_float2((v2 + b0) * mk1, (v3 + b1) * mk1);
            }
        }
    }
}

// ---------------------------------------------------------------------------
// Kernel 3: tensor-core flash attention. CTA = 128 threads (4 warps),
// 128 query rows; warp w owns rows [w*32, w*32+32) (two 16-row M-tiles).
// grid (4, 512): h = bx, r = by>>1, qhalf = by&1.
// Buffers: bufA @0, bufB @20480, each KH+0|KL+5120|VF+10240 (15360 B).
// Q (QH@0, QL@10240) overlays bufA during the prologue; tile0 -> bufB.
// QK^T: 3-term split-bf16 MMA. PV: SINGLE fp16 MMA (P and V fp16).
// Softmax bias carries a -4 shift (fp16 P overflow guard; cancels in O/l).
// ---------------------------------------------------------------------------
__global__ __launch_bounds__(128, 4) void attn_mma_kernel(const float* __restrict__ mask) {
    __shared__ __align__(16) char smb[36864];
    float* bsm = (float*)(smb + 35840);

    int h = blockIdx.x;
    int r = blockIdx.y >> 1, qc = blockIdx.y & 1;
    int tid = threadIdx.x, lane = tid & 31, w = tid >> 5;
    int q0 = qc * 128;
    size_t rowbase = (size_t)(r * 256) * 256;      // q|k planes, 256 cols
    size_t vbase = (size_t)(r * 256) * 128;        // v plane, 128 cols

    bsm[tid] = (mask[r * 256 + tid] - 1.f) * (32768.f * L2E) - 4.f;
    bsm[tid + 128] = (mask[r * 256 + tid + 128] - 1.f) * (32768.f * L2E) - 4.f;

    // ---- prologue: Q -> bufA (QH@0, QL@10240), tile0 -> bufB(20480) ----
#pragma unroll
    for (int p = 0; p < 8; p++) {
        int cix = tid + p * 128;            // 1024 chunks: QH 0..511, QL 512..1023
        int rg = cix & 511;
        int row = rg >> 2, g = rg & 3;
        size_t src = rowbase + (size_t)(q0 + row) * 256 + h * 32 + g * 8;
        const __nv_bfloat16* sp = (cix < 512) ? g_kvh : g_kvl;
        cpa16(smb + (cix < 512 ? 0 : 10240) + row * 80 + g * 16, sp + src);
    }
    cpa_commit();
    {
        // tile0: K hi/lo (512 chunks) + V fp16 (256 chunks)
#pragma unroll
        for (int p = 0; p < 4; p++) {
            int cix = tid + p * 128;        // 0..511
            int row = cix >> 2, g = cix & 3;
            size_t src = rowbase + (size_t)row * 256 + 128 + h * 32 + g * 8;
            const __nv_bfloat16* sp = (p < 2) ? g_kvh : g_kvl;
            int rg2 = cix & 255;
            int row2 = rg2 >> 2, g2 = rg2 & 3;
            size_t src2 = rowbase + (size_t)row2 * 256 + 128 + h * 32 + g2 * 8;
            (void)src; (void)row; (void)g;
            cpa16(smb + 20480 + (p < 2 ? 0 : 5120) + row2 * 80 + g2 * 16, sp + src2);
        }
#pragma unroll
        for (int p = 0; p < 2; p++) {
            int cix = tid + p * 128;        // 0..255
            int row = cix >> 2, g = cix & 3;
            size_t src = vbase + (size_t)row * 128 + h * 32 + g * 8;
            cpa16(smb + 20480 + 10240 + row * 80 + g * 16, g_v16 + src);
        }
    }
    cpa_commit();
    cpa_wait<1>();      // Q done (tile0 may be in flight)
    __syncthreads();

    int rowA = ((lane >> 3) & 1) * 8 + (lane & 7);
    int kofA = (lane >> 4) * 8;
    int rowB = (lane & 7) + ((lane >> 4) & 1) * 8;
    int kofB = ((lane >> 3) & 1) * 8;

    unsigned qh[2][2][4], ql[2][2][4];
#pragma unroll
    for (int mt = 0; mt < 2; mt++)
#pragma unroll
        for (int ks = 0; ks < 2; ks++) {
            const char* pq = smb + (w * 32 + mt * 16 + rowA) * 80 +
                             (ks * 16 + kofA) * 2;
            ldsm4(qh[mt][ks], pq);
            ldsm4(ql[mt][ks], pq + 10240);
        }
    __syncthreads();    // all warps done with Q region (bufA)

    float o[2][4][4];
#pragma unroll
    for (int mt = 0; mt < 2; mt++)
#pragma unroll
        for (int nt = 0; nt < 4; nt++)
#pragma unroll
            for (int d = 0; d < 4; d++) o[mt][nt][d] = 0.f;
    float lacc[2][2] = {{0.f, 0.f}, {0.f, 0.f}};

    int i1 = q0 + w * 32 + (lane >> 2);                 // mt=0 row; mt=1 is +16
    const float* nbrow = g_nb + h * 65536 + i1 * 256;

    for (int jt = 0; jt < 4; jt++) {
        if (jt < 3) {
            // stage tile jt+1 into the buffer NOT used by tile jt
            char* NB = smb + ((jt & 1) ? 20480 : 0);
#pragma unroll
            for (int p = 0; p < 4; p++) {
                int cix = tid + p * 128;
                int rg2 = cix & 255;
                int row = rg2 >> 2, g = rg2 & 3;
                size_t src = rowbase + (size_t)((jt + 1) * 64 + row) * 256 + 128 +
                             h * 32 + g * 8;
                const __nv_bfloat16* sp = (p < 2) ? g_kvh : g_kvl;
                cpa16(NB + (p < 2 ? 0 : 5120) + row * 80 + g * 16, sp + src);
            }
#pragma unroll
            for (int p = 0; p < 2; p++) {
                int cix = tid + p * 128;
                int row = cix >> 2, g = cix & 3;
                size_t src = vbase + (size_t)((jt + 1) * 64 + row) * 128 +
                             h * 32 + g * 8;
                cpa16(NB + 10240 + row * 80 + g * 16, g_v16 + src);
            }
            cpa_commit();
            cpa_wait<1>();
        } else {
            cpa_wait<0>();
        }
        __syncthreads();
        const char* B = smb + ((jt & 1) ? 0 : 20480);   // tile jt's buffer

#pragma unroll
        for (int np = 0; np < 4; np++) {
            // ---- K fragments (bf16 hi/lo) ----
            unsigned kh4[2][4], kl4[2][4];
#pragma unroll
            for (int ks = 0; ks < 2; ks++) {
                const char* pkm = B + (np * 16 + rowB) * 80 + (ks * 16 + kofB) * 2;
                ldsm4(kh4[ks], pkm);
                ldsm4(kl4[ks], pkm + 5120);
            }
            // ---- S init = mask bias (incl. -4 shift) + nb ----
            float s[2][2][4];
#pragma unroll
            for (int mt = 0; mt < 2; mt++) {
                const float* nbp = nbrow + mt * 4096 + jt * 64 + np * 16;
#pragma unroll
                for (int ntl = 0; ntl < 2; ntl++) {
                    int j0l = ntl * 8 + (lane & 3) * 2;
                    float2 b2 = *(float2*)&bsm[jt * 64 + np * 16 + j0l];
                    float2 na = *(const float2*)&nbp[j0l];
                    float2 nb2 = *(const float2*)&nbp[2048 + j0l];
                    s[mt][ntl][0] = b2.x + na.x;
                    s[mt][ntl][1] = b2.y + na.y;
                    s[mt][ntl][2] = b2.x + nb2.x;
                    s[mt][ntl][3] = b2.y + nb2.y;
                }
            }
            // ---- QK^T (3-term split) ----
#pragma unroll
            for (int ks = 0; ks < 2; ks++)
#pragma unroll
                for (int mt = 0; mt < 2; mt++) {
                    mma16816(s[mt][0], qh[mt][ks], kh4[ks]);
                    mma16816(s[mt][0], qh[mt][ks], kl4[ks]);
                    mma16816(s[mt][0], ql[mt][ks], kh4[ks]);
                    mma16816(s[mt][1], qh[mt][ks], kh4[ks] + 2);
                    mma16816(s[mt][1], qh[mt][ks], kl4[ks] + 2);
                    mma16816(s[mt][1], ql[mt][ks], kh4[ks] + 2);
                }

            // ---- EX2 softmax + pack P as fp16 A-fragments ----
            unsigned pf[2][4];
#pragma unroll
            for (int mt = 0; mt < 2; mt++) {
                float e[8];
#pragma unroll
                for (int ntl = 0; ntl < 2; ntl++) {
                    float e0 = ex2(s[mt][ntl][0]);
                    float e1 = ex2(s[mt][ntl][1]);
                    float e2 = ex2(s[mt][ntl][2]);
                    float e3 = ex2(s[mt][ntl][3]);
                    lacc[mt][0] += e0 + e1;
                    lacc[mt][1] += e2 + e3;
                    e[ntl * 4 + 0] = e0; e[ntl * 4 + 1] = e1;
                    e[ntl * 4 + 2] = e2; e[ntl * 4 + 3] = e3;
                }
                pf[mt][0] = pack2f16(e[0], e[1]);
                pf[mt][1] = pack2f16(e[2], e[3]);
                pf[mt][2] = pack2f16(e[4], e[5]);
                pf[mt][3] = pack2f16(e[6], e[7]);
            }

            // ---- P @ V: single fp16 MMA per (vg, mt) pair ----
#pragma unroll
            for (int vg = 0; vg < 2; vg++) {
                unsigned vf4[4];
                const char* pvm = B + 10240 + (np * 16 + (lane & 15)) * 80 +
                                  (vg * 16 + (lane >> 4) * 8) * 2;
                ldsm4t(vf4, pvm);
#pragma unroll
                for (int mt = 0; mt < 2; mt++) {
                    mma16816h(o[mt][vg * 2], pf[mt], vf4);
                    mma16816h(o[mt][vg * 2 + 1], pf[mt], vf4 + 2);
                }
            }
        }
        __syncthreads();   // all warps done with this buffer before next issue
    }

    // ---- row-sum reduce (4 lanes per row) + gated epilogue ----
#pragma unroll
    for (int mt = 0; mt < 2; mt++) {
        float l0 = lacc[mt][0], l1 = lacc[mt][1];
        l0 += __shfl_xor_sync(0xffffffffu, l0, 1);
        l0 += __shfl_xor_sync(0xffffffffu, l0, 2);
        l1 += __shfl_xor_sync(0xffffffffu, l1, 1);
        l1 += __shfl_xor_sync(0xffffffffu, l1, 2);
        float rl0 = 1.f / l0, rl1 = 1.f / l1;
        size_t m0g = (size_t)(r * 256 + i1 + mt * 16);
#pragma unroll
        for (int nt = 0; nt < 4; nt++) {
            int vd0 = nt * 8 + (lane & 3) * 2;
            float2 g0 = __half22float2(*(const __half2*)&g_gate[m0g * 128 + h * 32 + vd0]);
            float2 g1 = __half22float2(*(const __half2*)&g_gate[(m0g + 8) * 128 + h * 32 + vd0]);
            float a0 = o[mt][nt][0] * rl0 * g0.x, a1 = o[mt][nt][1] * rl0 * g0.y;
            float a2 = o[mt][nt][2] * rl1 * g1.x, a3 = o[mt][nt][3] * rl1 * g1.y;
            unsigned h0 = pack2bf(a0, a1), h1 = pack2bf(a2, a3);
            unsigned l0p = pack2bf(a0 - bflo(h0), a1 - bfhi(h0));
            unsigned l1p = pack2bf(a2 - bflo(h1), a3 - bfhi(h1));
            *(unsigned*)&g_ogh[m0g * 128 + h * 32 + vd0] = h0;
            *(unsigned*)&g_ogl[m0g * 128 + h * 32 + vd0] = l0p;
            *(unsigned*)&g_ogh[(m0g + 8) * 128 + h * 32 + vd0] = h1;
            *(unsigned*)&g_ogl[(m0g + 8) * 128 + h * 32 + vd0] = l1p;
        }
    }
}

// ---------------------------------------------------------------------------

extern "C" void kernel_launch(void* const* d_in, const int* in_sizes, int n_in,
                              void* d_out, int out_size) {
    const float* pa  = (const float*)d_in[0];
    const float* pm  = (const float*)d_in[1];
    const float* lns = (const float*)d_in[2];
    const float* lnb = (const float*)d_in[3];
    const float* w2d = (const float*)d_in[4];
    const float* wq  = (const float*)d_in[5];
    const float* wk  = (const float*)d_in[6];
    const float* wv  = (const float*)d_in[7];
    const float* wg  = (const float*)d_in[8];
    const float* bg  = (const float*)d_in[9];
    const float* wo  = (const float*)d_in[10];
    const float* bo  = (const float*)d_in[11];
    float* out = (float*)d_out;

    prep_w_kernel<<<160, 512>>>(wq, wk, wv, wg, wo);
    ln_nb_kernel<<<8192, 256>>>(pa, lns, lnb, w2d);
    mma_gemm_kernel<<<dim3(8, 512), 256>>>(0, bg, nullptr, nullptr);
    attn_mma_kernel<<<dim3(4, 512), 128>>>(pm);
    mma_gemm_kernel<<<dim3(2, 512), 256>>>(1, bo, pm, out);
}

// round 14
// speedup vs baseline: 4.0714x; 1.1658x over previous
#include <cuda_runtime.h>
#include <cuda_bf16.h>
#include <cuda_fp16.h>

// TriangleAttention: B=1, N=256, D=128, H=4, kd=32
//   0. prep_w      : split wq|wk|wv|wg|wo into bf16 hi/lo planes
//   1. ln_nb       : warp-per-row LayerNorm -> bf16 hi/lo planes; nb*log2e
//   2. mma_gemm(0) : q|k fp16 plane, v fp16, fp16 gate  (split-bf16 compute)
//   3. attn_mma    : flash attention; QK fp16 (1 MMA), PV fp16 (1 MMA)
//   4. mma_gemm(1) : out = (og @ wo^T + bo) * mask      (split-bf16, full acc)
// Softmax is base-2 with a -4 shift folded into the bias so fp16 P can't
// overflow; the shift cancels exactly in O/l.

#define MTOT 65536
#define L2E 1.4426950408889634f

__device__ __align__(16) __nv_bfloat16 g_xh[MTOT * 128], g_xl[MTOT * 128];
__device__ __align__(16) __half g_qk16[MTOT * 256];   // q (scaled) | k, fp16
__device__ __align__(16) __half g_v16[MTOT * 128];    // v fp16
__device__ __align__(16) __nv_bfloat16 g_ogh[MTOT * 128], g_ogl[MTOT * 128];
__device__ __align__(16) __half g_gate[MTOT * 128];   // sigmoid(g+bg), fp16
__device__ __align__(16) float g_nb[4 * MTOT];        // [h][i*256+j], log2e folded
__device__ __align__(16) __nv_bfloat16 g_wh[5 * 16384];
__device__ __align__(16) __nv_bfloat16 g_wl[5 * 16384];

__device__ __forceinline__ float ex2(float x) {
    float y; asm("ex2.approx.ftz.f32 %0, %1;" : "=f"(y) : "f"(x)); return y;
}
__device__ __forceinline__ unsigned pack2bf(float lo, float hi) {
    unsigned d; asm("cvt.rn.bf16x2.f32 %0, %1, %2;" : "=r"(d) : "f"(hi), "f"(lo));
    return d;
}
__device__ __forceinline__ unsigned pack2f16(float lo, float hi) {
    unsigned d; asm("cvt.rn.f16x2.f32 %0, %1, %2;" : "=r"(d) : "f"(hi), "f"(lo));
    return d;
}
__device__ __forceinline__ float bflo(unsigned u) { return __uint_as_float(u << 16); }
__device__ __forceinline__ float bfhi(unsigned u) { return __uint_as_float(u & 0xffff0000u); }

__device__ __forceinline__ void cpa16(void* dst, const void* src) {
    unsigned d = (unsigned)__cvta_generic_to_shared(dst);
    asm volatile("cp.async.cg.shared.global [%0], [%1], 16;" :: "r"(d), "l"(src));
}
__device__ __forceinline__ void cpa_commit() {
    asm volatile("cp.async.commit_group;");
}
template <int N> __device__ __forceinline__ void cpa_wait() {
    asm volatile("cp.async.wait_group %0;" :: "n"(N));
}

__device__ __forceinline__ void ldsm4(unsigned int* r, const void* p) {
    unsigned int a = (unsigned int)__cvta_generic_to_shared(p);
    asm volatile("ldmatrix.sync.aligned.m8n8.x4.shared.b16 {%0,%1,%2,%3}, [%4];"
                 : "=r"(r[0]), "=r"(r[1]), "=r"(r[2]), "=r"(r[3]) : "r"(a));
}
__device__ __forceinline__ void ldsm4t(unsigned int* r, const void* p) {
    unsigned int a = (unsigned int)__cvta_generic_to_shared(p);
    asm volatile("ldmatrix.sync.aligned.m8n8.x4.trans.shared.b16 {%0,%1,%2,%3}, [%4];"
                 : "=r"(r[0]), "=r"(r[1]), "=r"(r[2]), "=r"(r[3]) : "r"(a));
}
__device__ __forceinline__ void mma16816(float* c, const unsigned int* a,
                                         const unsigned int* b) {
    asm volatile(
        "mma.sync.aligned.m16n8k16.row.col.f32.bf16.bf16.f32 "
        "{%0,%1,%2,%3}, {%4,%5,%6,%7}, {%8,%9}, {%0,%1,%2,%3};"
        : "+f"(c[0]), "+f"(c[1]), "+f"(c[2]), "+f"(c[3])
        : "r"(a[0]), "r"(a[1]), "r"(a[2]), "r"(a[3]), "r"(b[0]), "r"(b[1]));
}
__device__ __forceinline__ void mma16816h(float* c, const unsigned int* a,
                                          const unsigned int* b) {
    asm volatile(
        "mma.sync.aligned.m16n8k16.row.col.f32.f16.f16.f32 "
        "{%0,%1,%2,%3}, {%4,%5,%6,%7}, {%8,%9}, {%0,%1,%2,%3};"
        : "+f"(c[0]), "+f"(c[1]), "+f"(c[2]), "+f"(c[3])
        : "r"(a[0]), "r"(a[1]), "r"(a[2]), "r"(a[3]), "r"(b[0]), "r"(b[1]));
}

// ---------------------------------------------------------------------------
// Kernel 0: weight split
// ---------------------------------------------------------------------------
__global__ __launch_bounds__(512) void prep_w_kernel(
    const float* __restrict__ wq, const float* __restrict__ wk,
    const float* __restrict__ wv, const float* __restrict__ wg,
    const float* __restrict__ wo) {
    int idx = blockIdx.x * 512 + threadIdx.x;
    int which = idx >> 14, off = idx & 16383;
    float w;
    if (which == 0) w = wq[off];
    else if (which == 1) w = wk[off];
    else if (which == 2) w = wv[off];
    else if (which == 3) w = wg[off];
    else w = wo[off];
    __nv_bfloat16 h = __float2bfloat16(w);
    g_wh[idx] = h;
    g_wl[idx] = __float2bfloat16(w - __bfloat162float(h));
}

// ---------------------------------------------------------------------------
// Kernel 1: warp-per-row LayerNorm + nb. 256 threads = 8 rows; shuffle-only.
// ---------------------------------------------------------------------------
__global__ __launch_bounds__(256) void ln_nb_kernel(
    const float* __restrict__ pa, const float* __restrict__ sc,
    const float* __restrict__ bi, const float* __restrict__ w2d) {
    int lane = threadIdx.x & 31, wid = threadIdx.x >> 5;
    int m = blockIdx.x * 8 + wid;

    float4 v = *(const float4*)&pa[(size_t)m * 128 + lane * 4];
    float s1 = v.x + v.y + v.z + v.w;
    float s2 = v.x * v.x + v.y * v.y + v.z * v.z + v.w * v.w;
#pragma unroll
    for (int o = 16; o; o >>= 1) {
        s1 += __shfl_xor_sync(0xffffffffu, s1, o);
        s2 += __shfl_xor_sync(0xffffffffu, s2, o);
    }
    float mean = s1 * 0.0078125f;
    float var = s2 * 0.0078125f - mean * mean;
    float rs = rsqrtf(var + 1e-5f);
    float4 scv = *(const float4*)&sc[lane * 4];
    float4 biv = *(const float4*)&bi[lane * 4];
    float x0 = (v.x - mean) * rs * scv.x + biv.x;
    float x1 = (v.y - mean) * rs * scv.y + biv.y;
    float x2 = (v.z - mean) * rs * scv.z + biv.z;
    float x3 = (v.w - mean) * rs * scv.w + biv.w;

    unsigned h01 = pack2bf(x0, x1), h23 = pack2bf(x2, x3);
    unsigned l01 = pack2bf(x0 - bflo(h01), x1 - bfhi(h01));
    unsigned l23 = pack2bf(x2 - bflo(h23), x3 - bfhi(h23));
    *(uint2*)&g_xh[(size_t)m * 128 + lane * 4] = make_uint2(h01, h23);
    *(uint2*)&g_xl[(size_t)m * 128 + lane * 4] = make_uint2(l01, l23);

    float p[4];
#pragma unroll
    for (int hh = 0; hh < 4; hh++) {
        float4 wv4 = *(const float4*)&w2d[hh * 128 + lane * 4];
        float t = x0 * wv4.x + x1 * wv4.y + x2 * wv4.z + x3 * wv4.w;
#pragma unroll
        for (int o = 16; o; o >>= 1) t += __shfl_xor_sync(0xffffffffu, t, o);
        p[hh] = t;
    }
    if (lane < 4) {
        float sel = (lane == 0) ? p[0] : (lane == 1) ? p[1] : (lane == 2) ? p[2] : p[3];
        g_nb[lane * 65536 + m] = sel * L2E;
    }
}

// ---------------------------------------------------------------------------
// Kernels 2/4: split-bf16 tensor-core GEMM, C = A @ W^T (+ epilogue).
// Block 128(M) x 64(N), k-tile 32, 8 warps 2x4; C = Ah*Wh + Ah*Wl + Al*Wh.
// cp.async staging with double-buffered k-loop.
// mode 0 epilogue: n<256 q*scale|k -> fp16 g_qk16; n<384 v -> fp16 g_v16;
//                  else sigmoid gate -> fp16 g_gate
// ---------------------------------------------------------------------------
__global__ __launch_bounds__(256) void mma_gemm_kernel(
    int mode, const float* __restrict__ bias,
    const float* __restrict__ mask, float* __restrict__ out) {
    __shared__ __align__(16) char smb[61440];     // 2 x 30720
    const int AH = 0, AL = 10240, BH = 20480, BL = 25600;
    int tid = threadIdx.x, lane = tid & 31, wid = tid >> 5;
    int wm = wid & 1, wn = wid >> 1;
    int bx = blockIdx.x, m0 = blockIdx.y * 128;
    const __nv_bfloat16* Ah = (mode == 0) ? g_xh : g_ogh;
    const __nv_bfloat16* Al = (mode == 0) ? g_xl : g_ogl;
    int widx = (mode == 0) ? (bx >> 1) : 4;
    int nloc = (mode == 0) ? ((bx & 1) * 64) : bx * 64;
    int woff = widx * 16384;

    float c[4][2][4];
#pragma unroll
    for (int a = 0; a < 4; a++)
#pragma unroll
        for (int b = 0; b < 2; b++)
#pragma unroll
            for (int d = 0; d < 4; d++) c[a][b][d] = 0.f;

    int rowA = ((lane >> 3) & 1) * 8 + (lane & 7);
    int kofA = (lane >> 4) * 8;
    int rowB = (lane & 7) + ((lane >> 4) & 1) * 8;
    int kofB = ((lane >> 3) & 1) * 8;

    auto stage = [&](int kt, char* SB) {
#pragma unroll
        for (int p = 0; p < 2; p++) {
            int cix = tid + p * 256;
            int row = cix >> 2, g = cix & 3;
            size_t src = (size_t)(m0 + row) * 128 + kt + g * 8;
            cpa16(SB + AH + row * 80 + g * 16, Ah + src);
            cpa16(SB + AL + row * 80 + g * 16, Al + src);
        }
        {
            int row = tid >> 2, g = tid & 3;
            size_t src = (size_t)woff + (nloc + row) * 128 + kt + g * 8;
            cpa16(SB + BH + row * 80 + g * 16, g_wh + src);
            cpa16(SB + BL + row * 80 + g * 16, g_wl + src);
        }
        cpa_commit();
    };

    stage(0, smb);

    for (int ktile = 0; ktile < 4; ktile++) {
        if (ktile < 3) {
            stage((ktile + 1) * 32, smb + ((ktile + 1) & 1) * 30720);
            cpa_wait<1>();
        } else {
            cpa_wait<0>();
        }
        __syncthreads();
        const char* SB = smb + (ktile & 1) * 30720;
#pragma unroll
        for (int ks = 0; ks < 2; ks++) {
            unsigned int ah[4][4], al[4][4], bh[4], bl[4];
#pragma unroll
            for (int mt = 0; mt < 4; mt++) {
                const char* pa = SB + AH + (wm * 64 + mt * 16 + rowA) * 80 +
                                 (ks * 16 + kofA) * 2;
                ldsm4(ah[mt], pa);
                ldsm4(al[mt], pa + (AL - AH));
            }
            const char* pb = SB + BH + (wn * 16 + rowB) * 80 +
                             (ks * 16 + kofB) * 2;
            ldsm4(bh, pb);
            ldsm4(bl, pb + (BL - BH));
#pragma unroll
            for (int mt = 0; mt < 4; mt++)
#pragma unroll
                for (int nt = 0; nt < 2; nt++) {
                    mma16816(c[mt][nt], ah[mt], &bh[nt * 2]);
                    mma16816(c[mt][nt], ah[mt], &bl[nt * 2]);
                    mma16816(c[mt][nt], al[mt], &bh[nt * 2]);
                }
        }
        __syncthreads();
    }

    const float qscale = 0.17677669529663687f * L2E;
#pragma unroll
    for (int mt = 0; mt < 4; mt++) {
        int r0 = m0 + wm * 64 + mt * 16 + (lane >> 2);
#pragma unroll
        for (int nt = 0; nt < 2; nt++) {
            int n = bx * 64 + wn * 16 + nt * 8 + (lane & 3) * 2;
            float v0 = c[mt][nt][0], v1 = c[mt][nt][1];
            float v2 = c[mt][nt][2], v3 = c[mt][nt][3];
            if (mode == 0) {
                if (n >= 384) {
                    float b0 = bias[n - 384], b1 = bias[n - 383];
                    v0 = 1.f / (1.f + ex2(-(v0 + b0) * L2E));
                    v1 = 1.f / (1.f + ex2(-(v1 + b1) * L2E));
                    v2 = 1.f / (1.f + ex2(-(v2 + b0) * L2E));
                    v3 = 1.f / (1.f + ex2(-(v3 + b1) * L2E));
                    *(__half2*)&g_gate[(size_t)r0 * 128 + n - 384] =
                        __floats2half2_rn(v0, v1);
                    *(__half2*)&g_gate[(size_t)(r0 + 8) * 128 + n - 384] =
                        __floats2half2_rn(v2, v3);
                } else if (n >= 256) {
                    *(unsigned*)&g_v16[(size_t)r0 * 128 + n - 256] = pack2f16(v0, v1);
                    *(unsigned*)&g_v16[(size_t)(r0 + 8) * 128 + n - 256] = pack2f16(v2, v3);
                } else {
                    if (n < 128) {
                        v0 *= qscale; v1 *= qscale; v2 *= qscale; v3 *= qscale;
                    }
                    *(unsigned*)&g_qk16[(size_t)r0 * 256 + n] = pack2f16(v0, v1);
                    *(unsigned*)&g_qk16[(size_t)(r0 + 8) * 256 + n] = pack2f16(v2, v3);
                }
            } else {
                float b0 = bias[n], b1 = bias[n + 1];
                float mk0 = mask[r0], mk1 = mask[r0 + 8];
                *(float2*)&out[(size_t)r0 * 128 + n] =
                    make_float2((v0 + b0) * mk0, (v1 + b1) * mk0);
                *(float2*)&out[(size_t)(r0 + 8) * 128 + n] =
                    make_float2((v2 + b0) * mk1, (v3 + b1) * mk1);
            }
        }
    }
}

// ---------------------------------------------------------------------------
// Kernel 3: tensor-core flash attention, all-fp16 operands. CTA = 128
// threads (4 warps), 128 query rows; warp w owns rows [w*32, w*32+32).
// grid (4, 512): h = bx, r = by>>1, qhalf = by&1.
// Buffers: bufA @0, bufB @10240; each K@+0 (5120) | V@+5120 (5120).
// Q (fp16, 10240B) overlays bufA during the prologue; tile0 -> bufB.
// QK^T: 1 fp16 MMA per (ks,mt,n-half). PV: 1 fp16 MMA. Softmax bias carries
// a -4 shift (fp16 P overflow guard; cancels in O/l).
// ---------------------------------------------------------------------------
__global__ __launch_bounds__(128, 5) void attn_mma_kernel(const float* __restrict__ mask) {
    __shared__ __align__(16) char smb[21504];
    float* bsm = (float*)(smb + 20480);

    int h = blockIdx.x;
    int r = blockIdx.y >> 1, qc = blockIdx.y & 1;
    int tid = threadIdx.x, lane = tid & 31, w = tid >> 5;
    int q0 = qc * 128;
    size_t qkbase = (size_t)(r * 256) * 256;       // q|k plane, 256 cols
    size_t vbase = (size_t)(r * 256) * 128;        // v plane, 128 cols

    bsm[tid] = (mask[r * 256 + tid] - 1.f) * (32768.f * L2E) - 4.f;
    bsm[tid + 128] = (mask[r * 256 + tid + 128] - 1.f) * (32768.f * L2E) - 4.f;

    // ---- prologue: Q -> bufA (overlay), tile0 -> bufB ----
#pragma unroll
    for (int p = 0; p < 4; p++) {
        int cix = tid + p * 128;            // 512 chunks = 128 rows x 4
        int row = cix >> 2, g = cix & 3;
        size_t src = qkbase + (size_t)(q0 + row) * 256 + h * 32 + g * 8;
        cpa16(smb + row * 80 + g * 16, g_qk16 + src);
    }
    cpa_commit();
#pragma unroll
    for (int p = 0; p < 2; p++) {           // tile0 K: 256 chunks
        int cix = tid + p * 128;
        int row = cix >> 2, g = cix & 3;
        size_t src = qkbase + (size_t)row * 256 + 128 + h * 32 + g * 8;
        cpa16(smb + 10240 + row * 80 + g * 16, g_qk16 + src);
    }
#pragma unroll
    for (int p = 0; p < 2; p++) {           // tile0 V: 256 chunks
        int cix = tid + p * 128;
        int row = cix >> 2, g = cix & 3;
        size_t src = vbase + (size_t)row * 128 + h * 32 + g * 8;
        cpa16(smb + 10240 + 5120 + row * 80 + g * 16, g_v16 + src);
    }
    cpa_commit();
    cpa_wait<1>();      // Q done (tile0 may be in flight)
    __syncthreads();

    int rowA = ((lane >> 3) & 1) * 8 + (lane & 7);
    int kofA = (lane >> 4) * 8;
    int rowB = (lane & 7) + ((lane >> 4) & 1) * 8;
    int kofB = ((lane >> 3) & 1) * 8;

    unsigned qf[2][2][4];
#pragma unroll
    for (int mt = 0; mt < 2; mt++)
#pragma unroll
        for (int ks = 0; ks < 2; ks++)
            ldsm4(qf[mt][ks], smb + (w * 32 + mt * 16 + rowA) * 80 +
                              (ks * 16 + kofA) * 2);
    __syncthreads();    // all warps done with Q region (bufA)

    float o[2][4][4];
#pragma unroll
    for (int mt = 0; mt < 2; mt++)
#pragma unroll
        for (int nt = 0; nt < 4; nt++)
#pragma unroll
            for (int d = 0; d < 4; d++) o[mt][nt][d] = 0.f;
    float lacc[2][2] = {{0.f, 0.f}, {0.f, 0.f}};

    int i1 = q0 + w * 32 + (lane >> 2);                 // mt=0 row; mt=1 is +16
    const float* nbrow = g_nb + h * 65536 + i1 * 256;

    for (int jt = 0; jt < 4; jt++) {
        if (jt < 3) {
            // tile jt lives in bufB for even jt, bufA for odd; stage jt+1
            // into the other buffer.
            char* NB = smb + ((jt & 1) ? 10240 : 0);
#pragma unroll
            for (int p = 0; p < 2; p++) {
                int cix = tid + p * 128;
                int row = cix >> 2, g = cix & 3;
                size_t src = qkbase + (size_t)((jt + 1) * 64 + row) * 256 + 128 +
                             h * 32 + g * 8;
                cpa16(NB + row * 80 + g * 16, g_qk16 + src);
            }
#pragma unroll
            for (int p = 0; p < 2; p++) {
                int cix = tid + p * 128;
                int row = cix >> 2, g = cix & 3;
                size_t src = vbase + (size_t)((jt + 1) * 64 + row) * 128 +
                             h * 32 + g * 8;
                cpa16(NB + 5120 + row * 80 + g * 16, g_v16 + src);
            }
            cpa_commit();
            cpa_wait<1>();
        } else {
            cpa_wait<0>();
        }
        __syncthreads();
        const char* B = smb + ((jt & 1) ? 0 : 10240);   // tile jt's buffer

#pragma unroll
        for (int np = 0; np < 4; np++) {
            // ---- K fragments (fp16, single plane) ----
            unsigned kf[2][4];
#pragma unroll
            for (int ks = 0; ks < 2; ks++)
                ldsm4(kf[ks], B + (np * 16 + rowB) * 80 + (ks * 16 + kofB) * 2);
            // ---- S init = mask bias (incl. -4 shift) + nb ----
            float s[2][2][4];
#pragma unroll
            for (int mt = 0; mt < 2; mt++) {
                const float* nbp = nbrow + mt * 4096 + jt * 64 + np * 16;
#pragma unroll
                for (int ntl = 0; ntl < 2; ntl++) {
                    int j0l = ntl * 8 + (lane & 3) * 2;
                    float2 b2 = *(float2*)&bsm[jt * 64 + np * 16 + j0l];
                    float2 na = *(const float2*)&nbp[j0l];
                    float2 nb2 = *(const float2*)&nbp[2048 + j0l];
                    s[mt][ntl][0] = b2.x + na.x;
                    s[mt][ntl][1] = b2.y + na.y;
                    s[mt][ntl][2] = b2.x + nb2.x;
                    s[mt][ntl][3] = b2.y + nb2.y;
                }
            }
            // ---- QK^T: single fp16 MMA per (ks, mt, n-half) ----
#pragma unroll
            for (int ks = 0; ks < 2; ks++)
#pragma unroll
                for (int mt = 0; mt < 2; mt++) {
                    mma16816h(s[mt][0], qf[mt][ks], kf[ks]);
                    mma16816h(s[mt][1], qf[mt][ks], kf[ks] + 2);
                }

            // ---- EX2 softmax + pack P as fp16 A-fragments ----
            unsigned pf[2][4];
#pragma unroll
            for (int mt = 0; mt < 2; mt++) {
                float e[8];
#pragma unroll
                for (int ntl = 0; ntl < 2; ntl++) {
                    float e0 = ex2(s[mt][ntl][0]);
                    float e1 = ex2(s[mt][ntl][1]);
                    float e2 = ex2(s[mt][ntl][2]);
                    float e3 = ex2(s[mt][ntl][3]);
                    lacc[mt][0] += e0 + e1;
                    lacc[mt][1] += e2 + e3;
                    e[ntl * 4 + 0] = e0; e[ntl * 4 + 1] = e1;
                    e[ntl * 4 + 2] = e2; e[ntl * 4 + 3] = e3;
                }
                pf[mt][0] = pack2f16(e[0], e[1]);
                pf[mt][1] = pack2f16(e[2], e[3]);
                pf[mt][2] = pack2f16(e[4], e[5]);
                pf[mt][3] = pack2f16(e[6], e[7]);
            }

            // ---- P @ V: single fp16 MMA per (vg, mt) pair ----
#pragma unroll
            for (int vg = 0; vg < 2; vg++) {
                unsigned vf4[4];
                const char* pvm = B + 5120 + (np * 16 + (lane & 15)) * 80 +
                                  (vg * 16 + (lane >> 4) * 8) * 2;
                ldsm4t(vf4, pvm);
#pragma unroll
                for (int mt = 0; mt < 2; mt++) {
                    mma16816h(o[mt][vg * 2], pf[mt], vf4);
                    mma16816h(o[mt][vg * 2 + 1], pf[mt], vf4 + 2);
                }
            }
        }
        __syncthreads();   // all warps done with this buffer before next issue
    }

    // ---- row-sum reduce (4 lanes per row) + gated epilogue ----
#pragma unroll
    for (int mt = 0; mt < 2; mt++) {
        float l0 = lacc[mt][0], l1 = lacc[mt][1];
        l0 += __shfl_xor_sync(0xffffffffu, l0, 1);
        l0 += __shfl_xor_sync(0xffffffffu, l0, 2);
        l1 += __shfl_xor_sync(0xffffffffu, l1, 1);
        l1 += __shfl_xor_sync(0xffffffffu, l1, 2);
        float rl0 = 1.f / l0, rl1 = 1.f / l1;
        size_t m0g = (size_t)(r * 256 + i1 + mt * 16);
#pragma unroll
        for (int nt = 0; nt < 4; nt++) {
            int vd0 = nt * 8 + (lane & 3) * 2;
            float2 g0 = __half22float2(*(const __half2*)&g_gate[m0g * 128 + h * 32 + vd0]);
            float2 g1 = __half22float2(*(const __half2*)&g_gate[(m0g + 8) * 128 + h * 32 + vd0]);
            float a0 = o[mt][nt][0] * rl0 * g0.x, a1 = o[mt][nt][1] * rl0 * g0.y;
            float a2 = o[mt][nt][2] * rl1 * g1.x, a3 = o[mt][nt][3] * rl1 * g1.y;
            unsigned h0 = pack2bf(a0, a1), h1 = pack2bf(a2, a3);
            unsigned l0p = pack2bf(a0 - bflo(h0), a1 - bfhi(h0));
            unsigned l1p = pack2bf(a2 - bflo(h1), a3 - bfhi(h1));
            *(unsigned*)&g_ogh[m0g * 128 + h * 32 + vd0] = h0;
            *(unsigned*)&g_ogl[m0g * 128 + h * 32 + vd0] = l0p;
            *(unsigned*)&g_ogh[(m0g + 8) * 128 + h * 32 + vd0] = h1;
            *(unsigned*)&g_ogl[(m0g + 8) * 128 + h * 32 + vd0] = l1p;
        }
    }
}

// ---------------------------------------------------------------------------

extern "C" void kernel_launch(void* const* d_in, const int* in_sizes, int n_in,
                              void* d_out, int out_size) {
    const float* pa  = (const float*)d_in[0];
    const float* pm  = (const float*)d_in[1];
    const float* lns = (const float*)d_in[2];
    const float* lnb = (const float*)d_in[3];
    const float* w2d = (const float*)d_in[4];
    const float* wq  = (const float*)d_in[5];
    const float* wk  = (const float*)d_in[6];
    const float* wv  = (const float*)d_in[7];
    const float* wg  = (const float*)d_in[8];
    const float* bg  = (const float*)d_in[9];
    const float* wo  = (const float*)d_in[10];
    const float* bo  = (const float*)d_in[11];
    float* out = (float*)d_out;

    prep_w_kernel<<<160, 512>>>(wq, wk, wv, wg, wo);
    ln_nb_kernel<<<8192, 256>>>(pa, lns, lnb, w2d);
    mma_gemm_kernel<<<dim3(8, 512), 256>>>(0, bg, nullptr, nullptr);
    attn_mma_kernel<<<dim3(4, 512), 128>>>(pm);
    mma_gemm_kernel<<<dim3(2, 512), 256>>>(1, bo, pm, out);
}

// round 15
// speedup vs baseline: 5.6223x; 1.3809x over previous
#include <cuda_runtime.h>
#include <cuda_bf16.h>
#include <cuda_fp16.h>

// TriangleAttention: B=1, N=256, D=128, H=4, kd=32
//   0. prep_w      : weights -> single fp16 plane
//   1. ln_nb       : warp-per-row LayerNorm -> fp16 x ; nb*log2e fp32
//   2. mma_gemm(0) : fp16 GEMM -> q|k fp16, v fp16, gate fp16
//   3. attn_mma    : flash attention, all-fp16 operands, fp32 accum
//   4. mma_gemm(1) : out = (og @ wo^T + bo) * mask (fp16 MMA, fp32 epilogue)
// Softmax is base-2 with a -4 shift folded into the bias (fp16 P overflow
// guard; cancels exactly in O/l). Error budget: ~10 fp16 roundings x 1.9e-4
// (calibrated) ~= 6e-4 < 1e-3.

#define MTOT 65536
#define L2E 1.4426950408889634f

__device__ __align__(16) __half g_x16[MTOT * 128];    // LN output, fp16
__device__ __align__(16) __half g_qk16[MTOT * 256];   // q (scaled) | k, fp16
__device__ __align__(16) __half g_v16[MTOT * 128];    // v fp16
__device__ __align__(16) __half g_og16[MTOT * 128];   // attention output, fp16
__device__ __align__(16) __half g_gate[MTOT * 128];   // sigmoid(g+bg), fp16
__device__ __align__(16) float g_nb[4 * MTOT];        // [h][i*256+j], log2e folded
__device__ __align__(16) __half g_w16[5 * 16384];     // wq wk wv wg wo, fp16

__device__ __forceinline__ float ex2(float x) {
    float y; asm("ex2.approx.ftz.f32 %0, %1;" : "=f"(y) : "f"(x)); return y;
}
__device__ __forceinline__ unsigned pack2f16(float lo, float hi) {
    unsigned d; asm("cvt.rn.f16x2.f32 %0, %1, %2;" : "=r"(d) : "f"(hi), "f"(lo));
    return d;
}

__device__ __forceinline__ void cpa16(void* dst, const void* src) {
    unsigned d = (unsigned)__cvta_generic_to_shared(dst);
    asm volatile("cp.async.cg.shared.global [%0], [%1], 16;" :: "r"(d), "l"(src));
}
__device__ __forceinline__ void cpa_commit() {
    asm volatile("cp.async.commit_group;");
}
template <int N> __device__ __forceinline__ void cpa_wait() {
    asm volatile("cp.async.wait_group %0;" :: "n"(N));
}

__device__ __forceinline__ void ldsm4(unsigned int* r, const void* p) {
    unsigned int a = (unsigned int)__cvta_generic_to_shared(p);
    asm volatile("ldmatrix.sync.aligned.m8n8.x4.shared.b16 {%0,%1,%2,%3}, [%4];"
                 : "=r"(r[0]), "=r"(r[1]), "=r"(r[2]), "=r"(r[3]) : "r"(a));
}
__device__ __forceinline__ void ldsm4t(unsigned int* r, const void* p) {
    unsigned int a = (unsigned int)__cvta_generic_to_shared(p);
    asm volatile("ldmatrix.sync.aligned.m8n8.x4.trans.shared.b16 {%0,%1,%2,%3}, [%4];"
                 : "=r"(r[0]), "=r"(r[1]), "=r"(r[2]), "=r"(r[3]) : "r"(a));
}
__device__ __forceinline__ void mma16816h(float* c, const unsigned int* a,
                                          const unsigned int* b) {
    asm volatile(
        "mma.sync.aligned.m16n8k16.row.col.f32.f16.f16.f32 "
        "{%0,%1,%2,%3}, {%4,%5,%6,%7}, {%8,%9}, {%0,%1,%2,%3};"
        : "+f"(c[0]), "+f"(c[1]), "+f"(c[2]), "+f"(c[3])
        : "r"(a[0]), "r"(a[1]), "r"(a[2]), "r"(a[3]), "r"(b[0]), "r"(b[1]));
}

// ---------------------------------------------------------------------------
// Kernel 0: weight -> fp16
// ---------------------------------------------------------------------------
__global__ __launch_bounds__(512) void prep_w_kernel(
    const float* __restrict__ wq, const float* __restrict__ wk,
    const float* __restrict__ wv, const float* __restrict__ wg,
    const float* __restrict__ wo) {
    int idx = blockIdx.x * 512 + threadIdx.x;
    int which = idx >> 14, off = idx & 16383;
    float w;
    if (which == 0) w = wq[off];
    else if (which == 1) w = wk[off];
    else if (which == 2) w = wv[off];
    else if (which == 3) w = wg[off];
    else w = wo[off];
    g_w16[idx] = __float2half(w);
}

// ---------------------------------------------------------------------------
// Kernel 1: warp-per-row LayerNorm + nb. 256 threads = 8 rows; shuffle-only.
// ---------------------------------------------------------------------------
__global__ __launch_bounds__(256) void ln_nb_kernel(
    const float* __restrict__ pa, const float* __restrict__ sc,
    const float* __restrict__ bi, const float* __restrict__ w2d) {
    int lane = threadIdx.x & 31, wid = threadIdx.x >> 5;
    int m = blockIdx.x * 8 + wid;

    float4 v = *(const float4*)&pa[(size_t)m * 128 + lane * 4];
    float s1 = v.x + v.y + v.z + v.w;
    float s2 = v.x * v.x + v.y * v.y + v.z * v.z + v.w * v.w;
#pragma unroll
    for (int o = 16; o; o >>= 1) {
        s1 += __shfl_xor_sync(0xffffffffu, s1, o);
        s2 += __shfl_xor_sync(0xffffffffu, s2, o);
    }
    float mean = s1 * 0.0078125f;
    float var = s2 * 0.0078125f - mean * mean;
    float rs = rsqrtf(var + 1e-5f);
    float4 scv = *(const float4*)&sc[lane * 4];
    float4 biv = *(const float4*)&bi[lane * 4];
    float x0 = (v.x - mean) * rs * scv.x + biv.x;
    float x1 = (v.y - mean) * rs * scv.y + biv.y;
    float x2 = (v.z - mean) * rs * scv.z + biv.z;
    float x3 = (v.w - mean) * rs * scv.w + biv.w;

    *(uint2*)&g_x16[(size_t)m * 128 + lane * 4] =
        make_uint2(pack2f16(x0, x1), pack2f16(x2, x3));

    float p[4];
#pragma unroll
    for (int hh = 0; hh < 4; hh++) {
        float4 wv4 = *(const float4*)&w2d[hh * 128 + lane * 4];
        float t = x0 * wv4.x + x1 * wv4.y + x2 * wv4.z + x3 * wv4.w;
#pragma unroll
        for (int o = 16; o; o >>= 1) t += __shfl_xor_sync(0xffffffffu, t, o);
        p[hh] = t;
    }
    if (lane < 4) {
        float sel = (lane == 0) ? p[0] : (lane == 1) ? p[1] : (lane == 2) ? p[2] : p[3];
        g_nb[lane * 65536 + m] = sel * L2E;
    }
}

// ---------------------------------------------------------------------------
// Kernels 2/4: fp16 tensor-core GEMM, C = A @ W^T (+ epilogue), fp32 accum.
// Block 128(M) x 64(N), k-tile 32, 8 warps 2x4; single fp16 MMA per step.
// cp.async staging with double-buffered k-loop (15360 B/buffer).
// mode 0 epilogue: n<256 q*scale|k -> g_qk16; n<384 v -> g_v16; else gate
// mode 1 epilogue: (c + bo) * mask -> out (fp32)
// ---------------------------------------------------------------------------
__global__ __launch_bounds__(256) void mma_gemm_kernel(
    int mode, const float* __restrict__ bias,
    const float* __restrict__ mask, float* __restrict__ out) {
    __shared__ __align__(16) char smb[30720];     // 2 x 15360
    const int BOFF = 10240;                        // B plane within buffer
    int tid = threadIdx.x, lane = tid & 31, wid = tid >> 5;
    int wm = wid & 1, wn = wid >> 1;
    int bx = blockIdx.x, m0 = blockIdx.y * 128;
    const __half* Ap = (mode == 0) ? g_x16 : g_og16;
    int widx = (mode == 0) ? (bx >> 1) : 4;
    int nloc = (mode == 0) ? ((bx & 1) * 64) : bx * 64;
    int woff = widx * 16384;

    float c[4][2][4];
#pragma unroll
    for (int a = 0; a < 4; a++)
#pragma unroll
        for (int b = 0; b < 2; b++)
#pragma unroll
            for (int d = 0; d < 4; d++) c[a][b][d] = 0.f;

    int rowA = ((lane >> 3) & 1) * 8 + (lane & 7);
    int kofA = (lane >> 4) * 8;
    int rowB = (lane & 7) + ((lane >> 4) & 1) * 8;
    int kofB = ((lane >> 3) & 1) * 8;

    auto stage = [&](int kt, char* SB) {
        // A: 128 rows x 64B = 512 chunks
#pragma unroll
        for (int p = 0; p < 2; p++) {
            int cix = tid + p * 256;
            int row = cix >> 2, g = cix & 3;
            cpa16(SB + row * 80 + g * 16,
                  Ap + (size_t)(m0 + row) * 128 + kt + g * 8);
        }
        // B: 64 rows x 64B = 256 chunks
        {
            int row = tid >> 2, g = tid & 3;
            cpa16(SB + BOFF + row * 80 + g * 16,
                  g_w16 + (size_t)woff + (nloc + row) * 128 + kt + g * 8);
        }
        cpa_commit();
    };

    stage(0, smb);

    for (int ktile = 0; ktile < 4; ktile++) {
        if (ktile < 3) {
            stage((ktile + 1) * 32, smb + ((ktile + 1) & 1) * 15360);
            cpa_wait<1>();
        } else {
            cpa_wait<0>();
        }
        __syncthreads();
        const char* SB = smb + (ktile & 1) * 15360;
#pragma unroll
        for (int ks = 0; ks < 2; ks++) {
            unsigned int af[4][4], bf[4];
#pragma unroll
            for (int mt = 0; mt < 4; mt++)
                ldsm4(af[mt], SB + (wm * 64 + mt * 16 + rowA) * 80 +
                              (ks * 16 + kofA) * 2);
            ldsm4(bf, SB + BOFF + (wn * 16 + rowB) * 80 + (ks * 16 + kofB) * 2);
#pragma unroll
            for (int mt = 0; mt < 4; mt++) {
                mma16816h(c[mt][0], af[mt], bf);
                mma16816h(c[mt][1], af[mt], bf + 2);
            }
        }
        __syncthreads();
    }

    const float qscale = 0.17677669529663687f * L2E;
#pragma unroll
    for (int mt = 0; mt < 4; mt++) {
        int r0 = m0 + wm * 64 + mt * 16 + (lane >> 2);
#pragma unroll
        for (int nt = 0; nt < 2; nt++) {
            int n = bx * 64 + wn * 16 + nt * 8 + (lane & 3) * 2;
            float v0 = c[mt][nt][0], v1 = c[mt][nt][1];
            float v2 = c[mt][nt][2], v3 = c[mt][nt][3];
            if (mode == 0) {
                if (n >= 384) {
                    float b0 = bias[n - 384], b1 = bias[n - 383];
                    v0 = 1.f / (1.f + ex2(-(v0 + b0) * L2E));
                    v1 = 1.f / (1.f + ex2(-(v1 + b1) * L2E));
                    v2 = 1.f / (1.f + ex2(-(v2 + b0) * L2E));
                    v3 = 1.f / (1.f + ex2(-(v3 + b1) * L2E));
                    *(unsigned*)&g_gate[(size_t)r0 * 128 + n - 384] = pack2f16(v0, v1);
                    *(unsigned*)&g_gate[(size_t)(r0 + 8) * 128 + n - 384] = pack2f16(v2, v3);
                } else if (n >= 256) {
                    *(unsigned*)&g_v16[(size_t)r0 * 128 + n - 256] = pack2f16(v0, v1);
                    *(unsigned*)&g_v16[(size_t)(r0 + 8) * 128 + n - 256] = pack2f16(v2, v3);
                } else {
                    if (n < 128) {
                        v0 *= qscale; v1 *= qscale; v2 *= qscale; v3 *= qscale;
                    }
                    *(unsigned*)&g_qk16[(size_t)r0 * 256 + n] = pack2f16(v0, v1);
                    *(unsigned*)&g_qk16[(size_t)(r0 + 8) * 256 + n] = pack2f16(v2, v3);
                }
            } else {
                float b0 = bias[n], b1 = bias[n + 1];
                float mk0 = mask[r0], mk1 = mask[r0 + 8];
                *(float2*)&out[(size_t)r0 * 128 + n] =
                    make_float2((v0 + b0) * mk0, (v1 + b1) * mk0);
                *(float2*)&out[(size_t)(r0 + 8) * 128 + n] =
                    make_float2((v2 + b0) * mk1, (v3 + b1) * mk1);
            }
        }
    }
}

// ---------------------------------------------------------------------------
// Kernel 3: tensor-core flash attention, all-fp16 operands. CTA = 128
// threads (4 warps), 128 query rows; warp w owns rows [w*32, w*32+32).
// grid (4, 512): h = bx, r = by>>1, qhalf = by&1.
// Buffers: bufA @0, bufB @10240; each K@+0 (5120) | V@+5120 (5120).
// Q (fp16, 10240B) overlays bufA during the prologue; tile0 -> bufB.
// ---------------------------------------------------------------------------
__global__ __launch_bounds__(128, 5) void attn_mma_kernel(const float* __restrict__ mask) {
    __shared__ __align__(16) char smb[21504];
    float* bsm = (float*)(smb + 20480);

    int h = blockIdx.x;
    int r = blockIdx.y >> 1, qc = blockIdx.y & 1;
    int tid = threadIdx.x, lane = tid & 31, w = tid >> 5;
    int q0 = qc * 128;
    size_t qkbase = (size_t)(r * 256) * 256;       // q|k plane, 256 cols
    size_t vbase = (size_t)(r * 256) * 128;        // v plane, 128 cols

    bsm[tid] = (mask[r * 256 + tid] - 1.f) * (32768.f * L2E) - 4.f;
    bsm[tid + 128] = (mask[r * 256 + tid + 128] - 1.f) * (32768.f * L2E) - 4.f;

    // ---- prologue: Q -> bufA (overlay), tile0 -> bufB ----
#pragma unroll
    for (int p = 0; p < 4; p++) {
        int cix = tid + p * 128;            // 512 chunks = 128 rows x 4
        int row = cix >> 2, g = cix & 3;
        size_t src = qkbase + (size_t)(q0 + row) * 256 + h * 32 + g * 8;
        cpa16(smb + row * 80 + g * 16, g_qk16 + src);
    }
    cpa_commit();
#pragma unroll
    for (int p = 0; p < 2; p++) {           // tile0 K: 256 chunks
        int cix = tid + p * 128;
        int row = cix >> 2, g = cix & 3;
        size_t src = qkbase + (size_t)row * 256 + 128 + h * 32 + g * 8;
        cpa16(smb + 10240 + row * 80 + g * 16, g_qk16 + src);
    }
#pragma unroll
    for (int p = 0; p < 2; p++) {           // tile0 V: 256 chunks
        int cix = tid + p * 128;
        int row = cix >> 2, g = cix & 3;
        size_t src = vbase + (size_t)row * 128 + h * 32 + g * 8;
        cpa16(smb + 10240 + 5120 + row * 80 + g * 16, g_v16 + src);
    }
    cpa_commit();
    cpa_wait<1>();      // Q done (tile0 may be in flight)
    __syncthreads();

    int rowA = ((lane >> 3) & 1) * 8 + (lane & 7);
    int kofA = (lane >> 4) * 8;
    int rowB = (lane & 7) + ((lane >> 4) & 1) * 8;
    int kofB = ((lane >> 3) & 1) * 8;

    unsigned qf[2][2][4];
#pragma unroll
    for (int mt = 0; mt < 2; mt++)
#pragma unroll
        for (int ks = 0; ks < 2; ks++)
            ldsm4(qf[mt][ks], smb + (w * 32 + mt * 16 + rowA) * 80 +
                              (ks * 16 + kofA) * 2);
    __syncthreads();    // all warps done with Q region (bufA)

    float o[2][4][4];
#pragma unroll
    for (int mt = 0; mt < 2; mt++)
#pragma unroll
        for (int nt = 0; nt < 4; nt++)
#pragma unroll
            for (int d = 0; d < 4; d++) o[mt][nt][d] = 0.f;
    float lacc[2][2] = {{0.f, 0.f}, {0.f, 0.f}};

    int i1 = q0 + w * 32 + (lane >> 2);                 // mt=0 row; mt=1 is +16
    const float* nbrow = g_nb + h * 65536 + i1 * 256;

    for (int jt = 0; jt < 4; jt++) {
        if (jt < 3) {
            char* NB = smb + ((jt & 1) ? 10240 : 0);
#pragma unroll
            for (int p = 0; p < 2; p++) {
                int cix = tid + p * 128;
                int row = cix >> 2, g = cix & 3;
                size_t src = qkbase + (size_t)((jt + 1) * 64 + row) * 256 + 128 +
                             h * 32 + g * 8;
                cpa16(NB + row * 80 + g * 16, g_qk16 + src);
            }
#pragma unroll
            for (int p = 0; p < 2; p++) {
                int cix = tid + p * 128;
                int row = cix >> 2, g = cix & 3;
                size_t src = vbase + (size_t)((jt + 1) * 64 + row) * 128 +
                             h * 32 + g * 8;
                cpa16(NB + 5120 + row * 80 + g * 16, g_v16 + src);
            }
            cpa_commit();
            cpa_wait<1>();
        } else {
            cpa_wait<0>();
        }
        __syncthreads();
        const char* B = smb + ((jt & 1) ? 0 : 10240);   // tile jt's buffer

#pragma unroll
        for (int np = 0; np < 4; np++) {
            // ---- K fragments ----
            unsigned kf[2][4];
#pragma unroll
            for (int ks = 0; ks < 2; ks++)
                ldsm4(kf[ks], B + (np * 16 + rowB) * 80 + (ks * 16 + kofB) * 2);
            // ---- S init = mask bias (incl. -4 shift) + nb ----
            float s[2][2][4];
#pragma unroll
            for (int mt = 0; mt < 2; mt++) {
                const float* nbp = nbrow + mt * 4096 + jt * 64 + np * 16;
#pragma unroll
                for (int ntl = 0; ntl < 2; ntl++) {
                    int j0l = ntl * 8 + (lane & 3) * 2;
                    float2 b2 = *(float2*)&bsm[jt * 64 + np * 16 + j0l];
                    float2 na = *(const float2*)&nbp[j0l];
                    float2 nb2 = *(const float2*)&nbp[2048 + j0l];
                    s[mt][ntl][0] = b2.x + na.x;
                    s[mt][ntl][1] = b2.y + na.y;
                    s[mt][ntl][2] = b2.x + nb2.x;
                    s[mt][ntl][3] = b2.y + nb2.y;
                }
            }
            // ---- QK^T ----
#pragma unroll
            for (int ks = 0; ks < 2; ks++)
#pragma unroll
                for (int mt = 0; mt < 2; mt++) {
                    mma16816h(s[mt][0], qf[mt][ks], kf[ks]);
                    mma16816h(s[mt][1], qf[mt][ks], kf[ks] + 2);
                }

            // ---- EX2 softmax + pack P as fp16 A-fragments ----
            unsigned pf[2][4];
#pragma unroll
            for (int mt = 0; mt < 2; mt++) {
                float e[8];
#pragma unroll
                for (int ntl = 0; ntl < 2; ntl++) {
                    float e0 = ex2(s[mt][ntl][0]);
                    float e1 = ex2(s[mt][ntl][1]);
                    float e2 = ex2(s[mt][ntl][2]);
                    float e3 = ex2(s[mt][ntl][3]);
                    lacc[mt][0] += e0 + e1;
                    lacc[mt][1] += e2 + e3;
                    e[ntl * 4 + 0] = e0; e[ntl * 4 + 1] = e1;
                    e[ntl * 4 + 2] = e2; e[ntl * 4 + 3] = e3;
                }
                pf[mt][0] = pack2f16(e[0], e[1]);
                pf[mt][1] = pack2f16(e[2], e[3]);
                pf[mt][2] = pack2f16(e[4], e[5]);
                pf[mt][3] = pack2f16(e[6], e[7]);
            }

            // ---- P @ V ----
#pragma unroll
            for (int vg = 0; vg < 2; vg++) {
                unsigned vf4[4];
                const char* pvm = B + 5120 + (np * 16 + (lane & 15)) * 80 +
                                  (vg * 16 + (lane >> 4) * 8) * 2;
                ldsm4t(vf4, pvm);
#pragma unroll
                for (int mt = 0; mt < 2; mt++) {
                    mma16816h(o[mt][vg * 2], pf[mt], vf4);
                    mma16816h(o[mt][vg * 2 + 1], pf[mt], vf4 + 2);
                }
            }
        }
        __syncthreads();   // all warps done with this buffer before next issue
    }

    // ---- row-sum reduce (4 lanes per row) + gated epilogue (fp16 og) ----
#pragma unroll
    for (int mt = 0; mt < 2; mt++) {
        float l0 = lacc[mt][0], l1 = lacc[mt][1];
        l0 += __shfl_xor_sync(0xffffffffu, l0, 1);
        l0 += __shfl_xor_sync(0xffffffffu, l0, 2);
        l1 += __shfl_xor_sync(0xffffffffu, l1, 1);
        l1 += __shfl_xor_sync(0xffffffffu, l1, 2);
        float rl0 = 1.f / l0, rl1 = 1.f / l1;
        size_t m0g = (size_t)(r * 256 + i1 + mt * 16);
#pragma unroll
        for (int nt = 0; nt < 4; nt++) {
            int vd0 = nt * 8 + (lane & 3) * 2;
            float2 g0 = __half22float2(*(const __half2*)&g_gate[m0g * 128 + h * 32 + vd0]);
            float2 g1 = __half22float2(*(const __half2*)&g_gate[(m0g + 8) * 128 + h * 32 + vd0]);
            *(unsigned*)&g_og16[m0g * 128 + h * 32 + vd0] =
                pack2f16(o[mt][nt][0] * rl0 * g0.x, o[mt][nt][1] * rl0 * g0.y);
            *(unsigned*)&g_og16[(m0g + 8) * 128 + h * 32 + vd0] =
                pack2f16(o[mt][nt][2] * rl1 * g1.x, o[mt][nt][3] * rl1 * g1.y);
        }
    }
}

// ---------------------------------------------------------------------------

extern "C" void kernel_launch(void* const* d_in, const int* in_sizes, int n_in,
                              void* d_out, int out_size) {
    const float* pa  = (const float*)d_in[0];
    const float* pm  = (const float*)d_in[1];
    const float* lns = (const float*)d_in[2];
    const float* lnb = (const float*)d_in[3];
    const float* w2d = (const float*)d_in[4];
    const float* wq  = (const float*)d_in[5];
    const float* wk  = (const float*)d_in[6];
    const float* wv  = (const float*)d_in[7];
    const float* wg  = (const float*)d_in[8];
    const float* bg  = (const float*)d_in[9];
    const float* wo  = (const float*)d_in[10];
    const float* bo  = (const float*)d_in[11];
    float* out = (float*)d_out;

    prep_w_kernel<<<160, 512>>>(wq, wk, wv, wg, wo);
    ln_nb_kernel<<<8192, 256>>>(pa, lns, lnb, w2d);
    mma_gemm_kernel<<<dim3(8, 512), 256>>>(0, bg, nullptr, nullptr);
    attn_mma_kernel<<<dim3(4, 512), 128>>>(pm);
    mma_gemm_kernel<<<dim3(2, 512), 256>>>(1, bo, pm, out);
}

// round 16
// speedup vs baseline: 6.2541x; 1.1124x over previous
#include <cuda_runtime.h>
#include <cuda_bf16.h>
#include <cuda_fp16.h>

// TriangleAttention: B=1, N=256, D=128, H=4, kd=32
//   0. prep_w      : weights -> single fp16 plane
//   1. ln_nb       : warp-per-row LayerNorm -> fp16 x ; nb*log2e fp32,
//                    stored in MMA-fragment-major tiles (coalesced attn reads)
//   2. mma_gemm(0) : fp16 GEMM -> q|k fp16, v fp16, gate fp16
//   3. attn_mma    : flash attention, all-fp16 operands, fp32 accum
//   4. mma_gemm(1) : out = (og @ wo^T + bo) * mask (fp16 MMA, fp32 epilogue)
// Softmax is base-2 with a -4 shift folded into the bias (fp16 P overflow
// guard; cancels exactly in O/l).
// nb layout: per h, per 16x16 tile (tr*16+tc), [ntl][half][lane] float2 --
// the m16n8k16 fragment lane index (r&7)*4+(c>>1) == lane, so each warp read
// is 32 consecutive float2 (256B, 2 wavefronts) instead of an 8-line gather.

#define MTOT 65536
#define L2E 1.4426950408889634f

__device__ __align__(16) __half g_x16[MTOT * 128];    // LN output, fp16
__device__ __align__(16) __half g_qk16[MTOT * 256];   // q (scaled) | k, fp16
__device__ __align__(16) __half g_v16[MTOT * 128];    // v fp16
__device__ __align__(16) __half g_og16[MTOT * 128];   // attention output, fp16
__device__ __align__(16) __half g_gate[MTOT * 128];   // sigmoid(g+bg), fp16
__device__ __align__(16) float g_nb[4 * MTOT];        // fragment-major tiles
__device__ __align__(16) __half g_w16[5 * 16384];     // wq wk wv wg wo, fp16

__device__ __forceinline__ float ex2(float x) {
    float y; asm("ex2.approx.ftz.f32 %0, %1;" : "=f"(y) : "f"(x)); return y;
}
__device__ __forceinline__ unsigned pack2f16(float lo, float hi) {
    unsigned d; asm("cvt.rn.f16x2.f32 %0, %1, %2;" : "=r"(d) : "f"(hi), "f"(lo));
    return d;
}

__device__ __forceinline__ void cpa16(void* dst, const void* src) {
    unsigned d = (unsigned)__cvta_generic_to_shared(dst);
    asm volatile("cp.async.cg.shared.global [%0], [%1], 16;" :: "r"(d), "l"(src));
}
__device__ __forceinline__ void cpa_commit() {
    asm volatile("cp.async.commit_group;");
}
template <int N> __device__ __forceinline__ void cpa_wait() {
    asm volatile("cp.async.wait_group %0;" :: "n"(N));
}

__device__ __forceinline__ void ldsm4(unsigned int* r, const void* p) {
    unsigned int a = (unsigned int)__cvta_generic_to_shared(p);
    asm volatile("ldmatrix.sync.aligned.m8n8.x4.shared.b16 {%0,%1,%2,%3}, [%4];"
                 : "=r"(r[0]), "=r"(r[1]), "=r"(r[2]), "=r"(r[3]) : "r"(a));
}
__device__ __forceinline__ void ldsm4t(unsigned int* r, const void* p) {
    unsigned int a = (unsigned int)__cvta_generic_to_shared(p);
    asm volatile("ldmatrix.sync.aligned.m8n8.x4.trans.shared.b16 {%0,%1,%2,%3}, [%4];"
                 : "=r"(r[0]), "=r"(r[1]), "=r"(r[2]), "=r"(r[3]) : "r"(a));
}
__device__ __forceinline__ void mma16816h(float* c, const unsigned int* a,
                                          const unsigned int* b) {
    asm volatile(
        "mma.sync.aligned.m16n8k16.row.col.f32.f16.f16.f32 "
        "{%0,%1,%2,%3}, {%4,%5,%6,%7}, {%8,%9}, {%0,%1,%2,%3};"
        : "+f"(c[0]), "+f"(c[1]), "+f"(c[2]), "+f"(c[3])
        : "r"(a[0]), "r"(a[1]), "r"(a[2]), "r"(a[3]), "r"(b[0]), "r"(b[1]));
}

// ---------------------------------------------------------------------------
// Kernel 0: weight -> fp16
// ---------------------------------------------------------------------------
__global__ __launch_bounds__(512) void prep_w_kernel(
    const float* __restrict__ wq, const float* __restrict__ wk,
    const float* __restrict__ wv, const float* __restrict__ wg,
    const float* __restrict__ wo) {
    int idx = blockIdx.x * 512 + threadIdx.x;
    int which = idx >> 14, off = idx & 16383;
    float w;
    if (which == 0) w = wq[off];
    else if (which == 1) w = wk[off];
    else if (which == 2) w = wv[off];
    else if (which == 3) w = wg[off];
    else w = wo[off];
    g_w16[idx] = __float2half(w);
}

// ---------------------------------------------------------------------------
// Kernel 1: warp-per-row LayerNorm + nb. 256 threads = 8 rows; shuffle-only.
// nb written in fragment-major tile layout (see header comment).
// ---------------------------------------------------------------------------
__global__ __launch_bounds__(256) void ln_nb_kernel(
    const float* __restrict__ pa, const float* __restrict__ sc,
    const float* __restrict__ bi, const float* __restrict__ w2d) {
    int lane = threadIdx.x & 31, wid = threadIdx.x >> 5;
    int m = blockIdx.x * 8 + wid;

    float4 v = *(const float4*)&pa[(size_t)m * 128 + lane * 4];
    float s1 = v.x + v.y + v.z + v.w;
    float s2 = v.x * v.x + v.y * v.y + v.z * v.z + v.w * v.w;
#pragma unroll
    for (int o = 16; o; o >>= 1) {
        s1 += __shfl_xor_sync(0xffffffffu, s1, o);
        s2 += __shfl_xor_sync(0xffffffffu, s2, o);
    }
    float mean = s1 * 0.0078125f;
    float var = s2 * 0.0078125f - mean * mean;
    float rs = rsqrtf(var + 1e-5f);
    float4 scv = *(const float4*)&sc[lane * 4];
    float4 biv = *(const float4*)&bi[lane * 4];
    float x0 = (v.x - mean) * rs * scv.x + biv.x;
    float x1 = (v.y - mean) * rs * scv.y + biv.y;
    float x2 = (v.z - mean) * rs * scv.z + biv.z;
    float x3 = (v.w - mean) * rs * scv.w + biv.w;

    *(uint2*)&g_x16[(size_t)m * 128 + lane * 4] =
        make_uint2(pack2f16(x0, x1), pack2f16(x2, x3));

    float p[4];
#pragma unroll
    for (int hh = 0; hh < 4; hh++) {
        float4 wv4 = *(const float4*)&w2d[hh * 128 + lane * 4];
        float t = x0 * wv4.x + x1 * wv4.y + x2 * wv4.z + x3 * wv4.w;
#pragma unroll
        for (int o = 16; o; o >>= 1) t += __shfl_xor_sync(0xffffffffu, t, o);
        p[hh] = t;
    }
    if (lane < 4) {
        float sel = (lane == 0) ? p[0] : (lane == 1) ? p[1] : (lane == 2) ? p[2] : p[3];
        // fragment-major nb store
        int i = m >> 8, j = m & 255;
        int tr = i >> 4, tc = j >> 4;
        int rr = i & 15, cc = j & 15;
        int ntl2 = cc >> 3, half = rr >> 3;
        int lidx = (rr & 7) * 4 + ((cc & 7) >> 1);
        int elem = cc & 1;
        g_nb[(size_t)lane * 65536 + (tr * 16 + tc) * 256 +
             ((ntl2 * 2 + half) * 32 + lidx) * 2 + elem] = sel * L2E;
    }
}

// ---------------------------------------------------------------------------
// Kernels 2/4: fp16 tensor-core GEMM, C = A @ W^T (+ epilogue), fp32 accum.
// Block 128(M) x 64(N), k-tile 32, 8 warps 2x4; single fp16 MMA per step.
// cp.async staging with double-buffered k-loop (15360 B/buffer).
// ---------------------------------------------------------------------------
__global__ __launch_bounds__(256) void mma_gemm_kernel(
    int mode, const float* __restrict__ bias,
    const float* __restrict__ mask, float* __restrict__ out) {
    __shared__ __align__(16) char smb[30720];     // 2 x 15360
    const int BOFF = 10240;                        // B plane within buffer
    int tid = threadIdx.x, lane = tid & 31, wid = tid >> 5;
    int wm = wid & 1, wn = wid >> 1;
    int bx = blockIdx.x, m0 = blockIdx.y * 128;
    const __half* Ap = (mode == 0) ? g_x16 : g_og16;
    int widx = (mode == 0) ? (bx >> 1) : 4;
    int nloc = (mode == 0) ? ((bx & 1) * 64) : bx * 64;
    int woff = widx * 16384;

    float c[4][2][4];
#pragma unroll
    for (int a = 0; a < 4; a++)
#pragma unroll
        for (int b = 0; b < 2; b++)
#pragma unroll
            for (int d = 0; d < 4; d++) c[a][b][d] = 0.f;

    int rowA = ((lane >> 3) & 1) * 8 + (lane & 7);
    int kofA = (lane >> 4) * 8;
    int rowB = (lane & 7) + ((lane >> 4) & 1) * 8;
    int kofB = ((lane >> 3) & 1) * 8;

    auto stage = [&](int kt, char* SB) {
#pragma unroll
        for (int p = 0; p < 2; p++) {
            int cix = tid + p * 256;
            int row = cix >> 2, g = cix & 3;
            cpa16(SB + row * 80 + g * 16,
                  Ap + (size_t)(m0 + row) * 128 + kt + g * 8);
        }
        {
            int row = tid >> 2, g = tid & 3;
            cpa16(SB + BOFF + row * 80 + g * 16,
                  g_w16 + (size_t)woff + (nloc + row) * 128 + kt + g * 8);
        }
        cpa_commit();
    };

    stage(0, smb);

    for (int ktile = 0; ktile < 4; ktile++) {
        if (ktile < 3) {
            stage((ktile + 1) * 32, smb + ((ktile + 1) & 1) * 15360);
            cpa_wait<1>();
        } else {
            cpa_wait<0>();
        }
        __syncthreads();
        const char* SB = smb + (ktile & 1) * 15360;
#pragma unroll
        for (int ks = 0; ks < 2; ks++) {
            unsigned int af[4][4], bf[4];
#pragma unroll
            for (int mt = 0; mt < 4; mt++)
                ldsm4(af[mt], SB + (wm * 64 + mt * 16 + rowA) * 80 +
                              (ks * 16 + kofA) * 2);
            ldsm4(bf, SB + BOFF + (wn * 16 + rowB) * 80 + (ks * 16 + kofB) * 2);
#pragma unroll
            for (int mt = 0; mt < 4; mt++) {
                mma16816h(c[mt][0], af[mt], bf);
                mma16816h(c[mt][1], af[mt], bf + 2);
            }
        }
        __syncthreads();
    }

    const float qscale = 0.17677669529663687f * L2E;
#pragma unroll
    for (int mt = 0; mt < 4; mt++) {
        int r0 = m0 + wm * 64 + mt * 16 + (lane >> 2);
#pragma unroll
        for (int nt = 0; nt < 2; nt++) {
            int n = bx * 64 + wn * 16 + nt * 8 + (lane & 3) * 2;
            float v0 = c[mt][nt][0], v1 = c[mt][nt][1];
            float v2 = c[mt][nt][2], v3 = c[mt][nt][3];
            if (mode == 0) {
                if (n >= 384) {
                    float b0 = bias[n - 384], b1 = bias[n - 383];
                    v0 = 1.f / (1.f + ex2(-(v0 + b0) * L2E));
                    v1 = 1.f / (1.f + ex2(-(v1 + b1) * L2E));
                    v2 = 1.f / (1.f + ex2(-(v2 + b0) * L2E));
                    v3 = 1.f / (1.f + ex2(-(v3 + b1) * L2E));
                    *(unsigned*)&g_gate[(size_t)r0 * 128 + n - 384] = pack2f16(v0, v1);
                    *(unsigned*)&g_gate[(size_t)(r0 + 8) * 128 + n - 384] = pack2f16(v2, v3);
                } else if (n >= 256) {
                    *(unsigned*)&g_v16[(size_t)r0 * 128 + n - 256] = pack2f16(v0, v1);
                    *(unsigned*)&g_v16[(size_t)(r0 + 8) * 128 + n - 256] = pack2f16(v2, v3);
                } else {
                    if (n < 128) {
                        v0 *= qscale; v1 *= qscale; v2 *= qscale; v3 *= qscale;
                    }
                    *(unsigned*)&g_qk16[(size_t)r0 * 256 + n] = pack2f16(v0, v1);
                    *(unsigned*)&g_qk16[(size_t)(r0 + 8) * 256 + n] = pack2f16(v2, v3);
                }
            } else {
                float b0 = bias[n], b1 = bias[n + 1];
                float mk0 = mask[r0], mk1 = mask[r0 + 8];
                *(float2*)&out[(size_t)r0 * 128 + n] =
                    make_float2((v0 + b0) * mk0, (v1 + b1) * mk0);
                *(float2*)&out[(size_t)(r0 + 8) * 128 + n] =
                    make_float2((v2 + b0) * mk1, (v3 + b1) * mk1);
            }
        }
    }
}

// ---------------------------------------------------------------------------
// Kernel 3: tensor-core flash attention, all-fp16 operands. CTA = 128
// threads (4 warps), 128 query rows; warp w owns rows [w*32, w*32+32).
// grid (4, 512): h = bx, r = by>>1, qhalf = by&1.
// Buffers: bufA @0, bufB @10240; each K@+0 (5120) | V@+5120 (5120).
// Q (fp16, 10240B) overlays bufA during the prologue; tile0 -> bufB.
// nb read from fragment-major tiles: 32 consecutive float2 per warp access.
// ---------------------------------------------------------------------------
__global__ __launch_bounds__(128, 5) void attn_mma_kernel(const float* __restrict__ mask) {
    __shared__ __align__(16) char smb[21504];
    float* bsm = (float*)(smb + 20480);

    int h = blockIdx.x;
    int r = blockIdx.y >> 1, qc = blockIdx.y & 1;
    int tid = threadIdx.x, lane = tid & 31, w = tid >> 5;
    int q0 = qc * 128;
    size_t qkbase = (size_t)(r * 256) * 256;       // q|k plane, 256 cols
    size_t vbase = (size_t)(r * 256) * 128;        // v plane, 128 cols

    bsm[tid] = (mask[r * 256 + tid] - 1.f) * (32768.f * L2E) - 4.f;
    bsm[tid + 128] = (mask[r * 256 + tid + 128] - 1.f) * (32768.f * L2E) - 4.f;

    // ---- prologue: Q -> bufA (overlay), tile0 -> bufB ----
#pragma unroll
    for (int p = 0; p < 4; p++) {
        int cix = tid + p * 128;            // 512 chunks = 128 rows x 4
        int row = cix >> 2, g = cix & 3;
        size_t src = qkbase + (size_t)(q0 + row) * 256 + h * 32 + g * 8;
        cpa16(smb + row * 80 + g * 16, g_qk16 + src);
    }
    cpa_commit();
#pragma unroll
    for (int p = 0; p < 2; p++) {           // tile0 K: 256 chunks
        int cix = tid + p * 128;
        int row = cix >> 2, g = cix & 3;
        size_t src = qkbase + (size_t)row * 256 + 128 + h * 32 + g * 8;
        cpa16(smb + 10240 + row * 80 + g * 16, g_qk16 + src);
    }
#pragma unroll
    for (int p = 0; p < 2; p++) {           // tile0 V: 256 chunks
        int cix = tid + p * 128;
        int row = cix >> 2, g = cix & 3;
        size_t src = vbase + (size_t)row * 128 + h * 32 + g * 8;
        cpa16(smb + 10240 + 5120 + row * 80 + g * 16, g_v16 + src);
    }
    cpa_commit();
    cpa_wait<1>();      // Q done (tile0 may be in flight)
    __syncthreads();

    int rowA = ((lane >> 3) & 1) * 8 + (lane & 7);
    int kofA = (lane >> 4) * 8;
    int rowB = (lane & 7) + ((lane >> 4) & 1) * 8;
    int kofB = ((lane >> 3) & 1) * 8;

    unsigned qf[2][2][4];
#pragma unroll
    for (int mt = 0; mt < 2; mt++)
#pragma unroll
        for (int ks = 0; ks < 2; ks++)
            ldsm4(qf[mt][ks], smb + (w * 32 + mt * 16 + rowA) * 80 +
                              (ks * 16 + kofA) * 2);
    __syncthreads();    // all warps done with Q region (bufA)

    float o[2][4][4];
#pragma unroll
    for (int mt = 0; mt < 2; mt++)
#pragma unroll
        for (int nt = 0; nt < 4; nt++)
#pragma unroll
            for (int d = 0; d < 4; d++) o[mt][nt][d] = 0.f;
    float lacc[2][2] = {{0.f, 0.f}, {0.f, 0.f}};

    int i1 = q0 + w * 32 + (lane >> 2);                 // mt=0 row; mt=1 is +16
    int trw = (q0 + w * 32) >> 4;                       // tile row for mt=0

    for (int jt = 0; jt < 4; jt++) {
        if (jt < 3) {
            char* NB = smb + ((jt & 1) ? 10240 : 0);
#pragma unroll
            for (int p = 0; p < 2; p++) {
                int cix = tid + p * 128;
                int row = cix >> 2, g = cix & 3;
                size_t src = qkbase + (size_t)((jt + 1) * 64 + row) * 256 + 128 +
                             h * 32 + g * 8;
                cpa16(NB + row * 80 + g * 16, g_qk16 + src);
            }
#pragma unroll
            for (int p = 0; p < 2; p++) {
                int cix = tid + p * 128;
                int row = cix >> 2, g = cix & 3;
                size_t src = vbase + (size_t)((jt + 1) * 64 + row) * 128 +
                             h * 32 + g * 8;
                cpa16(NB + 5120 + row * 80 + g * 16, g_v16 + src);
            }
            cpa_commit();
            cpa_wait<1>();
        } else {
            cpa_wait<0>();
        }
        __syncthreads();
        const char* B = smb + ((jt & 1) ? 0 : 10240);   // tile jt's buffer

#pragma unroll
        for (int np = 0; np < 4; np++) {
            // ---- K fragments ----
            unsigned kf[2][4];
#pragma unroll
            for (int ks = 0; ks < 2; ks++)
                ldsm4(kf[ks], B + (np * 16 + rowB) * 80 + (ks * 16 + kofB) * 2);
            // ---- S init = mask bias (incl. -4 shift) + nb (fragment-major) ----
            float s[2][2][4];
#pragma unroll
            for (int mt = 0; mt < 2; mt++) {
                const float* nbt = g_nb + h * 65536 +
                    ((trw + mt) * 16 + jt * 4 + np) * 256 + lane * 2;
#pragma unroll
                for (int ntl = 0; ntl < 2; ntl++) {
                    int j0l = ntl * 8 + (lane & 3) * 2;
                    float2 b2 = *(float2*)&bsm[jt * 64 + np * 16 + j0l];
                    float2 fa = *(const float2*)&nbt[(ntl * 2 + 0) * 64];
                    float2 fb = *(const float2*)&nbt[(ntl * 2 + 1) * 64];
                    s[mt][ntl][0] = b2.x + fa.x;
                    s[mt][ntl][1] = b2.y + fa.y;
                    s[mt][ntl][2] = b2.x + fb.x;
                    s[mt][ntl][3] = b2.y + fb.y;
                }
            }
            // ---- QK^T ----
#pragma unroll
            for (int ks = 0; ks < 2; ks++)
#pragma unroll
                for (int mt = 0; mt < 2; mt++) {
                    mma16816h(s[mt][0], qf[mt][ks], kf[ks]);
                    mma16816h(s[mt][1], qf[mt][ks], kf[ks] + 2);
                }

            // ---- EX2 softmax + pack P as fp16 A-fragments ----
            unsigned pf[2][4];
#pragma unroll
            for (int mt = 0; mt < 2; mt++) {
                float e[8];
#pragma unroll
                for (int ntl = 0; ntl < 2; ntl++) {
                    float e0 = ex2(s[mt][ntl][0]);
                    float e1 = ex2(s[mt][ntl][1]);
                    float e2 = ex2(s[mt][ntl][2]);
                    float e3 = ex2(s[mt][ntl][3]);
                    lacc[mt][0] += e0 + e1;
                    lacc[mt][1] += e2 + e3;
                    e[ntl * 4 + 0] = e0; e[ntl * 4 + 1] = e1;
                    e[ntl * 4 + 2] = e2; e[ntl * 4 + 3] = e3;
                }
                pf[mt][0] = pack2f16(e[0], e[1]);
                pf[mt][1] = pack2f16(e[2], e[3]);
                pf[mt][2] = pack2f16(e[4], e[5]);
                pf[mt][3] = pack2f16(e[6], e[7]);
            }

            // ---- P @ V ----
#pragma unroll
            for (int vg = 0; vg < 2; vg++) {
                unsigned vf4[4];
                const char* pvm = B + 5120 + (np * 16 + (lane & 15)) * 80 +
                                  (vg * 16 + (lane >> 4) * 8) * 2;
                ldsm4t(vf4, pvm);
#pragma unroll
                for (int mt = 0; mt < 2; mt++) {
                    mma16816h(o[mt][vg * 2], pf[mt], vf4);
                    mma16816h(o[mt][vg * 2 + 1], pf[mt], vf4 + 2);
                }
            }
        }
        __syncthreads();   // all warps done with this buffer before next issue
    }

    // ---- row-sum reduce (4 lanes per row) + gated epilogue (fp16 og) ----
#pragma unroll
    for (int mt = 0; mt < 2; mt++) {
        float l0 = lacc[mt][0], l1 = lacc[mt][1];
        l0 += __shfl_xor_sync(0xffffffffu, l0, 1);
        l0 += __shfl_xor_sync(0xffffffffu, l0, 2);
        l1 += __shfl_xor_sync(0xffffffffu, l1, 1);
        l1 += __shfl_xor_sync(0xffffffffu, l1, 2);
        float rl0 = 1.f / l0, rl1 = 1.f / l1;
        size_t m0g = (size_t)(r * 256 + i1 + mt * 16);
#pragma unroll
        for (int nt = 0; nt < 4; nt++) {
            int vd0 = nt * 8 + (lane & 3) * 2;
            float2 g0 = __half22float2(*(const __half2*)&g_gate[m0g * 128 + h * 32 + vd0]);
            float2 g1 = __half22float2(*(const __half2*)&g_gate[(m0g + 8) * 128 + h * 32 + vd0]);
            *(unsigned*)&g_og16[m0g * 128 + h * 32 + vd0] =
                pack2f16(o[mt][nt][0] * rl0 * g0.x, o[mt][nt][1] * rl0 * g0.y);
            *(unsigned*)&g_og16[(m0g + 8) * 128 + h * 32 + vd0] =
                pack2f16(o[mt][nt][2] * rl1 * g1.x, o[mt][nt][3] * rl1 * g1.y);
        }
    }
}

// ---------------------------------------------------------------------------

extern "C" void kernel_launch(void* const* d_in, const int* in_sizes, int n_in,
                              void* d_out, int out_size) {
    const float* pa  = (const float*)d_in[0];
    const float* pm  = (const float*)d_in[1];
    const float* lns = (const float*)d_in[2];
    const float* lnb = (const float*)d_in[3];
    const float* w2d = (const float*)d_in[4];
    const float* wq  = (const float*)d_in[5];
    const float* wk  = (const float*)d_in[6];
    const float* wv  = (const float*)d_in[7];
    const float* wg  = (const float*)d_in[8];
    const float* wo  = (const float*)d_in[10];
    const float* bg  = (const float*)d_in[9];
    const float* bo  = (const float*)d_in[11];
    float* out = (float*)d_out;

    prep_w_kernel<<<160, 512>>>(wq, wk, wv, wg, wo);
    ln_nb_kernel<<<8192, 256>>>(pa, lns, lnb, w2d);
    mma_gemm_kernel<<<dim3(8, 512), 256>>>(0, bg, nullptr, nullptr);
    attn_mma_kernel<<<dim3(4, 512), 128>>>(pm);
    mma_gemm_kernel<<<dim3(2, 512), 256>>>(1, bo, pm, out);
}